// round 10
// baseline (speedup 1.0000x reference)
#include <cuda_runtime.h>
#include <cuda_bf16.h>
#include <math.h>
#include <stdint.h>

// ---------------------------------------------------------------------------
// VPGNet forward. Conv2..8 as split-bf16 HMMA GEMMs (fp32 accumulate).
// 4-warp 64x32 warp tiles (min smem-crossbar traffic), split-K, fused
// transpose epilogues. Output: [x6|x8a|x8b|x8c|x8d] = 1,747,200 floats
// ---------------------------------------------------------------------------

// ---- scratch ----
__device__ float g_c1[96 * 118 * 158];
__device__ float g_u1[96 * 59 * 79];
__device__ float g_c2[256 * 59 * 79];
__device__ float g_p2[256 * 29 * 39];
__device__ float g_c3[384 * 29 * 39];
__device__ float g_c4[384 * 29 * 39];
__device__ float g_c5[384 * 29 * 39];
__device__ float g_p5[384 * 14 * 19];
__device__ float g_p6[6 * 4096 * 300];        // split-K partials (also conv2..5)
__device__ float g_p7[2 * 4 * 4096 * 300];
__device__ float g_p8[4 * 1728 * 300];
// bf16 split activation buffers [Npad][K]; max conv2 4672*2400 = 11.2M
__device__ __nv_bfloat16 gB_hi[11250000];
__device__ __nv_bfloat16 gB_lo[11250000];
__device__ __nv_bfloat16 gB6_hi[320 * 4096];
__device__ __nv_bfloat16 gB6_lo[320 * 4096];

// ============================ helpers ============================
__device__ __forceinline__ uint32_t smem_u32(const void* p) {
    uint32_t a;
    asm("{ .reg .u64 t; cvta.to.shared.u64 t, %1; cvt.u32.u64 %0, t; }" : "=r"(a) : "l"(p));
    return a;
}
__device__ __forceinline__ uint32_t swz64(uint32_t o) { return o ^ ((o >> 3) & 0x30); }

__device__ __forceinline__ void ldm4(uint32_t* r, uint32_t a) {
    asm volatile("ldmatrix.sync.aligned.m8n8.x4.shared.b16 {%0,%1,%2,%3}, [%4];"
                 : "=r"(r[0]), "=r"(r[1]), "=r"(r[2]), "=r"(r[3]) : "r"(a));
}
__device__ __forceinline__ void mma_bf16(float* c, const uint32_t* a, const uint32_t* b) {
    asm volatile("mma.sync.aligned.m16n8k16.row.col.f32.bf16.bf16.f32 "
                 "{%0,%1,%2,%3}, {%4,%5,%6,%7}, {%8,%9}, {%0,%1,%2,%3};"
                 : "+f"(c[0]), "+f"(c[1]), "+f"(c[2]), "+f"(c[3])
                 : "r"(a[0]), "r"(a[1]), "r"(a[2]), "r"(a[3]), "r"(b[0]), "r"(b[1]));
}
__device__ __forceinline__ void sts128(uint32_t a, uint4 v) {
    asm volatile("st.shared.v4.b32 [%0], {%1,%2,%3,%4};"
                 :: "r"(a), "r"(v.x), "r"(v.y), "r"(v.z), "r"(v.w) : "memory");
}
__device__ __forceinline__ uint32_t packbf2(float lo, float hi) {
    uint32_t d;
    asm("cvt.rn.bf16x2.f32 %0, %1, %2;" : "=r"(d) : "f"(hi), "f"(lo));
    return d;
}
__device__ __forceinline__ uint32_t pack2(__nv_bfloat16 a, __nv_bfloat16 b) {
    return (uint32_t)__bfloat16_as_ushort(a) | ((uint32_t)__bfloat16_as_ushort(b) << 16);
}

// ============================ elementwise layers ============================
__global__ void k_conv1(const float* __restrict__ x, const float* __restrict__ w,
                        const float* __restrict__ b, float* __restrict__ out) {
    const int HO = 118, WO = 158;
    int i = blockIdx.x * blockDim.x + threadIdx.x;
    if (i >= 96 * HO * WO) return;
    int c = i / (HO * WO), r = i % (HO * WO), oh = r / WO, ow = r % WO;
    float acc = b[c];
    const float* wp = w + c * 3 * 121;
    for (int ci = 0; ci < 3; ci++) {
        const float* xc = x + ci * 480 * 640;
        const float* wc = wp + ci * 121;
        #pragma unroll
        for (int kh = 0; kh < 11; kh++) {
            const float* xp = xc + (oh * 4 + kh) * 640 + ow * 4;
            const float* wq = wc + kh * 11;
            #pragma unroll
            for (int kw = 0; kw < 11; kw++) acc = fmaf(xp[kw], wq[kw], acc);
        }
    }
    out[i] = fmaxf(acc, 0.f);
}

// stage-1 fused LRN + maxpool3s2 + upsample (59,79)
__global__ void k_pooluplrn(const float* __restrict__ c1, float* __restrict__ out) {
    int i = blockIdx.x * blockDim.x + threadIdx.x;
    if (i >= 96 * 59 * 79) return;
    int c = i / (59 * 79), r = i % (59 * 79), oh = r / 79, ow = r % 79;
    int hi = (oh * 58) / 59, wi = (ow * 78) / 79;
    int jlo = c - 2 > 0 ? c - 2 : 0;
    int jhi = c + 2 < 95 ? c + 2 : 95;
    const int HW = 118 * 158;
    float m = -1e30f;
    #pragma unroll
    for (int dh = 0; dh < 3; dh++) {
        #pragma unroll
        for (int dw = 0; dw < 3; dw++) {
            const float* p = c1 + (2 * hi + dh) * 158 + 2 * wi + dw;
            float s = 0.f;
            for (int j = jlo; j <= jhi; j++) { float v = p[j * HW]; s = fmaf(v, v, s); }
            float t = 2.0f + 1e-4f * s;
            float rr = rsqrtf(t);
            m = fmaxf(m, p[c * HW] * rr * sqrtf(rr));
        }
    }
    out[i] = m;
}

// conv2 fused LRN(k=8) + maxpool3s2
__global__ void k_poollrn(const float* __restrict__ in, float* __restrict__ out,
                          int C, int Hin, int Win, int Ho, int Wo,
                          float kc, float a) {
    int i = blockIdx.x * blockDim.x + threadIdx.x;
    if (i >= C * Ho * Wo) return;
    int c = i / (Ho * Wo), r = i % (Ho * Wo), oh = r / Wo, ow = r % Wo;
    int jlo = c - 2 > 0 ? c - 2 : 0;
    int jhi = c + 2 < C - 1 ? c + 2 : C - 1;
    const int HW = Hin * Win;
    float m = -1e30f;
    #pragma unroll
    for (int dh = 0; dh < 3; dh++) {
        #pragma unroll
        for (int dw = 0; dw < 3; dw++) {
            const float* p = in + (2 * oh + dh) * Win + 2 * ow + dw;
            float s = 0.f;
            for (int j = jlo; j <= jhi; j++) { float v = p[j * HW]; s = fmaf(v, v, s); }
            float t = kc + a * s;
            float rr = rsqrtf(t);
            m = fmaxf(m, p[c * HW] * rr * sqrtf(rr));
        }
    }
    out[i] = m;
}

__global__ void k_pool(const float* __restrict__ in, float* __restrict__ out,
                       int C, int Hin, int Win, int Ho, int Wo) {
    int i = blockIdx.x * blockDim.x + threadIdx.x;
    if (i >= C * Ho * Wo) return;
    int c = i / (Ho * Wo), r = i % (Ho * Wo), oh = r / Wo, ow = r % Wo;
    const float* p = in + (c * Hin + 2 * oh) * Win + 2 * ow;
    float m = p[0];
    #pragma unroll
    for (int dh = 0; dh < 3; dh++)
        #pragma unroll
        for (int dw = 0; dw < 3; dw++) m = fmaxf(m, p[dh * Win + dw]);
    out[i] = m;
}

// ---- im2col + transpose + split, 4 k-positions per thread ----
template <int KSZ>
__global__ void k_prepB4(const float* __restrict__ src, __nv_bfloat16* __restrict__ hi,
                         __nv_bfloat16* __restrict__ lo, int H, int W, int pad,
                         int Ho, int Wo, int K) {
    int k4 = blockIdx.x * 256 + threadIdx.x;
    int kidx = k4 * 4;
    if (kidx >= K) return;
    int n = blockIdx.y;
    int oh = n / Wo, ow = n % Wo;
    bool vn = n < Ho * Wo;
    int kw = kidx % KSZ;
    int t = kidx / KSZ;
    int kh = t % KSZ, cc = t / KSZ;
    float v[4];
    #pragma unroll
    for (int j = 0; j < 4; j++) {
        float val = 0.f;
        if (vn) {
            int ih = oh - pad + kh, iw = ow - pad + kw;
            if (ih >= 0 && ih < H && iw >= 0 && iw < W)
                val = src[((size_t)cc * H + ih) * W + iw];
        }
        v[j] = val;
        if (++kw == KSZ) { kw = 0; if (++kh == KSZ) { kh = 0; ++cc; } }
    }
    __nv_bfloat16 h0 = __float2bfloat16(v[0]), h1 = __float2bfloat16(v[1]),
                  h2 = __float2bfloat16(v[2]), h3 = __float2bfloat16(v[3]);
    uint2 ph = make_uint2(pack2(h0, h1), pack2(h2, h3));
    uint2 pl = make_uint2(
        packbf2(v[0] - __bfloat162float(h0), v[1] - __bfloat162float(h1)),
        packbf2(v[2] - __bfloat162float(h2), v[3] - __bfloat162float(h3)));
    size_t o = (size_t)n * K + kidx;
    *reinterpret_cast<uint2*>(hi + o) = ph;
    *reinterpret_cast<uint2*>(lo + o) = pl;
}

// ---- fused reduce(4)+bias+relu -> d_out(x6) AND transposed bf16 split ----
__global__ void k_fuse6(const float* __restrict__ p, const float* __restrict__ bias,
                        float* __restrict__ out, __nv_bfloat16* __restrict__ hi,
                        __nv_bfloat16* __restrict__ lo) {
    __shared__ float t[32][33];
    int rb = blockIdx.x * 32, nb = blockIdx.y * 32;
    int tx = threadIdx.x, ty = threadIdx.y;
    #pragma unroll
    for (int j = 0; j < 4; j++) {
        int row = rb + ty + j * 8;
        int n = nb + tx;
        float v = 0.f;
        if (n < 300) {
            size_t o = (size_t)row * 300 + n;
            v = fmaxf(p[o] + p[o + 1228800] + p[o + 2 * 1228800] + p[o + 3 * 1228800]
                      + bias[row], 0.f);
            out[o] = v;
        }
        t[ty + j * 8][tx] = v;
    }
    __syncthreads();
    #pragma unroll
    for (int j = 0; j < 4; j++) {
        int n = nb + ty + j * 8;
        int k = rb + tx;
        float v = t[tx][ty + j * 8];
        __nv_bfloat16 h = __float2bfloat16(v);
        size_t o = (size_t)n * 4096 + k;
        hi[o] = h;
        lo[o] = __float2bfloat16(v - __bfloat162float(h));
    }
}

// ---- fused reduce(2)+bias+relu + transposed split for the 4 x7 tensors ----
struct Bias4 { const float* b[4]; };
__global__ void k_fuse7(const float* __restrict__ P, Bias4 bias,
                        __nv_bfloat16* __restrict__ hi, __nv_bfloat16* __restrict__ lo) {
    __shared__ float t[32][33];
    int br = blockIdx.z;
    const float* p = P + (size_t)br * 1228800;
    int rb = blockIdx.x * 32, nb = blockIdx.y * 32;
    int tx = threadIdx.x, ty = threadIdx.y;
    #pragma unroll
    for (int j = 0; j < 4; j++) {
        int row = rb + ty + j * 8;
        int n = nb + tx;
        float v = 0.f;
        if (n < 300) {
            size_t o = (size_t)row * 300 + n;
            v = fmaxf(p[o] + p[o + 4 * 1228800] + bias.b[br][row], 0.f);
        }
        t[ty + j * 8][tx] = v;
    }
    __syncthreads();
    #pragma unroll
    for (int j = 0; j < 4; j++) {
        int n = nb + ty + j * 8;
        int k = rb + tx;
        float v = t[tx][ty + j * 8];
        __nv_bfloat16 h = __float2bfloat16(v);
        size_t o = (size_t)br * 1310720 + (size_t)n * 4096 + k;
        hi[o] = h;
        lo[o] = __float2bfloat16(v - __bfloat162float(h));
    }
}

// ---- fused reduce(4)+bias + pixel-shuffle for all branches ----
__global__ void k_fuse8(const float* __restrict__ p, Bias4 bias, float* __restrict__ out) {
    int i = blockIdx.x * blockDim.x + threadIdx.x;
    if (i >= 518400) return;
    int br, start, r;
    long oofs;
    if (i < 76800)       { br = 0; start = 0;      r = 8; oofs = 1228800L; }
    else if (i < 115200) { br = 1; start = 76800;  r = 8; oofs = 1305600L; }
    else if (i < 422400) { br = 2; start = 115200; r = 4; oofs = 1344000L; }
    else                 { br = 3; start = 422400; r = 8; oofs = 1651200L; }
    int li = i - start;
    int OW = 20 * r;
    int OHW = 300 * r * r;
    int oc = li / OHW, rem = li % OHW;
    int oh = rem / OW, ow = rem % OW;
    int ic = oc * r * r + (oh % r) * r + (ow % r);
    int src = start + ic * 300 + (oh / r) * 20 + (ow / r);
    float v = p[src] + p[src + 518400] + p[src + 2 * 518400] + p[src + 3 * 518400];
    out[oofs + li] = v + bias.b[br][ic];
}

// ---- generic split-K reduce (conv2..5) ----
__global__ void k_redG(const float* __restrict__ p, const float* __restrict__ bias,
                       float* __restrict__ out, int total, int Ncols, int S,
                       long stride, int relu) {
    int i = blockIdx.x * blockDim.x + threadIdx.x;
    if (i >= total) return;
    float v = 0.f;
    for (int s = 0; s < S; s++) v += p[(size_t)s * stride + i];
    v += bias[i / Ncols];
    out[i] = relu ? fmaxf(v, 0.f) : v;
}

// ============================ HMMA GEMM core ============================
// CTA tile 128x64, BK=32, 128 threads = 4 warps of 64x32 (2m x 2n):
// minimal smem-crossbar duplication (A x2, B x2). Ping-pong, 1 barrier/chunk.
#define STG 24576
#define GT_SMEM (2 * STG + 1024)

__device__ __forceinline__ void gemm_core(
    char* dsm, const float* __restrict__ A, const __nv_bfloat16* __restrict__ Bh,
    const __nv_bfloat16* __restrict__ Bl, const float* __restrict__ bias,
    float* __restrict__ C, int M, int K, int Ncols, int relu, int m0, int n0,
    int c0, int cEnd) {
    const int tid = threadIdx.x;
    const int lane = tid & 31;
    const int wid = tid >> 5;           // 0..3
    const int wm = wid & 1, wn = wid >> 1;

    const uint32_t base = (smem_u32(dsm) + 1023u) & ~1023u;

    uint32_t pA[4], pB[2];
    {
        uint32_t kc = (uint32_t)((lane >> 4) * 16);
        #pragma unroll
        for (int mt = 0; mt < 4; mt++) {
            uint32_t o = (uint32_t)(wm * 64 + mt * 16 + (lane & 15)) * 64 + kc;
            pA[mt] = o ^ ((o >> 3) & 0x30);
        }
        uint32_t rn = (uint32_t)(wn * 32 + (lane & 7) + ((lane >> 4) << 3));
        uint32_t kcb = (uint32_t)(((lane >> 3) & 1) * 16);
        #pragma unroll
        for (int nt = 0; nt < 2; nt++) {
            uint32_t o = (rn + nt * 16) * 64 + kcb;
            pB[nt] = o ^ ((o >> 3) & 0x30);
        }
    }

    float acc[4][4][4] = {};

    for (int c = c0; c < cEnd; c++) {
        const uint32_t stg = base + (uint32_t)(c & 1) * STG;
        const int k0 = c << 5;
        // A: 128 rows x 32 k fp32 -> split -> smem (512 slots of 8, 4 iters)
        #pragma unroll
        for (int it = 0; it < 4; it++) {
            int idx = tid + it * 128;
            int row = idx >> 2, f8 = idx & 3;
            int gr = m0 + row, k = k0 + f8 * 8;
            float4 v0, v1;
            if (gr < M) {
                v0 = *reinterpret_cast<const float4*>(A + (size_t)gr * K + k);
                v1 = *reinterpret_cast<const float4*>(A + (size_t)gr * K + k + 4);
            } else {
                v0 = v1 = make_float4(0.f, 0.f, 0.f, 0.f);
            }
            float s[8] = {v0.x, v0.y, v0.z, v0.w, v1.x, v1.y, v1.z, v1.w};
            __nv_bfloat16 h[8];
            float l[8];
            #pragma unroll
            for (int e = 0; e < 8; e++) {
                h[e] = __float2bfloat16(s[e]);
                l[e] = s[e] - __bfloat162float(h[e]);
            }
            uint4 hv = make_uint4(pack2(h[0], h[1]), pack2(h[2], h[3]),
                                  pack2(h[4], h[5]), pack2(h[6], h[7]));
            uint4 lv = make_uint4(packbf2(l[0], l[1]), packbf2(l[2], l[3]),
                                  packbf2(l[4], l[5]), packbf2(l[6], l[7]));
            uint32_t off = swz64((uint32_t)(row * 64 + f8 * 16));
            sts128(stg + off, hv);
            sts128(stg + 8192u + off, lv);
        }
        // B: 64 rows x 32 k bf16 (pre-split) -> smem (256 slots, 2 iters)
        #pragma unroll
        for (int it = 0; it < 2; it++) {
            int idx = tid + it * 128;
            int r = idx >> 2, f = idx & 3;
            uint4 vh = *reinterpret_cast<const uint4*>(Bh + (size_t)(n0 + r) * K + k0 + f * 8);
            uint4 vl = *reinterpret_cast<const uint4*>(Bl + (size_t)(n0 + r) * K + k0 + f * 8);
            uint32_t off = swz64((uint32_t)(r * 64 + f * 16));
            sts128(stg + 16384u + off, vh);
            sts128(stg + 20480u + off, vl);
        }
        __syncthreads();   // one barrier per chunk (ping-pong)
        #pragma unroll
        for (int ks = 0; ks < 2; ks++) {
            const uint32_t kb = (uint32_t)(ks << 5);
            uint32_t ah[4][4], al[4][4], bh_[2][4], bl_[2][4];
            #pragma unroll
            for (int mt = 0; mt < 4; mt++) {
                ldm4(ah[mt], stg + (pA[mt] ^ kb));
                ldm4(al[mt], stg + 8192u + (pA[mt] ^ kb));
            }
            #pragma unroll
            for (int nt = 0; nt < 2; nt++) {
                ldm4(bh_[nt], stg + 16384u + (pB[nt] ^ kb));
                ldm4(bl_[nt], stg + 20480u + (pB[nt] ^ kb));
            }
            #pragma unroll
            for (int mt = 0; mt < 4; mt++)
                #pragma unroll
                for (int nt2 = 0; nt2 < 4; nt2++) {
                    const uint32_t* bh2 = &bh_[nt2 >> 1][(nt2 & 1) * 2];
                    const uint32_t* bl2 = &bl_[nt2 >> 1][(nt2 & 1) * 2];
                    mma_bf16(acc[mt][nt2], ah[mt], bh2);
                    mma_bf16(acc[mt][nt2], ah[mt], bl2);
                    mma_bf16(acc[mt][nt2], al[mt], bh2);
                }
        }
    }

    #pragma unroll
    for (int mt = 0; mt < 4; mt++) {
        int r0 = m0 + wm * 64 + mt * 16 + (lane >> 2);
        #pragma unroll
        for (int half = 0; half < 2; half++) {
            int row = r0 + half * 8;
            if (row >= M) continue;
            float bv = bias ? bias[row] : 0.f;
            #pragma unroll
            for (int nt2 = 0; nt2 < 4; nt2++) {
                int col = n0 + wn * 32 + nt2 * 8 + (lane & 3) * 2;
                float v0 = acc[mt][nt2][half * 2 + 0] + bv;
                float v1 = acc[mt][nt2][half * 2 + 1] + bv;
                if (relu) { v0 = fmaxf(v0, 0.f); v1 = fmaxf(v1, 0.f); }
                if (col < Ncols) C[(size_t)row * Ncols + col] = v0;
                if (col + 1 < Ncols) C[(size_t)row * Ncols + col + 1] = v1;
            }
        }
    }
}

__global__ __launch_bounds__(128, 3) void k_gemm_skG(
    const float* __restrict__ A, const __nv_bfloat16* __restrict__ Bh,
    const __nv_bfloat16* __restrict__ Bl, float* __restrict__ P,
    int M, int K, int Ncols, int S, long stride) {
    extern __shared__ char dsm[];
    const int z = blockIdx.z;
    const int nc = K >> 5;
    const int per = nc / S, rem = nc % S;
    const int c0 = z * per + (z < rem ? z : rem);
    const int cEnd = c0 + per + (z < rem ? 1 : 0);
    gemm_core(dsm, A, Bh, Bl, nullptr, P + (size_t)z * stride,
              M, K, Ncols, 0, blockIdx.y * 128, blockIdx.x * 64, c0, cEnd);
}

__global__ __launch_bounds__(128, 3) void k_gemm_sk6(
    const float* __restrict__ A, const __nv_bfloat16* __restrict__ Bh,
    const __nv_bfloat16* __restrict__ Bl, float* __restrict__ P) {
    extern __shared__ char dsm[];
    const int z = blockIdx.z;
    const int per = (13824 >> 5) >> 2;
    gemm_core(dsm, A, Bh, Bl, nullptr, P + (size_t)z * 1228800,
              4096, 13824, 300, 0, blockIdx.y * 128, blockIdx.x * 64,
              z * per, (z + 1) * per);
}

struct Ptr4 { const float* p[4]; };
__global__ __launch_bounds__(128, 3) void k_gemm7(
    Ptr4 W, const __nv_bfloat16* __restrict__ Bh,
    const __nv_bfloat16* __restrict__ Bl, float* __restrict__ P) {
    extern __shared__ char dsm[];
    const int br = blockIdx.z >> 1, sl = blockIdx.z & 1;
    const int per = 128 >> 1;
    float* out = P + (size_t)sl * 4 * 1228800 + (size_t)br * 1228800;
    gemm_core(dsm, W.p[br], Bh, Bl, nullptr, out,
              4096, 4096, 300, 0, blockIdx.y * 128, blockIdx.x * 64,
              sl * per, (sl + 1) * per);
}

__global__ __launch_bounds__(128, 3) void k_gemm8(
    Ptr4 W, const __nv_bfloat16* __restrict__ Bh,
    const __nv_bfloat16* __restrict__ Bl, float* __restrict__ P) {
    extern __shared__ char dsm[];
    const int br = blockIdx.z >> 2, sl = blockIdx.z & 3;
    const int C8s[4] = {256, 128, 1024, 320};
    const int roff[4] = {0, 256, 384, 1408};
    const int M = C8s[br];
    const int m0 = blockIdx.y * 128;
    if (m0 >= M) return;
    const int per = 128 >> 2;
    float* out = P + (size_t)sl * 518400 + (size_t)roff[br] * 300;
    gemm_core(dsm, W.p[br], Bh + (size_t)br * 1310720, Bl + (size_t)br * 1310720,
              nullptr, out, M, 4096, 300, 0, m0, blockIdx.x * 64,
              sl * per, (sl + 1) * per);
}

static inline dim3 blk1(long n) { return dim3((unsigned)((n + 255) / 256)); }

extern "C" void kernel_launch(void* const* d_in, const int* in_sizes, int n_in,
                              void* d_out, int out_size) {
    const float* x  = (const float*)d_in[0];
    const float* w1 = (const float*)d_in[1];  const float* b1 = (const float*)d_in[2];
    const float* w2 = (const float*)d_in[3];  const float* b2 = (const float*)d_in[4];
    const float* w3 = (const float*)d_in[5];  const float* b3 = (const float*)d_in[6];
    const float* w4 = (const float*)d_in[7];  const float* b4 = (const float*)d_in[8];
    const float* w5 = (const float*)d_in[9];  const float* b5 = (const float*)d_in[10];
    const float* w6 = (const float*)d_in[11]; const float* b6 = (const float*)d_in[12];
    const float* w7[4] = {(const float*)d_in[13], (const float*)d_in[17],
                          (const float*)d_in[21], (const float*)d_in[25]};
    const float* b7[4] = {(const float*)d_in[14], (const float*)d_in[18],
                          (const float*)d_in[22], (const float*)d_in[26]};
    const float* w8[4] = {(const float*)d_in[15], (const float*)d_in[19],
                          (const float*)d_in[23], (const float*)d_in[27]};
    const float* b8[4] = {(const float*)d_in[16], (const float*)d_in[20],
                          (const float*)d_in[24], (const float*)d_in[28]};
    float* out = (float*)d_out;

    cudaFuncSetAttribute(k_gemm_skG, cudaFuncAttributeMaxDynamicSharedMemorySize, GT_SMEM);
    cudaFuncSetAttribute(k_gemm_sk6, cudaFuncAttributeMaxDynamicSharedMemorySize, GT_SMEM);
    cudaFuncSetAttribute(k_gemm7,    cudaFuncAttributeMaxDynamicSharedMemorySize, GT_SMEM);
    cudaFuncSetAttribute(k_gemm8,    cudaFuncAttributeMaxDynamicSharedMemorySize, GT_SMEM);

    float *c1, *u1, *c2, *p2, *c3, *c4, *c5, *p5, *p6, *p7, *p8;
    __nv_bfloat16 *bh, *bl, *b6h, *b6l;
    cudaGetSymbolAddress((void**)&c1, g_c1);
    cudaGetSymbolAddress((void**)&u1, g_u1);
    cudaGetSymbolAddress((void**)&c2, g_c2);
    cudaGetSymbolAddress((void**)&p2, g_p2);
    cudaGetSymbolAddress((void**)&c3, g_c3);
    cudaGetSymbolAddress((void**)&c4, g_c4);
    cudaGetSymbolAddress((void**)&c5, g_c5);
    cudaGetSymbolAddress((void**)&p5, g_p5);
    cudaGetSymbolAddress((void**)&p6, g_p6);
    cudaGetSymbolAddress((void**)&p7, g_p7);
    cudaGetSymbolAddress((void**)&p8, g_p8);
    cudaGetSymbolAddress((void**)&bh, gB_hi);
    cudaGetSymbolAddress((void**)&bl, gB_lo);
    cudaGetSymbolAddress((void**)&b6h, gB6_hi);
    cudaGetSymbolAddress((void**)&b6l, gB6_lo);

    // stage 1: direct conv1 -> fused LRN+pool+upsample
    k_conv1<<<blk1(96L * 118 * 158), 256>>>(x, w1, b1, c1);
    k_pooluplrn<<<blk1(96L * 59 * 79), 256>>>(c1, u1);

    // conv2: M=256 K=2400 N=4661 (Npad 4672), split-K=3 (75 chunks -> 25)
    k_prepB4<5><<<dim3(3, 4672), 256>>>(u1, bh, bl, 59, 79, 2, 59, 79, 2400);
    k_gemm_skG<<<dim3(73, 2, 3), 128, GT_SMEM>>>(w2, bh, bl, p6,
                                                 256, 2400, 4661, 3, 1193216L);
    k_redG<<<blk1(1193216L), 256>>>(p6, b2, c2, 1193216, 4661, 3, 1193216L, 1);
    k_poollrn<<<blk1(256L * 29 * 39), 256>>>(c2, p2, 256, 59, 79, 29, 39, 8.0f, 1e-4f);

    // conv3: M=384 K=2304 N=1131 (Npad 1152), split-K=6 (72 -> 12)
    k_prepB4<3><<<dim3(3, 1152), 256>>>(p2, bh, bl, 29, 39, 1, 29, 39, 2304);
    k_gemm_skG<<<dim3(18, 3, 6), 128, GT_SMEM>>>(w3, bh, bl, p6,
                                                 384, 2304, 1131, 6, 434304L);
    k_redG<<<blk1(434304L), 256>>>(p6, b3, c3, 434304, 1131, 6, 434304L, 1);
    // conv4: K=3456, split-K=6 (108 -> 18)
    k_prepB4<3><<<dim3(4, 1152), 256>>>(c3, bh, bl, 29, 39, 1, 29, 39, 3456);
    k_gemm_skG<<<dim3(18, 3, 6), 128, GT_SMEM>>>(w4, bh, bl, p6,
                                                 384, 3456, 1131, 6, 434304L);
    k_redG<<<blk1(434304L), 256>>>(p6, b4, c4, 434304, 1131, 6, 434304L, 1);
    // conv5
    k_prepB4<3><<<dim3(4, 1152), 256>>>(c4, bh, bl, 29, 39, 1, 29, 39, 3456);
    k_gemm_skG<<<dim3(18, 3, 6), 128, GT_SMEM>>>(w5, bh, bl, p6,
                                                 384, 3456, 1131, 6, 434304L);
    k_redG<<<blk1(434304L), 256>>>(p6, b5, c5, 434304, 1131, 6, 434304L, 1);
    k_pool<<<blk1(384L * 14 * 19), 256>>>(c5, p5, 384, 29, 39, 14, 19);

    // conv6: split-K=4 -> fused reduce+relu -> d_out + transposed split
    k_prepB4<6><<<dim3(14, 320), 256>>>(p5, bh, bl, 14, 19, 3, 15, 20, 13824);
    k_gemm_sk6<<<dim3(5, 32, 4), 128, GT_SMEM>>>(w6, bh, bl, p6);
    k_fuse6<<<dim3(128, 10), dim3(32, 8)>>>(p6, b6, out, b6h, b6l);

    // gemm7 (4 branches, split-K=2) -> fused reduce+relu+transposed split
    Ptr4 W7 = {{w7[0], w7[1], w7[2], w7[3]}};
    k_gemm7<<<dim3(5, 32, 8), 128, GT_SMEM>>>(W7, b6h, b6l, p7);
    Bias4 B7 = {{b7[0], b7[1], b7[2], b7[3]}};
    k_fuse7<<<dim3(128, 10, 4), dim3(32, 8)>>>(p7, B7, bh, bl);

    // gemm8 (4 branches packed, split-K=4) -> fused reduce+bias+pixel-shuffle
    Ptr4 W8 = {{w8[0], w8[1], w8[2], w8[3]}};
    k_gemm8<<<dim3(5, 8, 16), 128, GT_SMEM>>>(W8, bh, bl, p8);
    Bias4 B8 = {{b8[0], b8[1], b8[2], b8[3]}};
    k_fuse8<<<blk1(518400L), 256>>>(p8, B8, out);
}

// round 11
// speedup vs baseline: 1.7843x; 1.7843x over previous
#include <cuda_runtime.h>
#include <cuda_bf16.h>
#include <math.h>
#include <stdint.h>

// ---------------------------------------------------------------------------
// VPGNet forward. Conv2..8 as split-bf16 HMMA GEMMs (fp32 accumulate).
// R9 GEMM shape (8 warps, 32x32 warp tiles, reg A-prefetch) + cp.async B.
// Output: [x6|x8a|x8b|x8c|x8d] = 1,747,200 floats
// ---------------------------------------------------------------------------

// ---- scratch ----
__device__ float g_c1[96 * 118 * 158];
__device__ float g_u1[96 * 59 * 79];
__device__ float g_c2[256 * 59 * 79];
__device__ float g_p2[256 * 29 * 39];
__device__ float g_c3[384 * 29 * 39];
__device__ float g_c4[384 * 29 * 39];
__device__ float g_c5[384 * 29 * 39];
__device__ float g_p5[384 * 14 * 19];
__device__ float g_p6[4 * 4096 * 300];        // split-K partials (also conv2..5)
__device__ float g_p7[2 * 4 * 4096 * 300];
__device__ float g_p8[4 * 1728 * 300];
// bf16 split activation buffers [Npad][K]; max conv2 4672*2400 = 11.2M
__device__ __nv_bfloat16 gB_hi[11250000];
__device__ __nv_bfloat16 gB_lo[11250000];
__device__ __nv_bfloat16 gB6_hi[320 * 4096];
__device__ __nv_bfloat16 gB6_lo[320 * 4096];

// ============================ helpers ============================
__device__ __forceinline__ uint32_t smem_u32(const void* p) {
    uint32_t a;
    asm("{ .reg .u64 t; cvta.to.shared.u64 t, %1; cvt.u32.u64 %0, t; }" : "=r"(a) : "l"(p));
    return a;
}
__device__ __forceinline__ uint32_t swz64(uint32_t o) { return o ^ ((o >> 3) & 0x30); }

__device__ __forceinline__ void ldm4(uint32_t* r, uint32_t a) {
    asm volatile("ldmatrix.sync.aligned.m8n8.x4.shared.b16 {%0,%1,%2,%3}, [%4];"
                 : "=r"(r[0]), "=r"(r[1]), "=r"(r[2]), "=r"(r[3]) : "r"(a));
}
__device__ __forceinline__ void mma_bf16(float* c, const uint32_t* a, const uint32_t* b) {
    asm volatile("mma.sync.aligned.m16n8k16.row.col.f32.bf16.bf16.f32 "
                 "{%0,%1,%2,%3}, {%4,%5,%6,%7}, {%8,%9}, {%0,%1,%2,%3};"
                 : "+f"(c[0]), "+f"(c[1]), "+f"(c[2]), "+f"(c[3])
                 : "r"(a[0]), "r"(a[1]), "r"(a[2]), "r"(a[3]), "r"(b[0]), "r"(b[1]));
}
__device__ __forceinline__ void sts128(uint32_t a, uint4 v) {
    asm volatile("st.shared.v4.b32 [%0], {%1,%2,%3,%4};"
                 :: "r"(a), "r"(v.x), "r"(v.y), "r"(v.z), "r"(v.w) : "memory");
}
__device__ __forceinline__ void cpasync16(uint32_t saddr, const void* gaddr) {
    asm volatile("cp.async.cg.shared.global [%0], [%1], 16;"
                 :: "r"(saddr), "l"(gaddr) : "memory");
}
__device__ __forceinline__ void cpasync_commit() {
    asm volatile("cp.async.commit_group;" ::: "memory");
}
__device__ __forceinline__ void cpasync_wait0() {
    asm volatile("cp.async.wait_group 0;" ::: "memory");
}
__device__ __forceinline__ uint32_t packbf2(float lo, float hi) {
    uint32_t d;
    asm("cvt.rn.bf16x2.f32 %0, %1, %2;" : "=r"(d) : "f"(hi), "f"(lo));
    return d;
}
__device__ __forceinline__ uint32_t pack2(__nv_bfloat16 a, __nv_bfloat16 b) {
    return (uint32_t)__bfloat16_as_ushort(a) | ((uint32_t)__bfloat16_as_ushort(b) << 16);
}

// ============================ elementwise layers ============================
__global__ void k_conv1(const float* __restrict__ x, const float* __restrict__ w,
                        const float* __restrict__ b, float* __restrict__ out) {
    const int HO = 118, WO = 158;
    int i = blockIdx.x * blockDim.x + threadIdx.x;
    if (i >= 96 * HO * WO) return;
    int c = i / (HO * WO), r = i % (HO * WO), oh = r / WO, ow = r % WO;
    float acc = b[c];
    const float* wp = w + c * 3 * 121;
    for (int ci = 0; ci < 3; ci++) {
        const float* xc = x + ci * 480 * 640;
        const float* wc = wp + ci * 121;
        #pragma unroll
        for (int kh = 0; kh < 11; kh++) {
            const float* xp = xc + (oh * 4 + kh) * 640 + ow * 4;
            const float* wq = wc + kh * 11;
            #pragma unroll
            for (int kw = 0; kw < 11; kw++) acc = fmaf(xp[kw], wq[kw], acc);
        }
    }
    out[i] = fmaxf(acc, 0.f);
}

// stage-1 fused LRN + maxpool3s2 + upsample (59,79)
__global__ void k_pooluplrn(const float* __restrict__ c1, float* __restrict__ out) {
    int i = blockIdx.x * blockDim.x + threadIdx.x;
    if (i >= 96 * 59 * 79) return;
    int c = i / (59 * 79), r = i % (59 * 79), oh = r / 79, ow = r % 79;
    int hi = (oh * 58) / 59, wi = (ow * 78) / 79;
    int jlo = c - 2 > 0 ? c - 2 : 0;
    int jhi = c + 2 < 95 ? c + 2 : 95;
    const int HW = 118 * 158;
    float m = -1e30f;
    #pragma unroll
    for (int dh = 0; dh < 3; dh++) {
        #pragma unroll
        for (int dw = 0; dw < 3; dw++) {
            const float* p = c1 + (2 * hi + dh) * 158 + 2 * wi + dw;
            float s = 0.f;
            for (int j = jlo; j <= jhi; j++) { float v = p[j * HW]; s = fmaf(v, v, s); }
            float t = 2.0f + 1e-4f * s;
            float rr = rsqrtf(t);
            m = fmaxf(m, p[c * HW] * rr * sqrtf(rr));
        }
    }
    out[i] = m;
}

// conv2 fused LRN(k=8) + maxpool3s2
__global__ void k_poollrn(const float* __restrict__ in, float* __restrict__ out,
                          int C, int Hin, int Win, int Ho, int Wo,
                          float kc, float a) {
    int i = blockIdx.x * blockDim.x + threadIdx.x;
    if (i >= C * Ho * Wo) return;
    int c = i / (Ho * Wo), r = i % (Ho * Wo), oh = r / Wo, ow = r % Wo;
    int jlo = c - 2 > 0 ? c - 2 : 0;
    int jhi = c + 2 < C - 1 ? c + 2 : C - 1;
    const int HW = Hin * Win;
    float m = -1e30f;
    #pragma unroll
    for (int dh = 0; dh < 3; dh++) {
        #pragma unroll
        for (int dw = 0; dw < 3; dw++) {
            const float* p = in + (2 * oh + dh) * Win + 2 * ow + dw;
            float s = 0.f;
            for (int j = jlo; j <= jhi; j++) { float v = p[j * HW]; s = fmaf(v, v, s); }
            float t = kc + a * s;
            float rr = rsqrtf(t);
            m = fmaxf(m, p[c * HW] * rr * sqrtf(rr));
        }
    }
    out[i] = m;
}

__global__ void k_pool(const float* __restrict__ in, float* __restrict__ out,
                       int C, int Hin, int Win, int Ho, int Wo) {
    int i = blockIdx.x * blockDim.x + threadIdx.x;
    if (i >= C * Ho * Wo) return;
    int c = i / (Ho * Wo), r = i % (Ho * Wo), oh = r / Wo, ow = r % Wo;
    const float* p = in + (c * Hin + 2 * oh) * Win + 2 * ow;
    float m = p[0];
    #pragma unroll
    for (int dh = 0; dh < 3; dh++)
        #pragma unroll
        for (int dw = 0; dw < 3; dw++) m = fmaxf(m, p[dh * Win + dw]);
    out[i] = m;
}

// ---- im2col + transpose + split, 8 k-positions per thread, uint4 stores ----
template <int KSZ>
__global__ void k_prepB8(const float* __restrict__ src, __nv_bfloat16* __restrict__ hi,
                         __nv_bfloat16* __restrict__ lo, int H, int W, int pad,
                         int Ho, int Wo, int K) {
    int kidx = (blockIdx.x * 256 + threadIdx.x) * 8;
    if (kidx >= K) return;
    int n = blockIdx.y;
    int oh = n / Wo, ow = n % Wo;
    bool vn = n < Ho * Wo;
    int kw = kidx % KSZ;
    int t = kidx / KSZ;
    int kh = t % KSZ, cc = t / KSZ;
    float v[8];
    #pragma unroll
    for (int j = 0; j < 8; j++) {
        float val = 0.f;
        if (vn) {
            int ih = oh - pad + kh, iw = ow - pad + kw;
            if (ih >= 0 && ih < H && iw >= 0 && iw < W)
                val = src[((size_t)cc * H + ih) * W + iw];
        }
        v[j] = val;
        if (++kw == KSZ) { kw = 0; if (++kh == KSZ) { kh = 0; ++cc; } }
    }
    __nv_bfloat16 h[8];
    float l[8];
    #pragma unroll
    for (int e = 0; e < 8; e++) {
        h[e] = __float2bfloat16(v[e]);
        l[e] = v[e] - __bfloat162float(h[e]);
    }
    uint4 ph = make_uint4(pack2(h[0], h[1]), pack2(h[2], h[3]),
                          pack2(h[4], h[5]), pack2(h[6], h[7]));
    uint4 pl = make_uint4(packbf2(l[0], l[1]), packbf2(l[2], l[3]),
                          packbf2(l[4], l[5]), packbf2(l[6], l[7]));
    size_t o = (size_t)n * K + kidx;
    *reinterpret_cast<uint4*>(hi + o) = ph;
    *reinterpret_cast<uint4*>(lo + o) = pl;
}

// ---- fused reduce(4)+bias+relu -> d_out(x6) AND transposed bf16 split ----
__global__ void k_fuse6(const float* __restrict__ p, const float* __restrict__ bias,
                        float* __restrict__ out, __nv_bfloat16* __restrict__ hi,
                        __nv_bfloat16* __restrict__ lo) {
    __shared__ float t[32][33];
    int rb = blockIdx.x * 32, nb = blockIdx.y * 32;
    int tx = threadIdx.x, ty = threadIdx.y;
    #pragma unroll
    for (int j = 0; j < 4; j++) {
        int row = rb + ty + j * 8;
        int n = nb + tx;
        float v = 0.f;
        if (n < 300) {
            size_t o = (size_t)row * 300 + n;
            v = fmaxf(p[o] + p[o + 1228800] + p[o + 2 * 1228800] + p[o + 3 * 1228800]
                      + bias[row], 0.f);
            out[o] = v;
        }
        t[ty + j * 8][tx] = v;
    }
    __syncthreads();
    #pragma unroll
    for (int j = 0; j < 4; j++) {
        int n = nb + ty + j * 8;
        int k = rb + tx;
        float v = t[tx][ty + j * 8];
        __nv_bfloat16 h = __float2bfloat16(v);
        size_t o = (size_t)n * 4096 + k;
        hi[o] = h;
        lo[o] = __float2bfloat16(v - __bfloat162float(h));
    }
}

// ---- fused reduce(2)+bias+relu + transposed split for the 4 x7 tensors ----
struct Bias4 { const float* b[4]; };
__global__ void k_fuse7(const float* __restrict__ P, Bias4 bias,
                        __nv_bfloat16* __restrict__ hi, __nv_bfloat16* __restrict__ lo) {
    __shared__ float t[32][33];
    int br = blockIdx.z;
    const float* p = P + (size_t)br * 1228800;
    int rb = blockIdx.x * 32, nb = blockIdx.y * 32;
    int tx = threadIdx.x, ty = threadIdx.y;
    #pragma unroll
    for (int j = 0; j < 4; j++) {
        int row = rb + ty + j * 8;
        int n = nb + tx;
        float v = 0.f;
        if (n < 300) {
            size_t o = (size_t)row * 300 + n;
            v = fmaxf(p[o] + p[o + 4 * 1228800] + bias.b[br][row], 0.f);
        }
        t[ty + j * 8][tx] = v;
    }
    __syncthreads();
    #pragma unroll
    for (int j = 0; j < 4; j++) {
        int n = nb + ty + j * 8;
        int k = rb + tx;
        float v = t[tx][ty + j * 8];
        __nv_bfloat16 h = __float2bfloat16(v);
        size_t o = (size_t)br * 1310720 + (size_t)n * 4096 + k;
        hi[o] = h;
        lo[o] = __float2bfloat16(v - __bfloat162float(h));
    }
}

// ---- fused reduce(4)+bias + pixel-shuffle for all branches ----
__global__ void k_fuse8(const float* __restrict__ p, Bias4 bias, float* __restrict__ out) {
    int i = blockIdx.x * blockDim.x + threadIdx.x;
    if (i >= 518400) return;
    int br, start, r;
    long oofs;
    if (i < 76800)       { br = 0; start = 0;      r = 8; oofs = 1228800L; }
    else if (i < 115200) { br = 1; start = 76800;  r = 8; oofs = 1305600L; }
    else if (i < 422400) { br = 2; start = 115200; r = 4; oofs = 1344000L; }
    else                 { br = 3; start = 422400; r = 8; oofs = 1651200L; }
    int li = i - start;
    int OW = 20 * r;
    int OHW = 300 * r * r;
    int oc = li / OHW, rem = li % OHW;
    int oh = rem / OW, ow = rem % OW;
    int ic = oc * r * r + (oh % r) * r + (ow % r);
    int src = start + ic * 300 + (oh / r) * 20 + (ow / r);
    float v = p[src] + p[src + 518400] + p[src + 2 * 518400] + p[src + 3 * 518400];
    out[oofs + li] = v + bias.b[br][ic];
}

// ---- generic split-K reduce (conv2..5) ----
__global__ void k_redG(const float* __restrict__ p, const float* __restrict__ bias,
                       float* __restrict__ out, int total, int Ncols, int S,
                       long stride, int relu) {
    int i = blockIdx.x * blockDim.x + threadIdx.x;
    if (i >= total) return;
    float v = 0.f;
    for (int s = 0; s < S; s++) v += p[(size_t)s * stride + i];
    v += bias[i / Ncols];
    out[i] = relu ? fmaxf(v, 0.f) : v;
}

// ============================ HMMA GEMM core ============================
// CTA tile 128x64, BK=32, 256 threads, 8 warps 4m x 2n (32x32 warp tiles).
// A: fp32 reg-prefetch + in-kernel split. B: cp.async double buffer.
#define STG 24576
#define GT_SMEM (2 * STG + 1024)

__device__ __forceinline__ void gemm_core(
    char* dsm, const float* __restrict__ A, const __nv_bfloat16* __restrict__ Bh,
    const __nv_bfloat16* __restrict__ Bl, const float* __restrict__ bias,
    float* __restrict__ C, int M, int K, int Ncols, int relu, int m0, int n0,
    int c0, int cEnd) {
    const int tid = threadIdx.x;
    const int lane = tid & 31;
    const int wid = tid >> 5;
    const int wm = wid & 3, wn = wid >> 2;

    const uint32_t base = (smem_u32(dsm) + 1023u) & ~1023u;
    const int bR = tid >> 2, bF = tid & 3;
    const uint32_t bOff = swz64((uint32_t)(bR * 64 + bF * 16));
    const __nv_bfloat16* bhSrc = Bh + (size_t)(n0 + bR) * K + bF * 8;
    const __nv_bfloat16* blSrc = Bl + (size_t)(n0 + bR) * K + bF * 8;

    uint32_t pA[2], pB[2];
    {
        uint32_t r = (uint32_t)(wm * 32 + (lane & 15));
        uint32_t kc = (uint32_t)((lane >> 4) * 16);
        #pragma unroll
        for (int mt = 0; mt < 2; mt++) {
            uint32_t o = (r + mt * 16) * 64 + kc;
            pA[mt] = o ^ ((o >> 3) & 0x30);
        }
        uint32_t rn = (uint32_t)(wn * 32 + (lane & 7) + ((lane >> 4) << 3));
        uint32_t kcb = (uint32_t)(((lane >> 3) & 1) * 16);
        #pragma unroll
        for (int nt = 0; nt < 2; nt++) {
            uint32_t o = (rn + nt * 16) * 64 + kcb;
            pB[nt] = o ^ ((o >> 3) & 0x30);
        }
    }

    float acc[2][4][4] = {};

    float4 aP[2][2];
    {
        const int k0 = c0 << 5;
        #pragma unroll
        for (int it = 0; it < 2; it++) {
            int idx = tid + it * 256;
            int row = idx >> 2, f8 = idx & 3;
            int gr = m0 + row, k = k0 + f8 * 8;
            if (gr < M) {
                aP[it][0] = *reinterpret_cast<const float4*>(A + (size_t)gr * K + k);
                aP[it][1] = *reinterpret_cast<const float4*>(A + (size_t)gr * K + k + 4);
            } else {
                aP[it][0] = aP[it][1] = make_float4(0.f, 0.f, 0.f, 0.f);
            }
        }
        // B chunk c0 via cp.async into stage (c0&1)
        const uint32_t stg0 = base + (uint32_t)(c0 & 1) * STG;
        cpasync16(stg0 + 16384u + bOff, bhSrc + k0);
        cpasync16(stg0 + 20480u + bOff, blSrc + k0);
        cpasync_commit();
    }

    for (int c = c0; c < cEnd; c++) {
        const uint32_t stg = base + (uint32_t)(c & 1) * STG;
        // A: split prefetched regs -> smem
        #pragma unroll
        for (int it = 0; it < 2; it++) {
            int idx = tid + it * 256;
            int row = idx >> 2, f8 = idx & 3;
            float s[8] = {aP[it][0].x, aP[it][0].y, aP[it][0].z, aP[it][0].w,
                          aP[it][1].x, aP[it][1].y, aP[it][1].z, aP[it][1].w};
            __nv_bfloat16 h[8];
            float l[8];
            #pragma unroll
            for (int e = 0; e < 8; e++) {
                h[e] = __float2bfloat16(s[e]);
                l[e] = s[e] - __bfloat162float(h[e]);
            }
            uint4 hv = make_uint4(pack2(h[0], h[1]), pack2(h[2], h[3]),
                                  pack2(h[4], h[5]), pack2(h[6], h[7]));
            uint4 lv = make_uint4(packbf2(l[0], l[1]), packbf2(l[2], l[3]),
                                  packbf2(l[4], l[5]), packbf2(l[6], l[7]));
            uint32_t off = swz64((uint32_t)(row * 64 + f8 * 16));
            sts128(stg + off, hv);
            sts128(stg + 8192u + off, lv);
        }
        cpasync_wait0();      // B(c) landed
        __syncthreads();      // publish A(c) + B(c); prior compute done
        if (c + 1 < cEnd) {
            const int k0 = (c + 1) << 5;
            #pragma unroll
            for (int it = 0; it < 2; it++) {
                int idx = tid + it * 256;
                int row = idx >> 2, f8 = idx & 3;
                int gr = m0 + row, k = k0 + f8 * 8;
                if (gr < M) {
                    aP[it][0] = *reinterpret_cast<const float4*>(A + (size_t)gr * K + k);
                    aP[it][1] = *reinterpret_cast<const float4*>(A + (size_t)gr * K + k + 4);
                } else {
                    aP[it][0] = aP[it][1] = make_float4(0.f, 0.f, 0.f, 0.f);
                }
            }
            const uint32_t stgN = base + (uint32_t)((c + 1) & 1) * STG;
            cpasync16(stgN + 16384u + bOff, bhSrc + k0);
            cpasync16(stgN + 20480u + bOff, blSrc + k0);
            cpasync_commit();
        }
        #pragma unroll
        for (int ks = 0; ks < 2; ks++) {
            const uint32_t kb = (uint32_t)(ks << 5);
            uint32_t ah[2][4], al[2][4], bh_[2][4], bl_[2][4];
            ldm4(ah[0], stg + (pA[0] ^ kb));
            ldm4(ah[1], stg + (pA[1] ^ kb));
            ldm4(al[0], stg + 8192u + (pA[0] ^ kb));
            ldm4(al[1], stg + 8192u + (pA[1] ^ kb));
            ldm4(bh_[0], stg + 16384u + (pB[0] ^ kb));
            ldm4(bh_[1], stg + 16384u + (pB[1] ^ kb));
            ldm4(bl_[0], stg + 20480u + (pB[0] ^ kb));
            ldm4(bl_[1], stg + 20480u + (pB[1] ^ kb));
            #pragma unroll
            for (int mt = 0; mt < 2; mt++)
                #pragma unroll
                for (int nt = 0; nt < 4; nt++) {
                    const uint32_t* bh2 = &bh_[nt >> 1][(nt & 1) * 2];
                    const uint32_t* bl2 = &bl_[nt >> 1][(nt & 1) * 2];
                    mma_bf16(acc[mt][nt], ah[mt], bh2);
                    mma_bf16(acc[mt][nt], ah[mt], bl2);
                    mma_bf16(acc[mt][nt], al[mt], bh2);
                }
        }
    }

    #pragma unroll
    for (int mt = 0; mt < 2; mt++) {
        int r0 = m0 + wm * 32 + mt * 16 + (lane >> 2);
        #pragma unroll
        for (int half = 0; half < 2; half++) {
            int row = r0 + half * 8;
            if (row >= M) continue;
            float bv = bias ? bias[row] : 0.f;
            #pragma unroll
            for (int nt = 0; nt < 4; nt++) {
                int col = n0 + wn * 32 + nt * 8 + (lane & 3) * 2;
                float v0 = acc[mt][nt][half * 2 + 0] + bv;
                float v1 = acc[mt][nt][half * 2 + 1] + bv;
                if (relu) { v0 = fmaxf(v0, 0.f); v1 = fmaxf(v1, 0.f); }
                if (col < Ncols) C[(size_t)row * Ncols + col] = v0;
                if (col + 1 < Ncols) C[(size_t)row * Ncols + col + 1] = v1;
            }
        }
    }
}

__global__ __launch_bounds__(256, 2) void k_gemm_skG(
    const float* __restrict__ A, const __nv_bfloat16* __restrict__ Bh,
    const __nv_bfloat16* __restrict__ Bl, float* __restrict__ P,
    int M, int K, int Ncols, int S, long stride) {
    extern __shared__ char dsm[];
    const int z = blockIdx.z;
    const int nc = K >> 5;
    const int per = nc / S, rem = nc % S;
    const int c0 = z * per + (z < rem ? z : rem);
    const int cEnd = c0 + per + (z < rem ? 1 : 0);
    gemm_core(dsm, A, Bh, Bl, nullptr, P + (size_t)z * stride,
              M, K, Ncols, 0, blockIdx.y * 128, blockIdx.x * 64, c0, cEnd);
}

__global__ __launch_bounds__(256, 2) void k_gemm_sk6(
    const float* __restrict__ A, const __nv_bfloat16* __restrict__ Bh,
    const __nv_bfloat16* __restrict__ Bl, float* __restrict__ P) {
    extern __shared__ char dsm[];
    const int z = blockIdx.z;
    const int per = (13824 >> 5) >> 2;
    gemm_core(dsm, A, Bh, Bl, nullptr, P + (size_t)z * 1228800,
              4096, 13824, 300, 0, blockIdx.y * 128, blockIdx.x * 64,
              z * per, (z + 1) * per);
}

struct Ptr4 { const float* p[4]; };
__global__ __launch_bounds__(256, 2) void k_gemm7(
    Ptr4 W, const __nv_bfloat16* __restrict__ Bh,
    const __nv_bfloat16* __restrict__ Bl, float* __restrict__ P) {
    extern __shared__ char dsm[];
    const int br = blockIdx.z >> 1, sl = blockIdx.z & 1;
    const int per = 128 >> 1;
    float* out = P + (size_t)sl * 4 * 1228800 + (size_t)br * 1228800;
    gemm_core(dsm, W.p[br], Bh, Bl, nullptr, out,
              4096, 4096, 300, 0, blockIdx.y * 128, blockIdx.x * 64,
              sl * per, (sl + 1) * per);
}

__global__ __launch_bounds__(256, 2) void k_gemm8(
    Ptr4 W, const __nv_bfloat16* __restrict__ Bh,
    const __nv_bfloat16* __restrict__ Bl, float* __restrict__ P) {
    extern __shared__ char dsm[];
    const int br = blockIdx.z >> 2, sl = blockIdx.z & 3;
    const int C8s[4] = {256, 128, 1024, 320};
    const int roff[4] = {0, 256, 384, 1408};
    const int M = C8s[br];
    const int m0 = blockIdx.y * 128;
    if (m0 >= M) return;
    const int per = 128 >> 2;
    float* out = P + (size_t)sl * 518400 + (size_t)roff[br] * 300;
    gemm_core(dsm, W.p[br], Bh + (size_t)br * 1310720, Bl + (size_t)br * 1310720,
              nullptr, out, M, 4096, 300, 0, m0, blockIdx.x * 64,
              sl * per, (sl + 1) * per);
}

static inline dim3 blk1(long n) { return dim3((unsigned)((n + 255) / 256)); }

extern "C" void kernel_launch(void* const* d_in, const int* in_sizes, int n_in,
                              void* d_out, int out_size) {
    const float* x  = (const float*)d_in[0];
    const float* w1 = (const float*)d_in[1];  const float* b1 = (const float*)d_in[2];
    const float* w2 = (const float*)d_in[3];  const float* b2 = (const float*)d_in[4];
    const float* w3 = (const float*)d_in[5];  const float* b3 = (const float*)d_in[6];
    const float* w4 = (const float*)d_in[7];  const float* b4 = (const float*)d_in[8];
    const float* w5 = (const float*)d_in[9];  const float* b5 = (const float*)d_in[10];
    const float* w6 = (const float*)d_in[11]; const float* b6 = (const float*)d_in[12];
    const float* w7[4] = {(const float*)d_in[13], (const float*)d_in[17],
                          (const float*)d_in[21], (const float*)d_in[25]};
    const float* b7[4] = {(const float*)d_in[14], (const float*)d_in[18],
                          (const float*)d_in[22], (const float*)d_in[26]};
    const float* w8[4] = {(const float*)d_in[15], (const float*)d_in[19],
                          (const float*)d_in[23], (const float*)d_in[27]};
    const float* b8[4] = {(const float*)d_in[16], (const float*)d_in[20],
                          (const float*)d_in[24], (const float*)d_in[28]};
    float* out = (float*)d_out;

    cudaFuncSetAttribute(k_gemm_skG, cudaFuncAttributeMaxDynamicSharedMemorySize, GT_SMEM);
    cudaFuncSetAttribute(k_gemm_sk6, cudaFuncAttributeMaxDynamicSharedMemorySize, GT_SMEM);
    cudaFuncSetAttribute(k_gemm7,    cudaFuncAttributeMaxDynamicSharedMemorySize, GT_SMEM);
    cudaFuncSetAttribute(k_gemm8,    cudaFuncAttributeMaxDynamicSharedMemorySize, GT_SMEM);

    float *c1, *u1, *c2, *p2, *c3, *c4, *c5, *p5, *p6, *p7, *p8;
    __nv_bfloat16 *bh, *bl, *b6h, *b6l;
    cudaGetSymbolAddress((void**)&c1, g_c1);
    cudaGetSymbolAddress((void**)&u1, g_u1);
    cudaGetSymbolAddress((void**)&c2, g_c2);
    cudaGetSymbolAddress((void**)&p2, g_p2);
    cudaGetSymbolAddress((void**)&c3, g_c3);
    cudaGetSymbolAddress((void**)&c4, g_c4);
    cudaGetSymbolAddress((void**)&c5, g_c5);
    cudaGetSymbolAddress((void**)&p5, g_p5);
    cudaGetSymbolAddress((void**)&p6, g_p6);
    cudaGetSymbolAddress((void**)&p7, g_p7);
    cudaGetSymbolAddress((void**)&p8, g_p8);
    cudaGetSymbolAddress((void**)&bh, gB_hi);
    cudaGetSymbolAddress((void**)&bl, gB_lo);
    cudaGetSymbolAddress((void**)&b6h, gB6_hi);
    cudaGetSymbolAddress((void**)&b6l, gB6_lo);

    // stage 1: direct conv1 -> fused LRN+pool+upsample
    k_conv1<<<blk1(96L * 118 * 158), 256>>>(x, w1, b1, c1);
    k_pooluplrn<<<blk1(96L * 59 * 79), 256>>>(c1, u1);

    // conv2: M=256 K=2400 N=4661 (Npad 4672), split-K=2
    k_prepB8<5><<<dim3(2, 4672), 256>>>(u1, bh, bl, 59, 79, 2, 59, 79, 2400);
    k_gemm_skG<<<dim3(73, 2, 2), 256, GT_SMEM>>>(w2, bh, bl, p6,
                                                 256, 2400, 4661, 2, 1193216L);
    k_redG<<<blk1(1193216L), 256>>>(p6, b2, c2, 1193216, 4661, 2, 1193216L, 1);
    k_poollrn<<<blk1(256L * 29 * 39), 256>>>(c2, p2, 256, 59, 79, 29, 39, 8.0f, 1e-4f);

    // conv3: M=384 K=2304 N=1131 (Npad 1152), split-K=4
    k_prepB8<3><<<dim3(2, 1152), 256>>>(p2, bh, bl, 29, 39, 1, 29, 39, 2304);
    k_gemm_skG<<<dim3(18, 3, 4), 256, GT_SMEM>>>(w3, bh, bl, p6,
                                                 384, 2304, 1131, 4, 434304L);
    k_redG<<<blk1(434304L), 256>>>(p6, b3, c3, 434304, 1131, 4, 434304L, 1);
    // conv4
    k_prepB8<3><<<dim3(2, 1152), 256>>>(c3, bh, bl, 29, 39, 1, 29, 39, 3456);
    k_gemm_skG<<<dim3(18, 3, 4), 256, GT_SMEM>>>(w4, bh, bl, p6,
                                                 384, 3456, 1131, 4, 434304L);
    k_redG<<<blk1(434304L), 256>>>(p6, b4, c4, 434304, 1131, 4, 434304L, 1);
    // conv5
    k_prepB8<3><<<dim3(2, 1152), 256>>>(c4, bh, bl, 29, 39, 1, 29, 39, 3456);
    k_gemm_skG<<<dim3(18, 3, 4), 256, GT_SMEM>>>(w5, bh, bl, p6,
                                                 384, 3456, 1131, 4, 434304L);
    k_redG<<<blk1(434304L), 256>>>(p6, b5, c5, 434304, 1131, 4, 434304L, 1);
    k_pool<<<blk1(384L * 14 * 19), 256>>>(c5, p5, 384, 29, 39, 14, 19);

    // conv6: split-K=4 -> fused reduce+relu -> d_out + transposed split
    k_prepB8<6><<<dim3(7, 320), 256>>>(p5, bh, bl, 14, 19, 3, 15, 20, 13824);
    k_gemm_sk6<<<dim3(5, 32, 4), 256, GT_SMEM>>>(w6, bh, bl, p6);
    k_fuse6<<<dim3(128, 10), dim3(32, 8)>>>(p6, b6, out, b6h, b6l);

    // gemm7 (4 branches, split-K=2) -> fused reduce+relu+transposed split
    Ptr4 W7 = {{w7[0], w7[1], w7[2], w7[3]}};
    k_gemm7<<<dim3(5, 32, 8), 256, GT_SMEM>>>(W7, b6h, b6l, p7);
    Bias4 B7 = {{b7[0], b7[1], b7[2], b7[3]}};
    k_fuse7<<<dim3(128, 10, 4), dim3(32, 8)>>>(p7, B7, bh, bl);

    // gemm8 (4 branches packed, split-K=4) -> fused reduce+bias+pixel-shuffle
    Ptr4 W8 = {{w8[0], w8[1], w8[2], w8[3]}};
    k_gemm8<<<dim3(5, 8, 16), 256, GT_SMEM>>>(W8, bh, bl, p8);
    Bias4 B8 = {{b8[0], b8[1], b8[2], b8[3]}};
    k_fuse8<<<blk1(518400L), 256>>>(p8, B8, out);
}

// round 12
// speedup vs baseline: 1.8692x; 1.0476x over previous
#include <cuda_runtime.h>
#include <cuda_bf16.h>
#include <cuda_fp16.h>
#include <math.h>
#include <stdint.h>

// ---------------------------------------------------------------------------
// VPGNet forward. Conv2..6 as split-bf16 3-MMA HMMA GEMMs; branch GEMMs
// (7,8) as exact-A-split fp16 2-MMA GEMMs. Split-K, cp.async B, fused
// transpose epilogues. Output: [x6|x8a|x8b|x8c|x8d] = 1,747,200 floats
// ---------------------------------------------------------------------------

// ---- scratch ----
__device__ float g_c1[96 * 118 * 158];
__device__ float g_u1[96 * 59 * 79];
__device__ float g_c2[256 * 59 * 79];
__device__ float g_p2[256 * 29 * 39];
__device__ float g_c3[384 * 29 * 39];
__device__ float g_c4[384 * 29 * 39];
__device__ float g_c5[384 * 29 * 39];
__device__ float g_p5[384 * 14 * 19];
__device__ float g_p6[4 * 4096 * 300];        // split-K partials (also conv2..5)
__device__ float g_p7[2 * 4 * 4096 * 300];
__device__ float g_p8[4 * 1728 * 300];
// bf16 split activation buffers [Npad][K] for conv2..6
__device__ __nv_bfloat16 gB_hi[11250000];
__device__ __nv_bfloat16 gB_lo[11250000];
// fp16 single activation buffers for branch GEMMs
__device__ __half g_x6f[320 * 4096];
__device__ __half g_x7f[4 * 320 * 4096];

// ============================ helpers ============================
__device__ __forceinline__ uint32_t smem_u32(const void* p) {
    uint32_t a;
    asm("{ .reg .u64 t; cvta.to.shared.u64 t, %1; cvt.u32.u64 %0, t; }" : "=r"(a) : "l"(p));
    return a;
}
__device__ __forceinline__ uint32_t swz64(uint32_t o) { return o ^ ((o >> 3) & 0x30); }

__device__ __forceinline__ void ldm4(uint32_t* r, uint32_t a) {
    asm volatile("ldmatrix.sync.aligned.m8n8.x4.shared.b16 {%0,%1,%2,%3}, [%4];"
                 : "=r"(r[0]), "=r"(r[1]), "=r"(r[2]), "=r"(r[3]) : "r"(a));
}
__device__ __forceinline__ void mma_bf16(float* c, const uint32_t* a, const uint32_t* b) {
    asm volatile("mma.sync.aligned.m16n8k16.row.col.f32.bf16.bf16.f32 "
                 "{%0,%1,%2,%3}, {%4,%5,%6,%7}, {%8,%9}, {%0,%1,%2,%3};"
                 : "+f"(c[0]), "+f"(c[1]), "+f"(c[2]), "+f"(c[3])
                 : "r"(a[0]), "r"(a[1]), "r"(a[2]), "r"(a[3]), "r"(b[0]), "r"(b[1]));
}
__device__ __forceinline__ void mma_f16(float* c, const uint32_t* a, const uint32_t* b) {
    asm volatile("mma.sync.aligned.m16n8k16.row.col.f32.f16.f16.f32 "
                 "{%0,%1,%2,%3}, {%4,%5,%6,%7}, {%8,%9}, {%0,%1,%2,%3};"
                 : "+f"(c[0]), "+f"(c[1]), "+f"(c[2]), "+f"(c[3])
                 : "r"(a[0]), "r"(a[1]), "r"(a[2]), "r"(a[3]), "r"(b[0]), "r"(b[1]));
}
__device__ __forceinline__ void sts128(uint32_t a, uint4 v) {
    asm volatile("st.shared.v4.b32 [%0], {%1,%2,%3,%4};"
                 :: "r"(a), "r"(v.x), "r"(v.y), "r"(v.z), "r"(v.w) : "memory");
}
__device__ __forceinline__ void cpasync16(uint32_t saddr, const void* gaddr) {
    asm volatile("cp.async.cg.shared.global [%0], [%1], 16;"
                 :: "r"(saddr), "l"(gaddr) : "memory");
}
__device__ __forceinline__ void cpasync_commit() {
    asm volatile("cp.async.commit_group;" ::: "memory");
}
__device__ __forceinline__ void cpasync_wait0() {
    asm volatile("cp.async.wait_group 0;" ::: "memory");
}
__device__ __forceinline__ uint32_t packbf2(float lo, float hi) {
    uint32_t d;
    asm("cvt.rn.bf16x2.f32 %0, %1, %2;" : "=r"(d) : "f"(hi), "f"(lo));
    return d;
}
__device__ __forceinline__ uint32_t pack2(__nv_bfloat16 a, __nv_bfloat16 b) {
    return (uint32_t)__bfloat16_as_ushort(a) | ((uint32_t)__bfloat16_as_ushort(b) << 16);
}
__device__ __forceinline__ uint32_t packh2(__half a, __half b) {
    return (uint32_t)__half_as_ushort(a) | ((uint32_t)__half_as_ushort(b) << 16);
}
__device__ __forceinline__ uint32_t packf16_2(float lo, float hi) {
    uint32_t d;
    asm("cvt.rn.f16x2.f32 %0, %1, %2;" : "=r"(d) : "f"(hi), "f"(lo));
    return d;
}

// ============================ elementwise layers ============================
__global__ void k_conv1(const float* __restrict__ x, const float* __restrict__ w,
                        const float* __restrict__ b, float* __restrict__ out) {
    const int HO = 118, WO = 158;
    int i = blockIdx.x * blockDim.x + threadIdx.x;
    if (i >= 96 * HO * WO) return;
    int c = i / (HO * WO), r = i % (HO * WO), oh = r / WO, ow = r % WO;
    float acc = b[c];
    const float* wp = w + c * 3 * 121;
    for (int ci = 0; ci < 3; ci++) {
        const float* xc = x + ci * 480 * 640;
        const float* wc = wp + ci * 121;
        #pragma unroll
        for (int kh = 0; kh < 11; kh++) {
            const float* xp = xc + (oh * 4 + kh) * 640 + ow * 4;
            const float* wq = wc + kh * 11;
            #pragma unroll
            for (int kw = 0; kw < 11; kw++) acc = fmaf(xp[kw], wq[kw], acc);
        }
    }
    out[i] = fmaxf(acc, 0.f);
}

__global__ void k_pooluplrn(const float* __restrict__ c1, float* __restrict__ out) {
    int i = blockIdx.x * blockDim.x + threadIdx.x;
    if (i >= 96 * 59 * 79) return;
    int c = i / (59 * 79), r = i % (59 * 79), oh = r / 79, ow = r % 79;
    int hi = (oh * 58) / 59, wi = (ow * 78) / 79;
    int jlo = c - 2 > 0 ? c - 2 : 0;
    int jhi = c + 2 < 95 ? c + 2 : 95;
    const int HW = 118 * 158;
    float m = -1e30f;
    #pragma unroll
    for (int dh = 0; dh < 3; dh++) {
        #pragma unroll
        for (int dw = 0; dw < 3; dw++) {
            const float* p = c1 + (2 * hi + dh) * 158 + 2 * wi + dw;
            float s = 0.f;
            for (int j = jlo; j <= jhi; j++) { float v = p[j * HW]; s = fmaf(v, v, s); }
            float t = 2.0f + 1e-4f * s;
            float rr = rsqrtf(t);
            m = fmaxf(m, p[c * HW] * rr * sqrtf(rr));
        }
    }
    out[i] = m;
}

__global__ void k_poollrn(const float* __restrict__ in, float* __restrict__ out,
                          int C, int Hin, int Win, int Ho, int Wo,
                          float kc, float a) {
    int i = blockIdx.x * blockDim.x + threadIdx.x;
    if (i >= C * Ho * Wo) return;
    int c = i / (Ho * Wo), r = i % (Ho * Wo), oh = r / Wo, ow = r % Wo;
    int jlo = c - 2 > 0 ? c - 2 : 0;
    int jhi = c + 2 < C - 1 ? c + 2 : C - 1;
    const int HW = Hin * Win;
    float m = -1e30f;
    #pragma unroll
    for (int dh = 0; dh < 3; dh++) {
        #pragma unroll
        for (int dw = 0; dw < 3; dw++) {
            const float* p = in + (2 * oh + dh) * Win + 2 * ow + dw;
            float s = 0.f;
            for (int j = jlo; j <= jhi; j++) { float v = p[j * HW]; s = fmaf(v, v, s); }
            float t = kc + a * s;
            float rr = rsqrtf(t);
            m = fmaxf(m, p[c * HW] * rr * sqrtf(rr));
        }
    }
    out[i] = m;
}

__global__ void k_pool(const float* __restrict__ in, float* __restrict__ out,
                       int C, int Hin, int Win, int Ho, int Wo) {
    int i = blockIdx.x * blockDim.x + threadIdx.x;
    if (i >= C * Ho * Wo) return;
    int c = i / (Ho * Wo), r = i % (Ho * Wo), oh = r / Wo, ow = r % Wo;
    const float* p = in + (c * Hin + 2 * oh) * Win + 2 * ow;
    float m = p[0];
    #pragma unroll
    for (int dh = 0; dh < 3; dh++)
        #pragma unroll
        for (int dw = 0; dw < 3; dw++) m = fmaxf(m, p[dh * Win + dw]);
    out[i] = m;
}

// ---- im2col + transpose + bf16 split, 8 k per thread ----
template <int KSZ>
__global__ void k_prepB8(const float* __restrict__ src, __nv_bfloat16* __restrict__ hi,
                         __nv_bfloat16* __restrict__ lo, int H, int W, int pad,
                         int Ho, int Wo, int K) {
    int kidx = (blockIdx.x * 256 + threadIdx.x) * 8;
    if (kidx >= K) return;
    int n = blockIdx.y;
    int oh = n / Wo, ow = n % Wo;
    bool vn = n < Ho * Wo;
    int kw = kidx % KSZ;
    int t = kidx / KSZ;
    int kh = t % KSZ, cc = t / KSZ;
    float v[8];
    #pragma unroll
    for (int j = 0; j < 8; j++) {
        float val = 0.f;
        if (vn) {
            int ih = oh - pad + kh, iw = ow - pad + kw;
            if (ih >= 0 && ih < H && iw >= 0 && iw < W)
                val = src[((size_t)cc * H + ih) * W + iw];
        }
        v[j] = val;
        if (++kw == KSZ) { kw = 0; if (++kh == KSZ) { kh = 0; ++cc; } }
    }
    __nv_bfloat16 h[8];
    float l[8];
    #pragma unroll
    for (int e = 0; e < 8; e++) {
        h[e] = __float2bfloat16(v[e]);
        l[e] = v[e] - __bfloat162float(h[e]);
    }
    uint4 ph = make_uint4(pack2(h[0], h[1]), pack2(h[2], h[3]),
                          pack2(h[4], h[5]), pack2(h[6], h[7]));
    uint4 pl = make_uint4(packbf2(l[0], l[1]), packbf2(l[2], l[3]),
                          packbf2(l[4], l[5]), packbf2(l[6], l[7]));
    size_t o = (size_t)n * K + kidx;
    *reinterpret_cast<uint4*>(hi + o) = ph;
    *reinterpret_cast<uint4*>(lo + o) = pl;
}

// ---- fused reduce(4)+bias+relu -> d_out(x6) AND transposed fp16 single ----
__global__ void k_fuse6(const float* __restrict__ p, const float* __restrict__ bias,
                        float* __restrict__ out, __half* __restrict__ xf) {
    __shared__ float t[32][33];
    int rb = blockIdx.x * 32, nb = blockIdx.y * 32;
    int tx = threadIdx.x, ty = threadIdx.y;
    #pragma unroll
    for (int j = 0; j < 4; j++) {
        int row = rb + ty + j * 8;
        int n = nb + tx;
        float v = 0.f;
        if (n < 300) {
            size_t o = (size_t)row * 300 + n;
            v = fmaxf(p[o] + p[o + 1228800] + p[o + 2 * 1228800] + p[o + 3 * 1228800]
                      + bias[row], 0.f);
            out[o] = v;
        }
        t[ty + j * 8][tx] = v;
    }
    __syncthreads();
    #pragma unroll
    for (int j = 0; j < 4; j++) {
        int n = nb + ty + j * 8;
        int k = rb + tx;
        xf[(size_t)n * 4096 + k] = __float2half_rn(t[tx][ty + j * 8]);
    }
}

// ---- fused reduce(2)+bias+relu -> transposed fp16 single for the 4 x7 ----
struct Bias4 { const float* b[4]; };
__global__ void k_fuse7(const float* __restrict__ P, Bias4 bias,
                        __half* __restrict__ xf) {
    __shared__ float t[32][33];
    int br = blockIdx.z;
    const float* p = P + (size_t)br * 1228800;
    int rb = blockIdx.x * 32, nb = blockIdx.y * 32;
    int tx = threadIdx.x, ty = threadIdx.y;
    #pragma unroll
    for (int j = 0; j < 4; j++) {
        int row = rb + ty + j * 8;
        int n = nb + tx;
        float v = 0.f;
        if (n < 300) {
            size_t o = (size_t)row * 300 + n;
            v = fmaxf(p[o] + p[o + 4 * 1228800] + bias.b[br][row], 0.f);
        }
        t[ty + j * 8][tx] = v;
    }
    __syncthreads();
    #pragma unroll
    for (int j = 0; j < 4; j++) {
        int n = nb + ty + j * 8;
        int k = rb + tx;
        xf[(size_t)br * 1310720 + (size_t)n * 4096 + k] =
            __float2half_rn(t[tx][ty + j * 8]);
    }
}

// ---- fused reduce(4)+bias + pixel-shuffle for all branches ----
__global__ void k_fuse8(const float* __restrict__ p, Bias4 bias, float* __restrict__ out) {
    int i = blockIdx.x * blockDim.x + threadIdx.x;
    if (i >= 518400) return;
    int br, start, r;
    long oofs;
    if (i < 76800)       { br = 0; start = 0;      r = 8; oofs = 1228800L; }
    else if (i < 115200) { br = 1; start = 76800;  r = 8; oofs = 1305600L; }
    else if (i < 422400) { br = 2; start = 115200; r = 4; oofs = 1344000L; }
    else                 { br = 3; start = 422400; r = 8; oofs = 1651200L; }
    int li = i - start;
    int OW = 20 * r;
    int OHW = 300 * r * r;
    int oc = li / OHW, rem = li % OHW;
    int oh = rem / OW, ow = rem % OW;
    int ic = oc * r * r + (oh % r) * r + (ow % r);
    int src = start + ic * 300 + (oh / r) * 20 + (ow / r);
    float v = p[src] + p[src + 518400] + p[src + 2 * 518400] + p[src + 3 * 518400];
    out[oofs + li] = v + bias.b[br][ic];
}

// ---- generic split-K reduce (conv2..5) ----
__global__ void k_redG(const float* __restrict__ p, const float* __restrict__ bias,
                       float* __restrict__ out, int total, int Ncols, int S,
                       long stride, int relu) {
    int i = blockIdx.x * blockDim.x + threadIdx.x;
    if (i >= total) return;
    float v = 0.f;
    for (int s = 0; s < S; s++) v += p[(size_t)s * stride + i];
    v += bias[i / Ncols];
    out[i] = relu ? fmaxf(v, 0.f) : v;
}

// ============================ HMMA GEMM cores ============================
#define STG 24576
#define GT_SMEM (2 * STG + 1024)

// ---- bf16 2-term split, 3 MMAs (conv2..6) ----
__device__ __forceinline__ void gemm_core(
    char* dsm, const float* __restrict__ A, const __nv_bfloat16* __restrict__ Bh,
    const __nv_bfloat16* __restrict__ Bl, float* __restrict__ C,
    int M, int K, int Ncols, int m0, int n0, int c0, int cEnd) {
    const int tid = threadIdx.x;
    const int lane = tid & 31;
    const int wid = tid >> 5;
    const int wm = wid & 3, wn = wid >> 2;

    const uint32_t base = (smem_u32(dsm) + 1023u) & ~1023u;
    const int bR = tid >> 2, bF = tid & 3;
    const uint32_t bOff = swz64((uint32_t)(bR * 64 + bF * 16));
    const __nv_bfloat16* bhSrc = Bh + (size_t)(n0 + bR) * K + bF * 8;
    const __nv_bfloat16* blSrc = Bl + (size_t)(n0 + bR) * K + bF * 8;

    uint32_t pA[2], pB[2];
    {
        uint32_t r = (uint32_t)(wm * 32 + (lane & 15));
        uint32_t kc = (uint32_t)((lane >> 4) * 16);
        #pragma unroll
        for (int mt = 0; mt < 2; mt++) {
            uint32_t o = (r + mt * 16) * 64 + kc;
            pA[mt] = o ^ ((o >> 3) & 0x30);
        }
        uint32_t rn = (uint32_t)(wn * 32 + (lane & 7) + ((lane >> 4) << 3));
        uint32_t kcb = (uint32_t)(((lane >> 3) & 1) * 16);
        #pragma unroll
        for (int nt = 0; nt < 2; nt++) {
            uint32_t o = (rn + nt * 16) * 64 + kcb;
            pB[nt] = o ^ ((o >> 3) & 0x30);
        }
    }

    float acc[2][4][4] = {};
    float4 aP[2][2];
    {
        const int k0 = c0 << 5;
        #pragma unroll
        for (int it = 0; it < 2; it++) {
            int idx = tid + it * 256;
            int row = idx >> 2, f8 = idx & 3;
            int gr = m0 + row, k = k0 + f8 * 8;
            if (gr < M) {
                aP[it][0] = *reinterpret_cast<const float4*>(A + (size_t)gr * K + k);
                aP[it][1] = *reinterpret_cast<const float4*>(A + (size_t)gr * K + k + 4);
            } else {
                aP[it][0] = aP[it][1] = make_float4(0.f, 0.f, 0.f, 0.f);
            }
        }
        const uint32_t stg0 = base + (uint32_t)(c0 & 1) * STG;
        cpasync16(stg0 + 16384u + bOff, bhSrc + k0);
        cpasync16(stg0 + 20480u + bOff, blSrc + k0);
        cpasync_commit();
    }

    for (int c = c0; c < cEnd; c++) {
        const uint32_t stg = base + (uint32_t)(c & 1) * STG;
        #pragma unroll
        for (int it = 0; it < 2; it++) {
            int idx = tid + it * 256;
            int row = idx >> 2, f8 = idx & 3;
            float s[8] = {aP[it][0].x, aP[it][0].y, aP[it][0].z, aP[it][0].w,
                          aP[it][1].x, aP[it][1].y, aP[it][1].z, aP[it][1].w};
            __nv_bfloat16 h[8];
            float l[8];
            #pragma unroll
            for (int e = 0; e < 8; e++) {
                h[e] = __float2bfloat16(s[e]);
                l[e] = s[e] - __bfloat162float(h[e]);
            }
            uint4 hv = make_uint4(pack2(h[0], h[1]), pack2(h[2], h[3]),
                                  pack2(h[4], h[5]), pack2(h[6], h[7]));
            uint4 lv = make_uint4(packbf2(l[0], l[1]), packbf2(l[2], l[3]),
                                  packbf2(l[4], l[5]), packbf2(l[6], l[7]));
            uint32_t off = swz64((uint32_t)(row * 64 + f8 * 16));
            sts128(stg + off, hv);
            sts128(stg + 8192u + off, lv);
        }
        cpasync_wait0();
        __syncthreads();
        if (c + 1 < cEnd) {
            const int k0 = (c + 1) << 5;
            #pragma unroll
            for (int it = 0; it < 2; it++) {
                int idx = tid + it * 256;
                int row = idx >> 2, f8 = idx & 3;
                int gr = m0 + row, k = k0 + f8 * 8;
                if (gr < M) {
                    aP[it][0] = *reinterpret_cast<const float4*>(A + (size_t)gr * K + k);
                    aP[it][1] = *reinterpret_cast<const float4*>(A + (size_t)gr * K + k + 4);
                } else {
                    aP[it][0] = aP[it][1] = make_float4(0.f, 0.f, 0.f, 0.f);
                }
            }
            const uint32_t stgN = base + (uint32_t)((c + 1) & 1) * STG;
            cpasync16(stgN + 16384u + bOff, bhSrc + k0);
            cpasync16(stgN + 20480u + bOff, blSrc + k0);
            cpasync_commit();
        }
        #pragma unroll
        for (int ks = 0; ks < 2; ks++) {
            const uint32_t kb = (uint32_t)(ks << 5);
            uint32_t ah[2][4], al[2][4], bh_[2][4], bl_[2][4];
            ldm4(ah[0], stg + (pA[0] ^ kb));
            ldm4(ah[1], stg + (pA[1] ^ kb));
            ldm4(al[0], stg + 8192u + (pA[0] ^ kb));
            ldm4(al[1], stg + 8192u + (pA[1] ^ kb));
            ldm4(bh_[0], stg + 16384u + (pB[0] ^ kb));
            ldm4(bh_[1], stg + 16384u + (pB[1] ^ kb));
            ldm4(bl_[0], stg + 20480u + (pB[0] ^ kb));
            ldm4(bl_[1], stg + 20480u + (pB[1] ^ kb));
            #pragma unroll
            for (int mt = 0; mt < 2; mt++)
                #pragma unroll
                for (int nt = 0; nt < 4; nt++) {
                    const uint32_t* bh2 = &bh_[nt >> 1][(nt & 1) * 2];
                    const uint32_t* bl2 = &bl_[nt >> 1][(nt & 1) * 2];
                    mma_bf16(acc[mt][nt], ah[mt], bh2);
                    mma_bf16(acc[mt][nt], ah[mt], bl2);
                    mma_bf16(acc[mt][nt], al[mt], bh2);
                }
        }
    }

    #pragma unroll
    for (int mt = 0; mt < 2; mt++) {
        int r0 = m0 + wm * 32 + mt * 16 + (lane >> 2);
        #pragma unroll
        for (int half = 0; half < 2; half++) {
            int row = r0 + half * 8;
            if (row >= M) continue;
            #pragma unroll
            for (int nt = 0; nt < 4; nt++) {
                int col = n0 + wn * 32 + nt * 8 + (lane & 3) * 2;
                if (col < Ncols) C[(size_t)row * Ncols + col] = acc[mt][nt][half * 2];
                if (col + 1 < Ncols)
                    C[(size_t)row * Ncols + col + 1] = acc[mt][nt][half * 2 + 1];
            }
        }
    }
}

// ---- fp16: A split exactly (x64), B single fp16, 2 MMAs (gemm7/8) ----
__device__ __forceinline__ void gemm_core_f16(
    char* dsm, const float* __restrict__ A, const __half* __restrict__ Bf,
    float* __restrict__ C, int M, int K, int Ncols, int m0, int n0,
    int c0, int cEnd) {
    const int tid = threadIdx.x;
    const int lane = tid & 31;
    const int wid = tid >> 5;
    const int wm = wid & 3, wn = wid >> 2;

    const uint32_t base = (smem_u32(dsm) + 1023u) & ~1023u;
    const int bR = tid >> 2, bF = tid & 3;
    const uint32_t bOff = swz64((uint32_t)(bR * 64 + bF * 16));
    const __half* bSrc = Bf + (size_t)(n0 + bR) * K + bF * 8;

    uint32_t pA[2], pB[2];
    {
        uint32_t r = (uint32_t)(wm * 32 + (lane & 15));
        uint32_t kc = (uint32_t)((lane >> 4) * 16);
        #pragma unroll
        for (int mt = 0; mt < 2; mt++) {
            uint32_t o = (r + mt * 16) * 64 + kc;
            pA[mt] = o ^ ((o >> 3) & 0x30);
        }
        uint32_t rn = (uint32_t)(wn * 32 + (lane & 7) + ((lane >> 4) << 3));
        uint32_t kcb = (uint32_t)(((lane >> 3) & 1) * 16);
        #pragma unroll
        for (int nt = 0; nt < 2; nt++) {
            uint32_t o = (rn + nt * 16) * 64 + kcb;
            pB[nt] = o ^ ((o >> 3) & 0x30);
        }
    }

    float acc[2][4][4] = {};
    float4 aP[2][2];
    {
        const int k0 = c0 << 5;
        #pragma unroll
        for (int it = 0; it < 2; it++) {
            int idx = tid + it * 256;
            int row = idx >> 2, f8 = idx & 3;
            int gr = m0 + row, k = k0 + f8 * 8;
            if (gr < M) {
                aP[it][0] = *reinterpret_cast<const float4*>(A + (size_t)gr * K + k);
                aP[it][1] = *reinterpret_cast<const float4*>(A + (size_t)gr * K + k + 4);
            } else {
                aP[it][0] = aP[it][1] = make_float4(0.f, 0.f, 0.f, 0.f);
            }
        }
        const uint32_t stg0 = base + (uint32_t)(c0 & 1) * STG;
        cpasync16(stg0 + 16384u + bOff, bSrc + k0);
        cpasync_commit();
    }

    for (int c = c0; c < cEnd; c++) {
        const uint32_t stg = base + (uint32_t)(c & 1) * STG;
        // A: scaled exact fp16 split (a*64 = ah + al)
        #pragma unroll
        for (int it = 0; it < 2; it++) {
            int idx = tid + it * 256;
            int row = idx >> 2, f8 = idx & 3;
            float s[8] = {aP[it][0].x, aP[it][0].y, aP[it][0].z, aP[it][0].w,
                          aP[it][1].x, aP[it][1].y, aP[it][1].z, aP[it][1].w};
            __half h[8];
            float l[8];
            #pragma unroll
            for (int e = 0; e < 8; e++) {
                float as = s[e] * 64.f;
                h[e] = __float2half_rn(as);
                l[e] = as - __half2float(h[e]);
            }
            uint4 hv = make_uint4(packh2(h[0], h[1]), packh2(h[2], h[3]),
                                  packh2(h[4], h[5]), packh2(h[6], h[7]));
            uint4 lv = make_uint4(packf16_2(l[0], l[1]), packf16_2(l[2], l[3]),
                                  packf16_2(l[4], l[5]), packf16_2(l[6], l[7]));
            uint32_t off = swz64((uint32_t)(row * 64 + f8 * 16));
            sts128(stg + off, hv);
            sts128(stg + 8192u + off, lv);
        }
        cpasync_wait0();
        __syncthreads();
        if (c + 1 < cEnd) {
            const int k0 = (c + 1) << 5;
            #pragma unroll
            for (int it = 0; it < 2; it++) {
                int idx = tid + it * 256;
                int row = idx >> 2, f8 = idx & 3;
                int gr = m0 + row, k = k0 + f8 * 8;
                if (gr < M) {
                    aP[it][0] = *reinterpret_cast<const float4*>(A + (size_t)gr * K + k);
                    aP[it][1] = *reinterpret_cast<const float4*>(A + (size_t)gr * K + k + 4);
                } else {
                    aP[it][0] = aP[it][1] = make_float4(0.f, 0.f, 0.f, 0.f);
                }
            }
            const uint32_t stgN = base + (uint32_t)((c + 1) & 1) * STG;
            cpasync16(stgN + 16384u + bOff, bSrc + k0);
            cpasync_commit();
        }
        #pragma unroll
        for (int ks = 0; ks < 2; ks++) {
            const uint32_t kb = (uint32_t)(ks << 5);
            uint32_t ah[2][4], al[2][4], bf_[2][4];
            ldm4(ah[0], stg + (pA[0] ^ kb));
            ldm4(ah[1], stg + (pA[1] ^ kb));
            ldm4(al[0], stg + 8192u + (pA[0] ^ kb));
            ldm4(al[1], stg + 8192u + (pA[1] ^ kb));
            ldm4(bf_[0], stg + 16384u + (pB[0] ^ kb));
            ldm4(bf_[1], stg + 16384u + (pB[1] ^ kb));
            #pragma unroll
            for (int mt = 0; mt < 2; mt++)
                #pragma unroll
                for (int nt = 0; nt < 4; nt++) {
                    const uint32_t* b2 = &bf_[nt >> 1][(nt & 1) * 2];
                    mma_f16(acc[mt][nt], ah[mt], b2);
                    mma_f16(acc[mt][nt], al[mt], b2);
                }
        }
    }

    const float INV = 1.f / 64.f;
    #pragma unroll
    for (int mt = 0; mt < 2; mt++) {
        int r0 = m0 + wm * 32 + mt * 16 + (lane >> 2);
        #pragma unroll
        for (int half = 0; half < 2; half++) {
            int row = r0 + half * 8;
            if (row >= M) continue;
            #pragma unroll
            for (int nt = 0; nt < 4; nt++) {
                int col = n0 + wn * 32 + nt * 8 + (lane & 3) * 2;
                if (col < Ncols)
                    C[(size_t)row * Ncols + col] = acc[mt][nt][half * 2] * INV;
                if (col + 1 < Ncols)
                    C[(size_t)row * Ncols + col + 1] = acc[mt][nt][half * 2 + 1] * INV;
            }
        }
    }
}

__global__ __launch_bounds__(256, 2) void k_gemm_skG(
    const float* __restrict__ A, const __nv_bfloat16* __restrict__ Bh,
    const __nv_bfloat16* __restrict__ Bl, float* __restrict__ P,
    int M, int K, int Ncols, int S, long stride) {
    extern __shared__ char dsm[];
    const int z = blockIdx.z;
    const int nc = K >> 5;
    const int per = nc / S, rem = nc % S;
    const int c0 = z * per + (z < rem ? z : rem);
    const int cEnd = c0 + per + (z < rem ? 1 : 0);
    gemm_core(dsm, A, Bh, Bl, P + (size_t)z * stride,
              M, K, Ncols, blockIdx.y * 128, blockIdx.x * 64, c0, cEnd);
}

__global__ __launch_bounds__(256, 2) void k_gemm_sk6(
    const float* __restrict__ A, const __nv_bfloat16* __restrict__ Bh,
    const __nv_bfloat16* __restrict__ Bl, float* __restrict__ P) {
    extern __shared__ char dsm[];
    const int z = blockIdx.z;
    const int per = (13824 >> 5) >> 2;
    gemm_core(dsm, A, Bh, Bl, P + (size_t)z * 1228800,
              4096, 13824, 300, blockIdx.y * 128, blockIdx.x * 64,
              z * per, (z + 1) * per);
}

struct Ptr4 { const float* p[4]; };
__global__ __launch_bounds__(256, 2) void k_gemm7f(
    Ptr4 W, const __half* __restrict__ Bf, float* __restrict__ P) {
    extern __shared__ char dsm[];
    const int br = blockIdx.z >> 1, sl = blockIdx.z & 1;
    const int per = 128 >> 1;
    float* out = P + (size_t)sl * 4 * 1228800 + (size_t)br * 1228800;
    gemm_core_f16(dsm, W.p[br], Bf, out, 4096, 4096, 300,
                  blockIdx.y * 128, blockIdx.x * 64, sl * per, (sl + 1) * per);
}

__global__ __launch_bounds__(256, 2) void k_gemm8f(
    Ptr4 W, const __half* __restrict__ Bf, float* __restrict__ P) {
    extern __shared__ char dsm[];
    const int br = blockIdx.z >> 2, sl = blockIdx.z & 3;
    const int C8s[4] = {256, 128, 1024, 320};
    const int roff[4] = {0, 256, 384, 1408};
    const int M = C8s[br];
    const int m0 = blockIdx.y * 128;
    if (m0 >= M) return;
    const int per = 128 >> 2;
    float* out = P + (size_t)sl * 518400 + (size_t)roff[br] * 300;
    gemm_core_f16(dsm, W.p[br], Bf + (size_t)br * 1310720, out, M, 4096, 300,
                  m0, blockIdx.x * 64, sl * per, (sl + 1) * per);
}

static inline dim3 blk1(long n) { return dim3((unsigned)((n + 255) / 256)); }

extern "C" void kernel_launch(void* const* d_in, const int* in_sizes, int n_in,
                              void* d_out, int out_size) {
    const float* x  = (const float*)d_in[0];
    const float* w1 = (const float*)d_in[1];  const float* b1 = (const float*)d_in[2];
    const float* w2 = (const float*)d_in[3];  const float* b2 = (const float*)d_in[4];
    const float* w3 = (const float*)d_in[5];  const float* b3 = (const float*)d_in[6];
    const float* w4 = (const float*)d_in[7];  const float* b4 = (const float*)d_in[8];
    const float* w5 = (const float*)d_in[9];  const float* b5 = (const float*)d_in[10];
    const float* w6 = (const float*)d_in[11]; const float* b6 = (const float*)d_in[12];
    const float* w7[4] = {(const float*)d_in[13], (const float*)d_in[17],
                          (const float*)d_in[21], (const float*)d_in[25]};
    const float* b7[4] = {(const float*)d_in[14], (const float*)d_in[18],
                          (const float*)d_in[22], (const float*)d_in[26]};
    const float* w8[4] = {(const float*)d_in[15], (const float*)d_in[19],
                          (const float*)d_in[23], (const float*)d_in[27]};
    const float* b8[4] = {(const float*)d_in[16], (const float*)d_in[20],
                          (const float*)d_in[24], (const float*)d_in[28]};
    float* out = (float*)d_out;

    cudaFuncSetAttribute(k_gemm_skG, cudaFuncAttributeMaxDynamicSharedMemorySize, GT_SMEM);
    cudaFuncSetAttribute(k_gemm_sk6, cudaFuncAttributeMaxDynamicSharedMemorySize, GT_SMEM);
    cudaFuncSetAttribute(k_gemm7f,   cudaFuncAttributeMaxDynamicSharedMemorySize, GT_SMEM);
    cudaFuncSetAttribute(k_gemm8f,   cudaFuncAttributeMaxDynamicSharedMemorySize, GT_SMEM);

    float *c1, *u1, *c2, *p2, *c3, *c4, *c5, *p5, *p6, *p7, *p8;
    __nv_bfloat16 *bh, *bl;
    __half *x6f, *x7f;
    cudaGetSymbolAddress((void**)&c1, g_c1);
    cudaGetSymbolAddress((void**)&u1, g_u1);
    cudaGetSymbolAddress((void**)&c2, g_c2);
    cudaGetSymbolAddress((void**)&p2, g_p2);
    cudaGetSymbolAddress((void**)&c3, g_c3);
    cudaGetSymbolAddress((void**)&c4, g_c4);
    cudaGetSymbolAddress((void**)&c5, g_c5);
    cudaGetSymbolAddress((void**)&p5, g_p5);
    cudaGetSymbolAddress((void**)&p6, g_p6);
    cudaGetSymbolAddress((void**)&p7, g_p7);
    cudaGetSymbolAddress((void**)&p8, g_p8);
    cudaGetSymbolAddress((void**)&bh, gB_hi);
    cudaGetSymbolAddress((void**)&bl, gB_lo);
    cudaGetSymbolAddress((void**)&x6f, g_x6f);
    cudaGetSymbolAddress((void**)&x7f, g_x7f);

    // stage 1: direct conv1 -> fused LRN+pool+upsample
    k_conv1<<<blk1(96L * 118 * 158), 256>>>(x, w1, b1, c1);
    k_pooluplrn<<<blk1(96L * 59 * 79), 256>>>(c1, u1);

    // conv2: M=256 K=2400 N=4661 (Npad 4672), split-K=2
    k_prepB8<5><<<dim3(2, 4672), 256>>>(u1, bh, bl, 59, 79, 2, 59, 79, 2400);
    k_gemm_skG<<<dim3(73, 2, 2), 256, GT_SMEM>>>(w2, bh, bl, p6,
                                                 256, 2400, 4661, 2, 1193216L);
    k_redG<<<blk1(1193216L), 256>>>(p6, b2, c2, 1193216, 4661, 2, 1193216L, 1);
    k_poollrn<<<blk1(256L * 29 * 39), 256>>>(c2, p2, 256, 59, 79, 29, 39, 8.0f, 1e-4f);

    // conv3: M=384 K=2304 N=1131 (Npad 1152), split-K=4
    k_prepB8<3><<<dim3(2, 1152), 256>>>(p2, bh, bl, 29, 39, 1, 29, 39, 2304);
    k_gemm_skG<<<dim3(18, 3, 4), 256, GT_SMEM>>>(w3, bh, bl, p6,
                                                 384, 2304, 1131, 4, 434304L);
    k_redG<<<blk1(434304L), 256>>>(p6, b3, c3, 434304, 1131, 4, 434304L, 1);
    // conv4
    k_prepB8<3><<<dim3(2, 1152), 256>>>(c3, bh, bl, 29, 39, 1, 29, 39, 3456);
    k_gemm_skG<<<dim3(18, 3, 4), 256, GT_SMEM>>>(w4, bh, bl, p6,
                                                 384, 3456, 1131, 4, 434304L);
    k_redG<<<blk1(434304L), 256>>>(p6, b4, c4, 434304, 1131, 4, 434304L, 1);
    // conv5
    k_prepB8<3><<<dim3(2, 1152), 256>>>(c4, bh, bl, 29, 39, 1, 29, 39, 3456);
    k_gemm_skG<<<dim3(18, 3, 4), 256, GT_SMEM>>>(w5, bh, bl, p6,
                                                 384, 3456, 1131, 4, 434304L);
    k_redG<<<blk1(434304L), 256>>>(p6, b5, c5, 434304, 1131, 4, 434304L, 1);
    k_pool<<<blk1(384L * 14 * 19), 256>>>(c5, p5, 384, 29, 39, 14, 19);

    // conv6 (bf16 3-MMA): split-K=4 -> fused reduce+relu -> d_out + x6 fp16
    k_prepB8<6><<<dim3(7, 320), 256>>>(p5, bh, bl, 14, 19, 3, 15, 20, 13824);
    k_gemm_sk6<<<dim3(5, 32, 4), 256, GT_SMEM>>>(w6, bh, bl, p6);
    k_fuse6<<<dim3(128, 10), dim3(32, 8)>>>(p6, b6, out, x6f);

    // gemm7 (fp16 2-MMA, 4 branches, split-K=2) -> fused -> x7 fp16
    Ptr4 W7 = {{w7[0], w7[1], w7[2], w7[3]}};
    k_gemm7f<<<dim3(5, 32, 8), 256, GT_SMEM>>>(W7, x6f, p7);
    Bias4 B7 = {{b7[0], b7[1], b7[2], b7[3]}};
    k_fuse7<<<dim3(128, 10, 4), dim3(32, 8)>>>(p7, B7, x7f);

    // gemm8 (fp16 2-MMA, 4 branches packed, split-K=4) -> reduce+bias+tile
    Ptr4 W8 = {{w8[0], w8[1], w8[2], w8[3]}};
    k_gemm8f<<<dim3(5, 8, 16), 256, GT_SMEM>>>(W8, x7f, p8);
    Bias4 B8 = {{b8[0], b8[1], b8[2], b8[3]}};
    k_fuse8<<<blk1(518400L), 256>>>(p8, B8, out);
}

// round 13
// speedup vs baseline: 1.8778x; 1.0046x over previous
#include <cuda_runtime.h>
#include <cuda_bf16.h>
#include <cuda_fp16.h>
#include <math.h>
#include <stdint.h>

// ---------------------------------------------------------------------------
// VPGNet forward. conv2..5: split-bf16 3-MMA GEMMs. conv6 + branch GEMMs:
// exact-A-split fp16 2-MMA GEMMs. Split-K, cp.async B, fused epilogues.
// Output: [x6|x8a|x8b|x8c|x8d] = 1,747,200 floats
// ---------------------------------------------------------------------------

// ---- scratch ----
__device__ float g_c1[96 * 118 * 158];
__device__ float g_u1[96 * 59 * 79];
__device__ float g_p2[256 * 29 * 39];
__device__ float g_c3[384 * 29 * 39];
__device__ float g_c4[384 * 29 * 39];
__device__ float g_c5[384 * 29 * 39];
__device__ float g_p5[384 * 14 * 19];
__device__ float g_p6[4 * 4096 * 300];        // split-K partials (also conv2..5)
__device__ float g_p7[2 * 4 * 4096 * 300];
__device__ float g_p8[4 * 1728 * 300];
// bf16 split activation buffers [Npad][K] for conv2..5
__device__ __nv_bfloat16 gB_hi[11250000];
__device__ __nv_bfloat16 gB_lo[11250000];
// fp16 single activation buffers
__device__ __half g_B6f[320 * 13824];         // conv6 im2col
__device__ __half g_x6f[320 * 4096];
__device__ __half g_x7f[4 * 320 * 4096];

// ============================ helpers ============================
__device__ __forceinline__ uint32_t smem_u32(const void* p) {
    uint32_t a;
    asm("{ .reg .u64 t; cvta.to.shared.u64 t, %1; cvt.u32.u64 %0, t; }" : "=r"(a) : "l"(p));
    return a;
}
__device__ __forceinline__ uint32_t swz64(uint32_t o) { return o ^ ((o >> 3) & 0x30); }

__device__ __forceinline__ void ldm4(uint32_t* r, uint32_t a) {
    asm volatile("ldmatrix.sync.aligned.m8n8.x4.shared.b16 {%0,%1,%2,%3}, [%4];"
                 : "=r"(r[0]), "=r"(r[1]), "=r"(r[2]), "=r"(r[3]) : "r"(a));
}
__device__ __forceinline__ void mma_bf16(float* c, const uint32_t* a, const uint32_t* b) {
    asm volatile("mma.sync.aligned.m16n8k16.row.col.f32.bf16.bf16.f32 "
                 "{%0,%1,%2,%3}, {%4,%5,%6,%7}, {%8,%9}, {%0,%1,%2,%3};"
                 : "+f"(c[0]), "+f"(c[1]), "+f"(c[2]), "+f"(c[3])
                 : "r"(a[0]), "r"(a[1]), "r"(a[2]), "r"(a[3]), "r"(b[0]), "r"(b[1]));
}
__device__ __forceinline__ void mma_f16(float* c, const uint32_t* a, const uint32_t* b) {
    asm volatile("mma.sync.aligned.m16n8k16.row.col.f32.f16.f16.f32 "
                 "{%0,%1,%2,%3}, {%4,%5,%6,%7}, {%8,%9}, {%0,%1,%2,%3};"
                 : "+f"(c[0]), "+f"(c[1]), "+f"(c[2]), "+f"(c[3])
                 : "r"(a[0]), "r"(a[1]), "r"(a[2]), "r"(a[3]), "r"(b[0]), "r"(b[1]));
}
__device__ __forceinline__ void sts128(uint32_t a, uint4 v) {
    asm volatile("st.shared.v4.b32 [%0], {%1,%2,%3,%4};"
                 :: "r"(a), "r"(v.x), "r"(v.y), "r"(v.z), "r"(v.w) : "memory");
}
__device__ __forceinline__ void cpasync16(uint32_t saddr, const void* gaddr) {
    asm volatile("cp.async.cg.shared.global [%0], [%1], 16;"
                 :: "r"(saddr), "l"(gaddr) : "memory");
}
__device__ __forceinline__ void cpasync_commit() {
    asm volatile("cp.async.commit_group;" ::: "memory");
}
__device__ __forceinline__ void cpasync_wait0() {
    asm volatile("cp.async.wait_group 0;" ::: "memory");
}
__device__ __forceinline__ uint32_t packbf2(float lo, float hi) {
    uint32_t d;
    asm("cvt.rn.bf16x2.f32 %0, %1, %2;" : "=r"(d) : "f"(hi), "f"(lo));
    return d;
}
__device__ __forceinline__ uint32_t pack2(__nv_bfloat16 a, __nv_bfloat16 b) {
    return (uint32_t)__bfloat16_as_ushort(a) | ((uint32_t)__bfloat16_as_ushort(b) << 16);
}
__device__ __forceinline__ uint32_t packh2(__half a, __half b) {
    return (uint32_t)__half_as_ushort(a) | ((uint32_t)__half_as_ushort(b) << 16);
}
__device__ __forceinline__ uint32_t packf16_2(float lo, float hi) {
    uint32_t d;
    asm("cvt.rn.f16x2.f32 %0, %1, %2;" : "=r"(d) : "f"(hi), "f"(lo));
    return d;
}

// ============================ elementwise layers ============================
__global__ void k_conv1(const float* __restrict__ x, const float* __restrict__ w,
                        const float* __restrict__ b, float* __restrict__ out) {
    const int HO = 118, WO = 158;
    int i = blockIdx.x * blockDim.x + threadIdx.x;
    if (i >= 96 * HO * WO) return;
    int c = i / (HO * WO), r = i % (HO * WO), oh = r / WO, ow = r % WO;
    float acc = b[c];
    const float* wp = w + c * 3 * 121;
    for (int ci = 0; ci < 3; ci++) {
        const float* xc = x + ci * 480 * 640;
        const float* wc = wp + ci * 121;
        #pragma unroll
        for (int kh = 0; kh < 11; kh++) {
            const float* xp = xc + (oh * 4 + kh) * 640 + ow * 4;
            const float* wq = wc + kh * 11;
            #pragma unroll
            for (int kw = 0; kw < 11; kw++) acc = fmaf(xp[kw], wq[kw], acc);
        }
    }
    out[i] = fmaxf(acc, 0.f);
}

__global__ void k_pooluplrn(const float* __restrict__ c1, float* __restrict__ out) {
    int i = blockIdx.x * blockDim.x + threadIdx.x;
    if (i >= 96 * 59 * 79) return;
    int c = i / (59 * 79), r = i % (59 * 79), oh = r / 79, ow = r % 79;
    int hi = (oh * 58) / 59, wi = (ow * 78) / 79;
    int jlo = c - 2 > 0 ? c - 2 : 0;
    int jhi = c + 2 < 95 ? c + 2 : 95;
    const int HW = 118 * 158;
    float m = -1e30f;
    #pragma unroll
    for (int dh = 0; dh < 3; dh++) {
        #pragma unroll
        for (int dw = 0; dw < 3; dw++) {
            const float* p = c1 + (2 * hi + dh) * 158 + 2 * wi + dw;
            float s = 0.f;
            for (int j = jlo; j <= jhi; j++) { float v = p[j * HW]; s = fmaf(v, v, s); }
            float t = 2.0f + 1e-4f * s;
            float rr = rsqrtf(t);
            m = fmaxf(m, p[c * HW] * rr * sqrtf(rr));
        }
    }
    out[i] = m;
}

// ---- fused conv2 split-K reduce + bias + relu + LRN(k=8) + maxpool ----
__global__ void k_redpool2(const float* __restrict__ p, const float* __restrict__ bias,
                           float* __restrict__ out) {
    int i = blockIdx.x * blockDim.x + threadIdx.x;
    if (i >= 256 * 29 * 39) return;
    int c = i / (29 * 39), r = i % (29 * 39), oh = r / 39, ow = r % 39;
    int jlo = c - 2 > 0 ? c - 2 : 0;
    int jhi = c + 2 < 255 ? c + 2 : 255;
    float m = -1e30f;
    #pragma unroll
    for (int dh = 0; dh < 3; dh++) {
        #pragma unroll
        for (int dw = 0; dw < 3; dw++) {
            int pos = (2 * oh + dh) * 79 + 2 * ow + dw;
            float s = 0.f, center = 0.f;
            for (int j = jlo; j <= jhi; j++) {
                size_t o = (size_t)j * 4661 + pos;
                float v = fmaxf(p[o] + p[o + 1193216] + bias[j], 0.f);
                s = fmaf(v, v, s);
                if (j == c) center = v;
            }
            float t = 8.0f + 1e-4f * s;
            float rr = rsqrtf(t);
            m = fmaxf(m, center * rr * sqrtf(rr));
        }
    }
    out[i] = m;
}

__global__ void k_pool(const float* __restrict__ in, float* __restrict__ out,
                       int C, int Hin, int Win, int Ho, int Wo) {
    int i = blockIdx.x * blockDim.x + threadIdx.x;
    if (i >= C * Ho * Wo) return;
    int c = i / (Ho * Wo), r = i % (Ho * Wo), oh = r / Wo, ow = r % Wo;
    const float* p = in + (c * Hin + 2 * oh) * Win + 2 * ow;
    float m = p[0];
    #pragma unroll
    for (int dh = 0; dh < 3; dh++)
        #pragma unroll
        for (int dw = 0; dw < 3; dw++) m = fmaxf(m, p[dh * Win + dw]);
    out[i] = m;
}

// ---- im2col + transpose + bf16 split, 8 k per thread ----
template <int KSZ>
__global__ void k_prepB8(const float* __restrict__ src, __nv_bfloat16* __restrict__ hi,
                         __nv_bfloat16* __restrict__ lo, int H, int W, int pad,
                         int Ho, int Wo, int K) {
    int kidx = (blockIdx.x * 256 + threadIdx.x) * 8;
    if (kidx >= K) return;
    int n = blockIdx.y;
    int oh = n / Wo, ow = n % Wo;
    bool vn = n < Ho * Wo;
    int kw = kidx % KSZ;
    int t = kidx / KSZ;
    int kh = t % KSZ, cc = t / KSZ;
    float v[8];
    #pragma unroll
    for (int j = 0; j < 8; j++) {
        float val = 0.f;
        if (vn) {
            int ih = oh - pad + kh, iw = ow - pad + kw;
            if (ih >= 0 && ih < H && iw >= 0 && iw < W)
                val = src[((size_t)cc * H + ih) * W + iw];
        }
        v[j] = val;
        if (++kw == KSZ) { kw = 0; if (++kh == KSZ) { kh = 0; ++cc; } }
    }
    __nv_bfloat16 h[8];
    float l[8];
    #pragma unroll
    for (int e = 0; e < 8; e++) {
        h[e] = __float2bfloat16(v[e]);
        l[e] = v[e] - __bfloat162float(h[e]);
    }
    uint4 ph = make_uint4(pack2(h[0], h[1]), pack2(h[2], h[3]),
                          pack2(h[4], h[5]), pack2(h[6], h[7]));
    uint4 pl = make_uint4(packbf2(l[0], l[1]), packbf2(l[2], l[3]),
                          packbf2(l[4], l[5]), packbf2(l[6], l[7]));
    size_t o = (size_t)n * K + kidx;
    *reinterpret_cast<uint4*>(hi + o) = ph;
    *reinterpret_cast<uint4*>(lo + o) = pl;
}

// ---- im2col + transpose, fp16 single, 8 k per thread (conv6) ----
template <int KSZ>
__global__ void k_prepF8(const float* __restrict__ src, __half* __restrict__ f,
                         int H, int W, int pad, int Ho, int Wo, int K) {
    int kidx = (blockIdx.x * 256 + threadIdx.x) * 8;
    if (kidx >= K) return;
    int n = blockIdx.y;
    int oh = n / Wo, ow = n % Wo;
    bool vn = n < Ho * Wo;
    int kw = kidx % KSZ;
    int t = kidx / KSZ;
    int kh = t % KSZ, cc = t / KSZ;
    float v[8];
    #pragma unroll
    for (int j = 0; j < 8; j++) {
        float val = 0.f;
        if (vn) {
            int ih = oh - pad + kh, iw = ow - pad + kw;
            if (ih >= 0 && ih < H && iw >= 0 && iw < W)
                val = src[((size_t)cc * H + ih) * W + iw];
        }
        v[j] = val;
        if (++kw == KSZ) { kw = 0; if (++kh == KSZ) { kh = 0; ++cc; } }
    }
    uint4 pv = make_uint4(packf16_2(v[0], v[1]), packf16_2(v[2], v[3]),
                          packf16_2(v[4], v[5]), packf16_2(v[6], v[7]));
    *reinterpret_cast<uint4*>(f + (size_t)n * K + kidx) = pv;
}

// ---- fused reduce(4)+bias+relu -> d_out(x6) AND transposed fp16 single ----
__global__ void k_fuse6(const float* __restrict__ p, const float* __restrict__ bias,
                        float* __restrict__ out, __half* __restrict__ xf) {
    __shared__ float t[32][33];
    int rb = blockIdx.x * 32, nb = blockIdx.y * 32;
    int tx = threadIdx.x, ty = threadIdx.y;
    #pragma unroll
    for (int j = 0; j < 4; j++) {
        int row = rb + ty + j * 8;
        int n = nb + tx;
        float v = 0.f;
        if (n < 300) {
            size_t o = (size_t)row * 300 + n;
            v = fmaxf(p[o] + p[o + 1228800] + p[o + 2 * 1228800] + p[o + 3 * 1228800]
                      + bias[row], 0.f);
            out[o] = v;
        }
        t[ty + j * 8][tx] = v;
    }
    __syncthreads();
    #pragma unroll
    for (int j = 0; j < 4; j++) {
        int n = nb + ty + j * 8;
        int k = rb + tx;
        xf[(size_t)n * 4096 + k] = __float2half_rn(t[tx][ty + j * 8]);
    }
}

struct Bias4 { const float* b[4]; };
__global__ void k_fuse7(const float* __restrict__ P, Bias4 bias,
                        __half* __restrict__ xf) {
    __shared__ float t[32][33];
    int br = blockIdx.z;
    const float* p = P + (size_t)br * 1228800;
    int rb = blockIdx.x * 32, nb = blockIdx.y * 32;
    int tx = threadIdx.x, ty = threadIdx.y;
    #pragma unroll
    for (int j = 0; j < 4; j++) {
        int row = rb + ty + j * 8;
        int n = nb + tx;
        float v = 0.f;
        if (n < 300) {
            size_t o = (size_t)row * 300 + n;
            v = fmaxf(p[o] + p[o + 4 * 1228800] + bias.b[br][row], 0.f);
        }
        t[ty + j * 8][tx] = v;
    }
    __syncthreads();
    #pragma unroll
    for (int j = 0; j < 4; j++) {
        int n = nb + ty + j * 8;
        int k = rb + tx;
        xf[(size_t)br * 1310720 + (size_t)n * 4096 + k] =
            __float2half_rn(t[tx][ty + j * 8]);
    }
}

__global__ void k_fuse8(const float* __restrict__ p, Bias4 bias, float* __restrict__ out) {
    int i = blockIdx.x * blockDim.x + threadIdx.x;
    if (i >= 518400) return;
    int br, start, r;
    long oofs;
    if (i < 76800)       { br = 0; start = 0;      r = 8; oofs = 1228800L; }
    else if (i < 115200) { br = 1; start = 76800;  r = 8; oofs = 1305600L; }
    else if (i < 422400) { br = 2; start = 115200; r = 4; oofs = 1344000L; }
    else                 { br = 3; start = 422400; r = 8; oofs = 1651200L; }
    int li = i - start;
    int OW = 20 * r;
    int OHW = 300 * r * r;
    int oc = li / OHW, rem = li % OHW;
    int oh = rem / OW, ow = rem % OW;
    int ic = oc * r * r + (oh % r) * r + (ow % r);
    int src = start + ic * 300 + (oh / r) * 20 + (ow / r);
    float v = p[src] + p[src + 518400] + p[src + 2 * 518400] + p[src + 3 * 518400];
    out[oofs + li] = v + bias.b[br][ic];
}

__global__ void k_redG(const float* __restrict__ p, const float* __restrict__ bias,
                       float* __restrict__ out, int total, int Ncols, int S,
                       long stride, int relu) {
    int i = blockIdx.x * blockDim.x + threadIdx.x;
    if (i >= total) return;
    float v = 0.f;
    for (int s = 0; s < S; s++) v += p[(size_t)s * stride + i];
    v += bias[i / Ncols];
    out[i] = relu ? fmaxf(v, 0.f) : v;
}

// ============================ HMMA GEMM cores ============================
#define STG 24576
#define GT_SMEM (2 * STG + 1024)

// ---- bf16 2-term split, 3 MMAs (conv2..5) ----
__device__ __forceinline__ void gemm_core(
    char* dsm, const float* __restrict__ A, const __nv_bfloat16* __restrict__ Bh,
    const __nv_bfloat16* __restrict__ Bl, float* __restrict__ C,
    int M, int K, int Ncols, int m0, int n0, int c0, int cEnd) {
    const int tid = threadIdx.x;
    const int lane = tid & 31;
    const int wid = tid >> 5;
    const int wm = wid & 3, wn = wid >> 2;

    const uint32_t base = (smem_u32(dsm) + 1023u) & ~1023u;
    const int bR = tid >> 2, bF = tid & 3;
    const uint32_t bOff = swz64((uint32_t)(bR * 64 + bF * 16));
    const __nv_bfloat16* bhSrc = Bh + (size_t)(n0 + bR) * K + bF * 8;
    const __nv_bfloat16* blSrc = Bl + (size_t)(n0 + bR) * K + bF * 8;

    uint32_t pA[2], pB[2];
    {
        uint32_t r = (uint32_t)(wm * 32 + (lane & 15));
        uint32_t kc = (uint32_t)((lane >> 4) * 16);
        #pragma unroll
        for (int mt = 0; mt < 2; mt++) {
            uint32_t o = (r + mt * 16) * 64 + kc;
            pA[mt] = o ^ ((o >> 3) & 0x30);
        }
        uint32_t rn = (uint32_t)(wn * 32 + (lane & 7) + ((lane >> 4) << 3));
        uint32_t kcb = (uint32_t)(((lane >> 3) & 1) * 16);
        #pragma unroll
        for (int nt = 0; nt < 2; nt++) {
            uint32_t o = (rn + nt * 16) * 64 + kcb;
            pB[nt] = o ^ ((o >> 3) & 0x30);
        }
    }

    float acc[2][4][4] = {};
    float4 aP[2][2];
    {
        const int k0 = c0 << 5;
        #pragma unroll
        for (int it = 0; it < 2; it++) {
            int idx = tid + it * 256;
            int row = idx >> 2, f8 = idx & 3;
            int gr = m0 + row, k = k0 + f8 * 8;
            if (gr < M) {
                aP[it][0] = *reinterpret_cast<const float4*>(A + (size_t)gr * K + k);
                aP[it][1] = *reinterpret_cast<const float4*>(A + (size_t)gr * K + k + 4);
            } else {
                aP[it][0] = aP[it][1] = make_float4(0.f, 0.f, 0.f, 0.f);
            }
        }
        const uint32_t stg0 = base + (uint32_t)(c0 & 1) * STG;
        cpasync16(stg0 + 16384u + bOff, bhSrc + k0);
        cpasync16(stg0 + 20480u + bOff, blSrc + k0);
        cpasync_commit();
    }

    for (int c = c0; c < cEnd; c++) {
        const uint32_t stg = base + (uint32_t)(c & 1) * STG;
        #pragma unroll
        for (int it = 0; it < 2; it++) {
            int idx = tid + it * 256;
            int row = idx >> 2, f8 = idx & 3;
            float s[8] = {aP[it][0].x, aP[it][0].y, aP[it][0].z, aP[it][0].w,
                          aP[it][1].x, aP[it][1].y, aP[it][1].z, aP[it][1].w};
            __nv_bfloat16 h[8];
            float l[8];
            #pragma unroll
            for (int e = 0; e < 8; e++) {
                h[e] = __float2bfloat16(s[e]);
                l[e] = s[e] - __bfloat162float(h[e]);
            }
            uint4 hv = make_uint4(pack2(h[0], h[1]), pack2(h[2], h[3]),
                                  pack2(h[4], h[5]), pack2(h[6], h[7]));
            uint4 lv = make_uint4(packbf2(l[0], l[1]), packbf2(l[2], l[3]),
                                  packbf2(l[4], l[5]), packbf2(l[6], l[7]));
            uint32_t off = swz64((uint32_t)(row * 64 + f8 * 16));
            sts128(stg + off, hv);
            sts128(stg + 8192u + off, lv);
        }
        cpasync_wait0();
        __syncthreads();
        if (c + 1 < cEnd) {
            const int k0 = (c + 1) << 5;
            #pragma unroll
            for (int it = 0; it < 2; it++) {
                int idx = tid + it * 256;
                int row = idx >> 2, f8 = idx & 3;
                int gr = m0 + row, k = k0 + f8 * 8;
                if (gr < M) {
                    aP[it][0] = *reinterpret_cast<const float4*>(A + (size_t)gr * K + k);
                    aP[it][1] = *reinterpret_cast<const float4*>(A + (size_t)gr * K + k + 4);
                } else {
                    aP[it][0] = aP[it][1] = make_float4(0.f, 0.f, 0.f, 0.f);
                }
            }
            const uint32_t stgN = base + (uint32_t)((c + 1) & 1) * STG;
            cpasync16(stgN + 16384u + bOff, bhSrc + k0);
            cpasync16(stgN + 20480u + bOff, blSrc + k0);
            cpasync_commit();
        }
        #pragma unroll
        for (int ks = 0; ks < 2; ks++) {
            const uint32_t kb = (uint32_t)(ks << 5);
            uint32_t ah[2][4], al[2][4], bh_[2][4], bl_[2][4];
            ldm4(ah[0], stg + (pA[0] ^ kb));
            ldm4(ah[1], stg + (pA[1] ^ kb));
            ldm4(al[0], stg + 8192u + (pA[0] ^ kb));
            ldm4(al[1], stg + 8192u + (pA[1] ^ kb));
            ldm4(bh_[0], stg + 16384u + (pB[0] ^ kb));
            ldm4(bh_[1], stg + 16384u + (pB[1] ^ kb));
            ldm4(bl_[0], stg + 20480u + (pB[0] ^ kb));
            ldm4(bl_[1], stg + 20480u + (pB[1] ^ kb));
            #pragma unroll
            for (int mt = 0; mt < 2; mt++)
                #pragma unroll
                for (int nt = 0; nt < 4; nt++) {
                    const uint32_t* bh2 = &bh_[nt >> 1][(nt & 1) * 2];
                    const uint32_t* bl2 = &bl_[nt >> 1][(nt & 1) * 2];
                    mma_bf16(acc[mt][nt], ah[mt], bh2);
                    mma_bf16(acc[mt][nt], ah[mt], bl2);
                    mma_bf16(acc[mt][nt], al[mt], bh2);
                }
        }
    }

    #pragma unroll
    for (int mt = 0; mt < 2; mt++) {
        int r0 = m0 + wm * 32 + mt * 16 + (lane >> 2);
        #pragma unroll
        for (int half = 0; half < 2; half++) {
            int row = r0 + half * 8;
            if (row >= M) continue;
            #pragma unroll
            for (int nt = 0; nt < 4; nt++) {
                int col = n0 + wn * 32 + nt * 8 + (lane & 3) * 2;
                if (col < Ncols) C[(size_t)row * Ncols + col] = acc[mt][nt][half * 2];
                if (col + 1 < Ncols)
                    C[(size_t)row * Ncols + col + 1] = acc[mt][nt][half * 2 + 1];
            }
        }
    }
}

// ---- fp16: A split exactly (x64), B single fp16, 2 MMAs ----
__device__ __forceinline__ void gemm_core_f16(
    char* dsm, const float* __restrict__ A, const __half* __restrict__ Bf,
    float* __restrict__ C, int M, int K, int Ncols, int m0, int n0,
    int c0, int cEnd) {
    const int tid = threadIdx.x;
    const int lane = tid & 31;
    const int wid = tid >> 5;
    const int wm = wid & 3, wn = wid >> 2;

    const uint32_t base = (smem_u32(dsm) + 1023u) & ~1023u;
    const int bR = tid >> 2, bF = tid & 3;
    const uint32_t bOff = swz64((uint32_t)(bR * 64 + bF * 16));
    const __half* bSrc = Bf + (size_t)(n0 + bR) * K + bF * 8;

    uint32_t pA[2], pB[2];
    {
        uint32_t r = (uint32_t)(wm * 32 + (lane & 15));
        uint32_t kc = (uint32_t)((lane >> 4) * 16);
        #pragma unroll
        for (int mt = 0; mt < 2; mt++) {
            uint32_t o = (r + mt * 16) * 64 + kc;
            pA[mt] = o ^ ((o >> 3) & 0x30);
        }
        uint32_t rn = (uint32_t)(wn * 32 + (lane & 7) + ((lane >> 4) << 3));
        uint32_t kcb = (uint32_t)(((lane >> 3) & 1) * 16);
        #pragma unroll
        for (int nt = 0; nt < 2; nt++) {
            uint32_t o = (rn + nt * 16) * 64 + kcb;
            pB[nt] = o ^ ((o >> 3) & 0x30);
        }
    }

    float acc[2][4][4] = {};
    float4 aP[2][2];
    {
        const int k0 = c0 << 5;
        #pragma unroll
        for (int it = 0; it < 2; it++) {
            int idx = tid + it * 256;
            int row = idx >> 2, f8 = idx & 3;
            int gr = m0 + row, k = k0 + f8 * 8;
            if (gr < M) {
                aP[it][0] = *reinterpret_cast<const float4*>(A + (size_t)gr * K + k);
                aP[it][1] = *reinterpret_cast<const float4*>(A + (size_t)gr * K + k + 4);
            } else {
                aP[it][0] = aP[it][1] = make_float4(0.f, 0.f, 0.f, 0.f);
            }
        }
        const uint32_t stg0 = base + (uint32_t)(c0 & 1) * STG;
        cpasync16(stg0 + 16384u + bOff, bSrc + k0);
        cpasync_commit();
    }

    for (int c = c0; c < cEnd; c++) {
        const uint32_t stg = base + (uint32_t)(c & 1) * STG;
        #pragma unroll
        for (int it = 0; it < 2; it++) {
            int idx = tid + it * 256;
            int row = idx >> 2, f8 = idx & 3;
            float s[8] = {aP[it][0].x, aP[it][0].y, aP[it][0].z, aP[it][0].w,
                          aP[it][1].x, aP[it][1].y, aP[it][1].z, aP[it][1].w};
            __half h[8];
            float l[8];
            #pragma unroll
            for (int e = 0; e < 8; e++) {
                float as = s[e] * 64.f;
                h[e] = __float2half_rn(as);
                l[e] = as - __half2float(h[e]);
            }
            uint4 hv = make_uint4(packh2(h[0], h[1]), packh2(h[2], h[3]),
                                  packh2(h[4], h[5]), packh2(h[6], h[7]));
            uint4 lv = make_uint4(packf16_2(l[0], l[1]), packf16_2(l[2], l[3]),
                                  packf16_2(l[4], l[5]), packf16_2(l[6], l[7]));
            uint32_t off = swz64((uint32_t)(row * 64 + f8 * 16));
            sts128(stg + off, hv);
            sts128(stg + 8192u + off, lv);
        }
        cpasync_wait0();
        __syncthreads();
        if (c + 1 < cEnd) {
            const int k0 = (c + 1) << 5;
            #pragma unroll
            for (int it = 0; it < 2; it++) {
                int idx = tid + it * 256;
                int row = idx >> 2, f8 = idx & 3;
                int gr = m0 + row, k = k0 + f8 * 8;
                if (gr < M) {
                    aP[it][0] = *reinterpret_cast<const float4*>(A + (size_t)gr * K + k);
                    aP[it][1] = *reinterpret_cast<const float4*>(A + (size_t)gr * K + k + 4);
                } else {
                    aP[it][0] = aP[it][1] = make_float4(0.f, 0.f, 0.f, 0.f);
                }
            }
            const uint32_t stgN = base + (uint32_t)((c + 1) & 1) * STG;
            cpasync16(stgN + 16384u + bOff, bSrc + k0);
            cpasync_commit();
        }
        #pragma unroll
        for (int ks = 0; ks < 2; ks++) {
            const uint32_t kb = (uint32_t)(ks << 5);
            uint32_t ah[2][4], al[2][4], bf_[2][4];
            ldm4(ah[0], stg + (pA[0] ^ kb));
            ldm4(ah[1], stg + (pA[1] ^ kb));
            ldm4(al[0], stg + 8192u + (pA[0] ^ kb));
            ldm4(al[1], stg + 8192u + (pA[1] ^ kb));
            ldm4(bf_[0], stg + 16384u + (pB[0] ^ kb));
            ldm4(bf_[1], stg + 16384u + (pB[1] ^ kb));
            #pragma unroll
            for (int mt = 0; mt < 2; mt++)
                #pragma unroll
                for (int nt = 0; nt < 4; nt++) {
                    const uint32_t* b2 = &bf_[nt >> 1][(nt & 1) * 2];
                    mma_f16(acc[mt][nt], ah[mt], b2);
                    mma_f16(acc[mt][nt], al[mt], b2);
                }
        }
    }

    const float INV = 1.f / 64.f;
    #pragma unroll
    for (int mt = 0; mt < 2; mt++) {
        int r0 = m0 + wm * 32 + mt * 16 + (lane >> 2);
        #pragma unroll
        for (int half = 0; half < 2; half++) {
            int row = r0 + half * 8;
            if (row >= M) continue;
            #pragma unroll
            for (int nt = 0; nt < 4; nt++) {
                int col = n0 + wn * 32 + nt * 8 + (lane & 3) * 2;
                if (col < Ncols)
                    C[(size_t)row * Ncols + col] = acc[mt][nt][half * 2] * INV;
                if (col + 1 < Ncols)
                    C[(size_t)row * Ncols + col + 1] = acc[mt][nt][half * 2 + 1] * INV;
            }
        }
    }
}

__global__ __launch_bounds__(256, 2) void k_gemm_skG(
    const float* __restrict__ A, const __nv_bfloat16* __restrict__ Bh,
    const __nv_bfloat16* __restrict__ Bl, float* __restrict__ P,
    int M, int K, int Ncols, int S, long stride) {
    extern __shared__ char dsm[];
    const int z = blockIdx.z;
    const int nc = K >> 5;
    const int per = nc / S, rem = nc % S;
    const int c0 = z * per + (z < rem ? z : rem);
    const int cEnd = c0 + per + (z < rem ? 1 : 0);
    gemm_core(dsm, A, Bh, Bl, P + (size_t)z * stride,
              M, K, Ncols, blockIdx.y * 128, blockIdx.x * 64, c0, cEnd);
}

// conv6 fp16 split-K=4
__global__ __launch_bounds__(256, 2) void k_gemm_sk6f(
    const float* __restrict__ A, const __half* __restrict__ Bf,
    float* __restrict__ P) {
    extern __shared__ char dsm[];
    const int z = blockIdx.z;
    const int per = (13824 >> 5) >> 2;
    gemm_core_f16(dsm, A, Bf, P + (size_t)z * 1228800, 4096, 13824, 300,
                  blockIdx.y * 128, blockIdx.x * 64, z * per, (z + 1) * per);
}

struct Ptr4 { const float* p[4]; };
__global__ __launch_bounds__(256, 2) void k_gemm7f(
    Ptr4 W, const __half* __restrict__ Bf, float* __restrict__ P) {
    extern __shared__ char dsm[];
    const int br = blockIdx.z >> 1, sl = blockIdx.z & 1;
    const int per = 128 >> 1;
    float* out = P + (size_t)sl * 4 * 1228800 + (size_t)br * 1228800;
    gemm_core_f16(dsm, W.p[br], Bf, out, 4096, 4096, 300,
                  blockIdx.y * 128, blockIdx.x * 64, sl * per, (sl + 1) * per);
}

__global__ __launch_bounds__(256, 2) void k_gemm8f(
    Ptr4 W, const __half* __restrict__ Bf, float* __restrict__ P) {
    extern __shared__ char dsm[];
    const int br = blockIdx.z >> 2, sl = blockIdx.z & 3;
    const int C8s[4] = {256, 128, 1024, 320};
    const int roff[4] = {0, 256, 384, 1408};
    const int M = C8s[br];
    const int m0 = blockIdx.y * 128;
    if (m0 >= M) return;
    const int per = 128 >> 2;
    float* out = P + (size_t)sl * 518400 + (size_t)roff[br] * 300;
    gemm_core_f16(dsm, W.p[br], Bf + (size_t)br * 1310720, out, M, 4096, 300,
                  m0, blockIdx.x * 64, sl * per, (sl + 1) * per);
}

static inline dim3 blk1(long n) { return dim3((unsigned)((n + 255) / 256)); }

extern "C" void kernel_launch(void* const* d_in, const int* in_sizes, int n_in,
                              void* d_out, int out_size) {
    const float* x  = (const float*)d_in[0];
    const float* w1 = (const float*)d_in[1];  const float* b1 = (const float*)d_in[2];
    const float* w2 = (const float*)d_in[3];  const float* b2 = (const float*)d_in[4];
    const float* w3 = (const float*)d_in[5];  const float* b3 = (const float*)d_in[6];
    const float* w4 = (const float*)d_in[7];  const float* b4 = (const float*)d_in[8];
    const float* w5 = (const float*)d_in[9];  const float* b5 = (const float*)d_in[10];
    const float* w6 = (const float*)d_in[11]; const float* b6 = (const float*)d_in[12];
    const float* w7[4] = {(const float*)d_in[13], (const float*)d_in[17],
                          (const float*)d_in[21], (const float*)d_in[25]};
    const float* b7[4] = {(const float*)d_in[14], (const float*)d_in[18],
                          (const float*)d_in[22], (const float*)d_in[26]};
    const float* w8[4] = {(const float*)d_in[15], (const float*)d_in[19],
                          (const float*)d_in[23], (const float*)d_in[27]};
    const float* b8[4] = {(const float*)d_in[16], (const float*)d_in[20],
                          (const float*)d_in[24], (const float*)d_in[28]};
    float* out = (float*)d_out;

    cudaFuncSetAttribute(k_gemm_skG,  cudaFuncAttributeMaxDynamicSharedMemorySize, GT_SMEM);
    cudaFuncSetAttribute(k_gemm_sk6f, cudaFuncAttributeMaxDynamicSharedMemorySize, GT_SMEM);
    cudaFuncSetAttribute(k_gemm7f,    cudaFuncAttributeMaxDynamicSharedMemorySize, GT_SMEM);
    cudaFuncSetAttribute(k_gemm8f,    cudaFuncAttributeMaxDynamicSharedMemorySize, GT_SMEM);

    float *c1, *u1, *p2, *c3, *c4, *c5, *p5, *p6, *p7, *p8;
    __nv_bfloat16 *bh, *bl;
    __half *b6f, *x6f, *x7f;
    cudaGetSymbolAddress((void**)&c1, g_c1);
    cudaGetSymbolAddress((void**)&u1, g_u1);
    cudaGetSymbolAddress((void**)&p2, g_p2);
    cudaGetSymbolAddress((void**)&c3, g_c3);
    cudaGetSymbolAddress((void**)&c4, g_c4);
    cudaGetSymbolAddress((void**)&c5, g_c5);
    cudaGetSymbolAddress((void**)&p5, g_p5);
    cudaGetSymbolAddress((void**)&p6, g_p6);
    cudaGetSymbolAddress((void**)&p7, g_p7);
    cudaGetSymbolAddress((void**)&p8, g_p8);
    cudaGetSymbolAddress((void**)&bh, gB_hi);
    cudaGetSymbolAddress((void**)&bl, gB_lo);
    cudaGetSymbolAddress((void**)&b6f, g_B6f);
    cudaGetSymbolAddress((void**)&x6f, g_x6f);
    cudaGetSymbolAddress((void**)&x7f, g_x7f);

    // stage 1: direct conv1 -> fused LRN+pool+upsample
    k_conv1<<<blk1(96L * 118 * 158), 256>>>(x, w1, b1, c1);
    k_pooluplrn<<<blk1(96L * 59 * 79), 256>>>(c1, u1);

    // conv2: M=256 K=2400 N=4661 (Npad 4672), split-K=2; fused red+LRN+pool
    k_prepB8<5><<<dim3(2, 4672), 256>>>(u1, bh, bl, 59, 79, 2, 59, 79, 2400);
    k_gemm_skG<<<dim3(73, 2, 2), 256, GT_SMEM>>>(w2, bh, bl, p6,
                                                 256, 2400, 4661, 2, 1193216L);
    k_redpool2<<<blk1(256L * 29 * 39), 256>>>(p6, b2, p2);

    // conv3: M=384 K=2304 N=1131 (Npad 1152), split-K=4
    k_prepB8<3><<<dim3(2, 1152), 256>>>(p2, bh, bl, 29, 39, 1, 29, 39, 2304);
    k_gemm_skG<<<dim3(18, 3, 4), 256, GT_SMEM>>>(w3, bh, bl, p6,
                                                 384, 2304, 1131, 4, 434304L);
    k_redG<<<blk1(434304L), 256>>>(p6, b3, c3, 434304, 1131, 4, 434304L, 1);
    // conv4
    k_prepB8<3><<<dim3(2, 1152), 256>>>(c3, bh, bl, 29, 39, 1, 29, 39, 3456);
    k_gemm_skG<<<dim3(18, 3, 4), 256, GT_SMEM>>>(w4, bh, bl, p6,
                                                 384, 3456, 1131, 4, 434304L);
    k_redG<<<blk1(434304L), 256>>>(p6, b4, c4, 434304, 1131, 4, 434304L, 1);
    // conv5
    k_prepB8<3><<<dim3(2, 1152), 256>>>(c4, bh, bl, 29, 39, 1, 29, 39, 3456);
    k_gemm_skG<<<dim3(18, 3, 4), 256, GT_SMEM>>>(w5, bh, bl, p6,
                                                 384, 3456, 1131, 4, 434304L);
    k_redG<<<blk1(434304L), 256>>>(p6, b5, c5, 434304, 1131, 4, 434304L, 1);
    k_pool<<<blk1(384L * 14 * 19), 256>>>(c5, p5, 384, 29, 39, 14, 19);

    // conv6 (fp16 2-MMA): split-K=4 -> fused reduce+relu -> d_out + x6 fp16
    k_prepF8<6><<<dim3(7, 320), 256>>>(p5, b6f, 14, 19, 3, 15, 20, 13824);
    k_gemm_sk6f<<<dim3(5, 32, 4), 256, GT_SMEM>>>(w6, b6f, p6);
    k_fuse6<<<dim3(128, 10), dim3(32, 8)>>>(p6, b6, out, x6f);

    // gemm7 (fp16 2-MMA, 4 branches, split-K=2) -> fused -> x7 fp16
    Ptr4 W7 = {{w7[0], w7[1], w7[2], w7[3]}};
    k_gemm7f<<<dim3(5, 32, 8), 256, GT_SMEM>>>(W7, x6f, p7);
    Bias4 B7 = {{b7[0], b7[1], b7[2], b7[3]}};
    k_fuse7<<<dim3(128, 10, 4), dim3(32, 8)>>>(p7, B7, x7f);

    // gemm8 (fp16 2-MMA, 4 branches packed, split-K=4) -> reduce+bias+tile
    Ptr4 W8 = {{w8[0], w8[1], w8[2], w8[3]}};
    k_gemm8f<<<dim3(5, 8, 16), 256, GT_SMEM>>>(W8, x7f, p8);
    Bias4 B8 = {{b8[0], b8[1], b8[2], b8[3]}};
    k_fuse8<<<blk1(518400L), 256>>>(p8, B8, out);
}

// round 14
// speedup vs baseline: 1.8932x; 1.0082x over previous
#include <cuda_runtime.h>
#include <cuda_fp16.h>
#include <math.h>
#include <stdint.h>

// ---------------------------------------------------------------------------
// VPGNet forward. ALL conv GEMMs: exact-A-split (x64) fp16 2-MMA HMMA,
// fp32 accumulate. Split-K, cp.async B, fused epilogues.
// Output: [x6|x8a|x8b|x8c|x8d] = 1,747,200 floats
// ---------------------------------------------------------------------------

// ---- scratch ----
__device__ float g_c1[96 * 118 * 158];
__device__ float g_u1[96 * 59 * 79];
__device__ float g_p2[256 * 29 * 39];
__device__ float g_c3[384 * 29 * 39];
__device__ float g_c4[384 * 29 * 39];
__device__ float g_c5[384 * 29 * 39];
__device__ float g_p5[384 * 14 * 19];
__device__ float g_p6[6 * 4096 * 300];        // split-K partials (shared)
__device__ float g_p7[2 * 4 * 4096 * 300];
__device__ float g_p8[4 * 1728 * 300];
// fp16 activation buffers
__device__ __half g_Bf[11250000];             // im2col (max conv2 4672*2400)
__device__ __half g_x6f[320 * 4096];
__device__ __half g_x7f[4 * 320 * 4096];

// ============================ helpers ============================
__device__ __forceinline__ uint32_t smem_u32(const void* p) {
    uint32_t a;
    asm("{ .reg .u64 t; cvta.to.shared.u64 t, %1; cvt.u32.u64 %0, t; }" : "=r"(a) : "l"(p));
    return a;
}
__device__ __forceinline__ uint32_t swz64(uint32_t o) { return o ^ ((o >> 3) & 0x30); }

__device__ __forceinline__ void ldm4(uint32_t* r, uint32_t a) {
    asm volatile("ldmatrix.sync.aligned.m8n8.x4.shared.b16 {%0,%1,%2,%3}, [%4];"
                 : "=r"(r[0]), "=r"(r[1]), "=r"(r[2]), "=r"(r[3]) : "r"(a));
}
__device__ __forceinline__ void mma_f16(float* c, const uint32_t* a, const uint32_t* b) {
    asm volatile("mma.sync.aligned.m16n8k16.row.col.f32.f16.f16.f32 "
                 "{%0,%1,%2,%3}, {%4,%5,%6,%7}, {%8,%9}, {%0,%1,%2,%3};"
                 : "+f"(c[0]), "+f"(c[1]), "+f"(c[2]), "+f"(c[3])
                 : "r"(a[0]), "r"(a[1]), "r"(a[2]), "r"(a[3]), "r"(b[0]), "r"(b[1]));
}
__device__ __forceinline__ void sts128(uint32_t a, uint4 v) {
    asm volatile("st.shared.v4.b32 [%0], {%1,%2,%3,%4};"
                 :: "r"(a), "r"(v.x), "r"(v.y), "r"(v.z), "r"(v.w) : "memory");
}
__device__ __forceinline__ void cpasync16(uint32_t saddr, const void* gaddr) {
    asm volatile("cp.async.cg.shared.global [%0], [%1], 16;"
                 :: "r"(saddr), "l"(gaddr) : "memory");
}
__device__ __forceinline__ void cpasync_commit() {
    asm volatile("cp.async.commit_group;" ::: "memory");
}
__device__ __forceinline__ void cpasync_wait0() {
    asm volatile("cp.async.wait_group 0;" ::: "memory");
}
__device__ __forceinline__ uint32_t packh2(__half a, __half b) {
    return (uint32_t)__half_as_ushort(a) | ((uint32_t)__half_as_ushort(b) << 16);
}
__device__ __forceinline__ uint32_t packf16_2(float lo, float hi) {
    uint32_t d;
    asm("cvt.rn.f16x2.f32 %0, %1, %2;" : "=r"(d) : "f"(hi), "f"(lo));
    return d;
}

// ============================ elementwise layers ============================
__global__ void k_conv1(const float* __restrict__ x, const float* __restrict__ w,
                        const float* __restrict__ b, float* __restrict__ out) {
    const int HO = 118, WO = 158;
    int i = blockIdx.x * blockDim.x + threadIdx.x;
    if (i >= 96 * HO * WO) return;
    int c = i / (HO * WO), r = i % (HO * WO), oh = r / WO, ow = r % WO;
    float acc = b[c];
    const float* wp = w + c * 3 * 121;
    for (int ci = 0; ci < 3; ci++) {
        const float* xc = x + ci * 480 * 640;
        const float* wc = wp + ci * 121;
        #pragma unroll
        for (int kh = 0; kh < 11; kh++) {
            const float* xp = xc + (oh * 4 + kh) * 640 + ow * 4;
            const float* wq = wc + kh * 11;
            #pragma unroll
            for (int kw = 0; kw < 11; kw++) acc = fmaf(xp[kw], wq[kw], acc);
        }
    }
    out[i] = fmaxf(acc, 0.f);
}

__global__ void k_pooluplrn(const float* __restrict__ c1, float* __restrict__ out) {
    int i = blockIdx.x * blockDim.x + threadIdx.x;
    if (i >= 96 * 59 * 79) return;
    int c = i / (59 * 79), r = i % (59 * 79), oh = r / 79, ow = r % 79;
    int hi = (oh * 58) / 59, wi = (ow * 78) / 79;
    int jlo = c - 2 > 0 ? c - 2 : 0;
    int jhi = c + 2 < 95 ? c + 2 : 95;
    const int HW = 118 * 158;
    float m = -1e30f;
    #pragma unroll
    for (int dh = 0; dh < 3; dh++) {
        #pragma unroll
        for (int dw = 0; dw < 3; dw++) {
            const float* p = c1 + (2 * hi + dh) * 158 + 2 * wi + dw;
            float s = 0.f;
            for (int j = jlo; j <= jhi; j++) { float v = p[j * HW]; s = fmaf(v, v, s); }
            float t = 2.0f + 1e-4f * s;
            float rr = rsqrtf(t);
            m = fmaxf(m, p[c * HW] * rr * sqrtf(rr));
        }
    }
    out[i] = m;
}

// ---- fused conv2 split-K reduce + bias + relu + LRN(k=8) + maxpool ----
__global__ void k_redpool2(const float* __restrict__ p, const float* __restrict__ bias,
                           float* __restrict__ out) {
    int i = blockIdx.x * blockDim.x + threadIdx.x;
    if (i >= 256 * 29 * 39) return;
    int c = i / (29 * 39), r = i % (29 * 39), oh = r / 39, ow = r % 39;
    int jlo = c - 2 > 0 ? c - 2 : 0;
    int jhi = c + 2 < 255 ? c + 2 : 255;
    float m = -1e30f;
    #pragma unroll
    for (int dh = 0; dh < 3; dh++) {
        #pragma unroll
        for (int dw = 0; dw < 3; dw++) {
            int pos = (2 * oh + dh) * 79 + 2 * ow + dw;
            float s = 0.f, center = 0.f;
            for (int j = jlo; j <= jhi; j++) {
                size_t o = (size_t)j * 4661 + pos;
                float v = fmaxf(p[o] + p[o + 1193216] + bias[j], 0.f);
                s = fmaf(v, v, s);
                if (j == c) center = v;
            }
            float t = 8.0f + 1e-4f * s;
            float rr = rsqrtf(t);
            m = fmaxf(m, center * rr * sqrtf(rr));
        }
    }
    out[i] = m;
}

__global__ void k_pool(const float* __restrict__ in, float* __restrict__ out,
                       int C, int Hin, int Win, int Ho, int Wo) {
    int i = blockIdx.x * blockDim.x + threadIdx.x;
    if (i >= C * Ho * Wo) return;
    int c = i / (Ho * Wo), r = i % (Ho * Wo), oh = r / Wo, ow = r % Wo;
    const float* p = in + (c * Hin + 2 * oh) * Win + 2 * ow;
    float m = p[0];
    #pragma unroll
    for (int dh = 0; dh < 3; dh++)
        #pragma unroll
        for (int dw = 0; dw < 3; dw++) m = fmaxf(m, p[dh * Win + dw]);
    out[i] = m;
}

// ---- im2col + transpose, fp16 single, 8 k per thread ----
template <int KSZ>
__global__ void k_prepF8(const float* __restrict__ src, __half* __restrict__ f,
                         int H, int W, int pad, int Ho, int Wo, int K) {
    int kidx = (blockIdx.x * 256 + threadIdx.x) * 8;
    if (kidx >= K) return;
    int n = blockIdx.y;
    int oh = n / Wo, ow = n % Wo;
    bool vn = n < Ho * Wo;
    int kw = kidx % KSZ;
    int t = kidx / KSZ;
    int kh = t % KSZ, cc = t / KSZ;
    float v[8];
    #pragma unroll
    for (int j = 0; j < 8; j++) {
        float val = 0.f;
        if (vn) {
            int ih = oh - pad + kh, iw = ow - pad + kw;
            if (ih >= 0 && ih < H && iw >= 0 && iw < W)
                val = src[((size_t)cc * H + ih) * W + iw];
        }
        v[j] = val;
        if (++kw == KSZ) { kw = 0; if (++kh == KSZ) { kh = 0; ++cc; } }
    }
    uint4 pv = make_uint4(packf16_2(v[0], v[1]), packf16_2(v[2], v[3]),
                          packf16_2(v[4], v[5]), packf16_2(v[6], v[7]));
    *reinterpret_cast<uint4*>(f + (size_t)n * K + kidx) = pv;
}

// ---- fused reduce(4)+bias+relu -> d_out(x6) AND transposed fp16 single ----
__global__ void k_fuse6(const float* __restrict__ p, const float* __restrict__ bias,
                        float* __restrict__ out, __half* __restrict__ xf) {
    __shared__ float t[32][33];
    int rb = blockIdx.x * 32, nb = blockIdx.y * 32;
    int tx = threadIdx.x, ty = threadIdx.y;
    #pragma unroll
    for (int j = 0; j < 4; j++) {
        int row = rb + ty + j * 8;
        int n = nb + tx;
        float v = 0.f;
        if (n < 300) {
            size_t o = (size_t)row * 300 + n;
            v = fmaxf(p[o] + p[o + 1228800] + p[o + 2 * 1228800] + p[o + 3 * 1228800]
                      + bias[row], 0.f);
            out[o] = v;
        }
        t[ty + j * 8][tx] = v;
    }
    __syncthreads();
    #pragma unroll
    for (int j = 0; j < 4; j++) {
        int n = nb + ty + j * 8;
        int k = rb + tx;
        xf[(size_t)n * 4096 + k] = __float2half_rn(t[tx][ty + j * 8]);
    }
}

struct Bias4 { const float* b[4]; };
__global__ void k_fuse7(const float* __restrict__ P, Bias4 bias,
                        __half* __restrict__ xf) {
    __shared__ float t[32][33];
    int br = blockIdx.z;
    const float* p = P + (size_t)br * 1228800;
    int rb = blockIdx.x * 32, nb = blockIdx.y * 32;
    int tx = threadIdx.x, ty = threadIdx.y;
    #pragma unroll
    for (int j = 0; j < 4; j++) {
        int row = rb + ty + j * 8;
        int n = nb + tx;
        float v = 0.f;
        if (n < 300) {
            size_t o = (size_t)row * 300 + n;
            v = fmaxf(p[o] + p[o + 4 * 1228800] + bias.b[br][row], 0.f);
        }
        t[ty + j * 8][tx] = v;
    }
    __syncthreads();
    #pragma unroll
    for (int j = 0; j < 4; j++) {
        int n = nb + ty + j * 8;
        int k = rb + tx;
        xf[(size_t)br * 1310720 + (size_t)n * 4096 + k] =
            __float2half_rn(t[tx][ty + j * 8]);
    }
}

__global__ void k_fuse8(const float* __restrict__ p, Bias4 bias, float* __restrict__ out) {
    int i = blockIdx.x * blockDim.x + threadIdx.x;
    if (i >= 518400) return;
    int br, start, r;
    long oofs;
    if (i < 76800)       { br = 0; start = 0;      r = 8; oofs = 1228800L; }
    else if (i < 115200) { br = 1; start = 76800;  r = 8; oofs = 1305600L; }
    else if (i < 422400) { br = 2; start = 115200; r = 4; oofs = 1344000L; }
    else                 { br = 3; start = 422400; r = 8; oofs = 1651200L; }
    int li = i - start;
    int OW = 20 * r;
    int OHW = 300 * r * r;
    int oc = li / OHW, rem = li % OHW;
    int oh = rem / OW, ow = rem % OW;
    int ic = oc * r * r + (oh % r) * r + (ow % r);
    int src = start + ic * 300 + (oh / r) * 20 + (ow / r);
    float v = p[src] + p[src + 518400] + p[src + 2 * 518400] + p[src + 3 * 518400];
    out[oofs + li] = v + bias.b[br][ic];
}

__global__ void k_redG(const float* __restrict__ p, const float* __restrict__ bias,
                       float* __restrict__ out, int total, int Ncols, int S,
                       long stride, int relu) {
    int i = blockIdx.x * blockDim.x + threadIdx.x;
    if (i >= total) return;
    float v = 0.f;
    for (int s = 0; s < S; s++) v += p[(size_t)s * stride + i];
    v += bias[i / Ncols];
    out[i] = relu ? fmaxf(v, 0.f) : v;
}

// ============================ fp16 HMMA GEMM core ============================
// CTA tile 128x64, BK=32, 256 threads, 8 warps 4m x 2n.
// A: fp32 reg-prefetch, exact x64 fp16 split (2 MMAs). B: cp.async fp16.
#define STG 24576
#define GT_SMEM (2 * STG + 1024)

__device__ __forceinline__ void gemm_core_f16(
    char* dsm, const float* __restrict__ A, const __half* __restrict__ Bf,
    float* __restrict__ C, int M, int K, int Ncols, int m0, int n0,
    int c0, int cEnd) {
    const int tid = threadIdx.x;
    const int lane = tid & 31;
    const int wid = tid >> 5;
    const int wm = wid & 3, wn = wid >> 2;

    const uint32_t base = (smem_u32(dsm) + 1023u) & ~1023u;
    const int bR = tid >> 2, bF = tid & 3;
    const uint32_t bOff = swz64((uint32_t)(bR * 64 + bF * 16));
    const __half* bSrc = Bf + (size_t)(n0 + bR) * K + bF * 8;

    uint32_t pA[2], pB[2];
    {
        uint32_t r = (uint32_t)(wm * 32 + (lane & 15));
        uint32_t kc = (uint32_t)((lane >> 4) * 16);
        #pragma unroll
        for (int mt = 0; mt < 2; mt++) {
            uint32_t o = (r + mt * 16) * 64 + kc;
            pA[mt] = o ^ ((o >> 3) & 0x30);
        }
        uint32_t rn = (uint32_t)(wn * 32 + (lane & 7) + ((lane >> 4) << 3));
        uint32_t kcb = (uint32_t)(((lane >> 3) & 1) * 16);
        #pragma unroll
        for (int nt = 0; nt < 2; nt++) {
            uint32_t o = (rn + nt * 16) * 64 + kcb;
            pB[nt] = o ^ ((o >> 3) & 0x30);
        }
    }

    float acc[2][4][4] = {};
    float4 aP[2][2];
    {
        const int k0 = c0 << 5;
        #pragma unroll
        for (int it = 0; it < 2; it++) {
            int idx = tid + it * 256;
            int row = idx >> 2, f8 = idx & 3;
            int gr = m0 + row, k = k0 + f8 * 8;
            if (gr < M) {
                aP[it][0] = *reinterpret_cast<const float4*>(A + (size_t)gr * K + k);
                aP[it][1] = *reinterpret_cast<const float4*>(A + (size_t)gr * K + k + 4);
            } else {
                aP[it][0] = aP[it][1] = make_float4(0.f, 0.f, 0.f, 0.f);
            }
        }
        const uint32_t stg0 = base + (uint32_t)(c0 & 1) * STG;
        cpasync16(stg0 + 16384u + bOff, bSrc + k0);
        cpasync_commit();
    }

    for (int c = c0; c < cEnd; c++) {
        const uint32_t stg = base + (uint32_t)(c & 1) * STG;
        #pragma unroll
        for (int it = 0; it < 2; it++) {
            int idx = tid + it * 256;
            int row = idx >> 2, f8 = idx & 3;
            float s[8] = {aP[it][0].x, aP[it][0].y, aP[it][0].z, aP[it][0].w,
                          aP[it][1].x, aP[it][1].y, aP[it][1].z, aP[it][1].w};
            __half h[8];
            float l[8];
            #pragma unroll
            for (int e = 0; e < 8; e++) {
                float as = s[e] * 64.f;
                h[e] = __float2half_rn(as);
                l[e] = as - __half2float(h[e]);
            }
            uint4 hv = make_uint4(packh2(h[0], h[1]), packh2(h[2], h[3]),
                                  packh2(h[4], h[5]), packh2(h[6], h[7]));
            uint4 lv = make_uint4(packf16_2(l[0], l[1]), packf16_2(l[2], l[3]),
                                  packf16_2(l[4], l[5]), packf16_2(l[6], l[7]));
            uint32_t off = swz64((uint32_t)(row * 64 + f8 * 16));
            sts128(stg + off, hv);
            sts128(stg + 8192u + off, lv);
        }
        cpasync_wait0();
        __syncthreads();
        if (c + 1 < cEnd) {
            const int k0 = (c + 1) << 5;
            #pragma unroll
            for (int it = 0; it < 2; it++) {
                int idx = tid + it * 256;
                int row = idx >> 2, f8 = idx & 3;
                int gr = m0 + row, k = k0 + f8 * 8;
                if (gr < M) {
                    aP[it][0] = *reinterpret_cast<const float4*>(A + (size_t)gr * K + k);
                    aP[it][1] = *reinterpret_cast<const float4*>(A + (size_t)gr * K + k + 4);
                } else {
                    aP[it][0] = aP[it][1] = make_float4(0.f, 0.f, 0.f, 0.f);
                }
            }
            const uint32_t stgN = base + (uint32_t)((c + 1) & 1) * STG;
            cpasync16(stgN + 16384u + bOff, bSrc + k0);
            cpasync_commit();
        }
        #pragma unroll
        for (int ks = 0; ks < 2; ks++) {
            const uint32_t kb = (uint32_t)(ks << 5);
            uint32_t ah[2][4], al[2][4], bf_[2][4];
            ldm4(ah[0], stg + (pA[0] ^ kb));
            ldm4(ah[1], stg + (pA[1] ^ kb));
            ldm4(al[0], stg + 8192u + (pA[0] ^ kb));
            ldm4(al[1], stg + 8192u + (pA[1] ^ kb));
            ldm4(bf_[0], stg + 16384u + (pB[0] ^ kb));
            ldm4(bf_[1], stg + 16384u + (pB[1] ^ kb));
            #pragma unroll
            for (int mt = 0; mt < 2; mt++)
                #pragma unroll
                for (int nt = 0; nt < 4; nt++) {
                    const uint32_t* b2 = &bf_[nt >> 1][(nt & 1) * 2];
                    mma_f16(acc[mt][nt], ah[mt], b2);
                    mma_f16(acc[mt][nt], al[mt], b2);
                }
        }
    }

    const float INV = 1.f / 64.f;
    #pragma unroll
    for (int mt = 0; mt < 2; mt++) {
        int r0 = m0 + wm * 32 + mt * 16 + (lane >> 2);
        #pragma unroll
        for (int half = 0; half < 2; half++) {
            int row = r0 + half * 8;
            if (row >= M) continue;
            #pragma unroll
            for (int nt = 0; nt < 4; nt++) {
                int col = n0 + wn * 32 + nt * 8 + (lane & 3) * 2;
                if (col < Ncols)
                    C[(size_t)row * Ncols + col] = acc[mt][nt][half * 2] * INV;
                if (col + 1 < Ncols)
                    C[(size_t)row * Ncols + col + 1] = acc[mt][nt][half * 2 + 1] * INV;
            }
        }
    }
}

// generic fp16 split-K GEMM (conv2..5)
__global__ __launch_bounds__(256, 2) void k_gemm_skF(
    const float* __restrict__ A, const __half* __restrict__ Bf,
    float* __restrict__ P, int M, int K, int Ncols, int S, long stride) {
    extern __shared__ char dsm[];
    const int z = blockIdx.z;
    const int nc = K >> 5;
    const int per = nc / S, rem = nc % S;
    const int c0 = z * per + (z < rem ? z : rem);
    const int cEnd = c0 + per + (z < rem ? 1 : 0);
    gemm_core_f16(dsm, A, Bf, P + (size_t)z * stride, M, K, Ncols,
                  blockIdx.y * 128, blockIdx.x * 64, c0, cEnd);
}

// conv6 fp16 split-K=4
__global__ __launch_bounds__(256, 2) void k_gemm_sk6f(
    const float* __restrict__ A, const __half* __restrict__ Bf,
    float* __restrict__ P) {
    extern __shared__ char dsm[];
    const int z = blockIdx.z;
    const int per = (13824 >> 5) >> 2;
    gemm_core_f16(dsm, A, Bf, P + (size_t)z * 1228800, 4096, 13824, 300,
                  blockIdx.y * 128, blockIdx.x * 64, z * per, (z + 1) * per);
}

struct Ptr4 { const float* p[4]; };
__global__ __launch_bounds__(256, 2) void k_gemm7f(
    Ptr4 W, const __half* __restrict__ Bf, float* __restrict__ P) {
    extern __shared__ char dsm[];
    const int br = blockIdx.z >> 1, sl = blockIdx.z & 1;
    const int per = 128 >> 1;
    float* out = P + (size_t)sl * 4 * 1228800 + (size_t)br * 1228800;
    gemm_core_f16(dsm, W.p[br], Bf, out, 4096, 4096, 300,
                  blockIdx.y * 128, blockIdx.x * 64, sl * per, (sl + 1) * per);
}

__global__ __launch_bounds__(256, 2) void k_gemm8f(
    Ptr4 W, const __half* __restrict__ Bf, float* __restrict__ P) {
    extern __shared__ char dsm[];
    const int br = blockIdx.z >> 2, sl = blockIdx.z & 3;
    const int C8s[4] = {256, 128, 1024, 320};
    const int roff[4] = {0, 256, 384, 1408};
    const int M = C8s[br];
    const int m0 = blockIdx.y * 128;
    if (m0 >= M) return;
    const int per = 128 >> 2;
    float* out = P + (size_t)sl * 518400 + (size_t)roff[br] * 300;
    gemm_core_f16(dsm, W.p[br], Bf + (size_t)br * 1310720, out, M, 4096, 300,
                  m0, blockIdx.x * 64, sl * per, (sl + 1) * per);
}

static inline dim3 blk1(long n) { return dim3((unsigned)((n + 255) / 256)); }

extern "C" void kernel_launch(void* const* d_in, const int* in_sizes, int n_in,
                              void* d_out, int out_size) {
    const float* x  = (const float*)d_in[0];
    const float* w1 = (const float*)d_in[1];  const float* b1 = (const float*)d_in[2];
    const float* w2 = (const float*)d_in[3];  const float* b2 = (const float*)d_in[4];
    const float* w3 = (const float*)d_in[5];  const float* b3 = (const float*)d_in[6];
    const float* w4 = (const float*)d_in[7];  const float* b4 = (const float*)d_in[8];
    const float* w5 = (const float*)d_in[9];  const float* b5 = (const float*)d_in[10];
    const float* w6 = (const float*)d_in[11]; const float* b6 = (const float*)d_in[12];
    const float* w7[4] = {(const float*)d_in[13], (const float*)d_in[17],
                          (const float*)d_in[21], (const float*)d_in[25]};
    const float* b7[4] = {(const float*)d_in[14], (const float*)d_in[18],
                          (const float*)d_in[22], (const float*)d_in[26]};
    const float* w8[4] = {(const float*)d_in[15], (const float*)d_in[19],
                          (const float*)d_in[23], (const float*)d_in[27]};
    const float* b8[4] = {(const float*)d_in[16], (const float*)d_in[20],
                          (const float*)d_in[24], (const float*)d_in[28]};
    float* out = (float*)d_out;

    cudaFuncSetAttribute(k_gemm_skF,  cudaFuncAttributeMaxDynamicSharedMemorySize, GT_SMEM);
    cudaFuncSetAttribute(k_gemm_sk6f, cudaFuncAttributeMaxDynamicSharedMemorySize, GT_SMEM);
    cudaFuncSetAttribute(k_gemm7f,    cudaFuncAttributeMaxDynamicSharedMemorySize, GT_SMEM);
    cudaFuncSetAttribute(k_gemm8f,    cudaFuncAttributeMaxDynamicSharedMemorySize, GT_SMEM);

    float *c1, *u1, *p2, *c3, *c4, *c5, *p5, *p6, *p7, *p8;
    __half *bf, *x6f, *x7f;
    cudaGetSymbolAddress((void**)&c1, g_c1);
    cudaGetSymbolAddress((void**)&u1, g_u1);
    cudaGetSymbolAddress((void**)&p2, g_p2);
    cudaGetSymbolAddress((void**)&c3, g_c3);
    cudaGetSymbolAddress((void**)&c4, g_c4);
    cudaGetSymbolAddress((void**)&c5, g_c5);
    cudaGetSymbolAddress((void**)&p5, g_p5);
    cudaGetSymbolAddress((void**)&p6, g_p6);
    cudaGetSymbolAddress((void**)&p7, g_p7);
    cudaGetSymbolAddress((void**)&p8, g_p8);
    cudaGetSymbolAddress((void**)&bf, g_Bf);
    cudaGetSymbolAddress((void**)&x6f, g_x6f);
    cudaGetSymbolAddress((void**)&x7f, g_x7f);

    // stage 1: direct conv1 -> fused LRN+pool+upsample
    k_conv1<<<blk1(96L * 118 * 158), 256>>>(x, w1, b1, c1);
    k_pooluplrn<<<blk1(96L * 59 * 79), 256>>>(c1, u1);

    // conv2: M=256 K=2400 N=4661 (Npad 4672), split-K=2; fused red+LRN+pool
    k_prepF8<5><<<dim3(2, 4672), 256>>>(u1, bf, 59, 79, 2, 59, 79, 2400);
    k_gemm_skF<<<dim3(73, 2, 2), 256, GT_SMEM>>>(w2, bf, p6,
                                                 256, 2400, 4661, 2, 1193216L);
    k_redpool2<<<blk1(256L * 29 * 39), 256>>>(p6, b2, p2);

    // conv3: M=384 K=2304 N=1131 (Npad 1152), split-K=4
    k_prepF8<3><<<dim3(2, 1152), 256>>>(p2, bf, 29, 39, 1, 29, 39, 2304);
    k_gemm_skF<<<dim3(18, 3, 4), 256, GT_SMEM>>>(w3, bf, p6,
                                                 384, 2304, 1131, 4, 434304L);
    k_redG<<<blk1(434304L), 256>>>(p6, b3, c3, 434304, 1131, 4, 434304L, 1);
    // conv4: K=3456, split-K=6 (324 CTAs)
    k_prepF8<3><<<dim3(2, 1152), 256>>>(c3, bf, 29, 39, 1, 29, 39, 3456);
    k_gemm_skF<<<dim3(18, 3, 6), 256, GT_SMEM>>>(w4, bf, p6,
                                                 384, 3456, 1131, 6, 434304L);
    k_redG<<<blk1(434304L), 256>>>(p6, b4, c4, 434304, 1131, 6, 434304L, 1);
    // conv5
    k_prepF8<3><<<dim3(2, 1152), 256>>>(c4, bf, 29, 39, 1, 29, 39, 3456);
    k_gemm_skF<<<dim3(18, 3, 6), 256, GT_SMEM>>>(w5, bf, p6,
                                                 384, 3456, 1131, 6, 434304L);
    k_redG<<<blk1(434304L), 256>>>(p6, b5, c5, 434304, 1131, 6, 434304L, 1);
    k_pool<<<blk1(384L * 14 * 19), 256>>>(c5, p5, 384, 29, 39, 14, 19);

    // conv6 (fp16 2-MMA): split-K=4 -> fused reduce+relu -> d_out + x6 fp16
    k_prepF8<6><<<dim3(7, 320), 256>>>(p5, bf, 14, 19, 3, 15, 20, 13824);
    k_gemm_sk6f<<<dim3(5, 32, 4), 256, GT_SMEM>>>(w6, bf, p6);
    k_fuse6<<<dim3(128, 10), dim3(32, 8)>>>(p6, b6, out, x6f);

    // gemm7 (fp16 2-MMA, 4 branches, split-K=2) -> fused -> x7 fp16
    Ptr4 W7 = {{w7[0], w7[1], w7[2], w7[3]}};
    k_gemm7f<<<dim3(5, 32, 8), 256, GT_SMEM>>>(W7, x6f, p7);
    Bias4 B7 = {{b7[0], b7[1], b7[2], b7[3]}};
    k_fuse7<<<dim3(128, 10, 4), dim3(32, 8)>>>(p7, B7, x7f);

    // gemm8 (fp16 2-MMA, 4 branches packed, split-K=4) -> reduce+bias+tile
    Ptr4 W8 = {{w8[0], w8[1], w8[2], w8[3]}};
    k_gemm8f<<<dim3(5, 8, 16), 256, GT_SMEM>>>(W8, x7f, p8);
    Bias4 B8 = {{b8[0], b8[1], b8[2], b8[3]}};
    k_fuse8<<<blk1(518400L), 256>>>(p8, B8, out);
}

// round 15
// speedup vs baseline: 1.9269x; 1.0178x over previous
#include <cuda_runtime.h>
#include <cuda_fp16.h>
#include <math.h>
#include <stdint.h>

// ---------------------------------------------------------------------------
// VPGNet forward. All conv GEMMs: exact-A-split (x64) fp16 2-MMA HMMA,
// fp32 accumulate. conv2..5 use pre-split weights + all-cp.async core
// (3 CTAs/SM); conv6/7/8 use in-kernel split. Split-K, fused epilogues.
// Output: [x6|x8a|x8b|x8c|x8d] = 1,747,200 floats
// ---------------------------------------------------------------------------

// ---- scratch ----
__device__ float g_c1[96 * 118 * 158];
__device__ float g_u1[96 * 59 * 79];
__device__ float g_p2[256 * 29 * 39];
__device__ float g_c3[384 * 29 * 39];
__device__ float g_c4[384 * 29 * 39];
__device__ float g_c5[384 * 29 * 39];
__device__ float g_p5[384 * 14 * 19];
__device__ float g_p6[6 * 4096 * 300];        // split-K partials (shared)
__device__ float g_p7[2 * 4 * 4096 * 300];
__device__ float g_p8[4 * 1728 * 300];
// fp16 activation buffers
__device__ __half g_Bf[11250000];             // im2col (max conv2 4672*2400)
__device__ __half g_x6f[320 * 4096];
__device__ __half g_x7f[4 * 320 * 4096];
// pre-split weights for conv2..5 (max w4/w5: 384*3456 = 1,327,104)
__device__ __half gWh[1400000];
__device__ __half gWl[1400000];

// ============================ helpers ============================
__device__ __forceinline__ uint32_t smem_u32(const void* p) {
    uint32_t a;
    asm("{ .reg .u64 t; cvta.to.shared.u64 t, %1; cvt.u32.u64 %0, t; }" : "=r"(a) : "l"(p));
    return a;
}
__device__ __forceinline__ uint32_t swz64(uint32_t o) { return o ^ ((o >> 3) & 0x30); }

__device__ __forceinline__ void ldm4(uint32_t* r, uint32_t a) {
    asm volatile("ldmatrix.sync.aligned.m8n8.x4.shared.b16 {%0,%1,%2,%3}, [%4];"
                 : "=r"(r[0]), "=r"(r[1]), "=r"(r[2]), "=r"(r[3]) : "r"(a));
}
__device__ __forceinline__ void mma_f16(float* c, const uint32_t* a, const uint32_t* b) {
    asm volatile("mma.sync.aligned.m16n8k16.row.col.f32.f16.f16.f32 "
                 "{%0,%1,%2,%3}, {%4,%5,%6,%7}, {%8,%9}, {%0,%1,%2,%3};"
                 : "+f"(c[0]), "+f"(c[1]), "+f"(c[2]), "+f"(c[3])
                 : "r"(a[0]), "r"(a[1]), "r"(a[2]), "r"(a[3]), "r"(b[0]), "r"(b[1]));
}
__device__ __forceinline__ void sts128(uint32_t a, uint4 v) {
    asm volatile("st.shared.v4.b32 [%0], {%1,%2,%3,%4};"
                 :: "r"(a), "r"(v.x), "r"(v.y), "r"(v.z), "r"(v.w) : "memory");
}
__device__ __forceinline__ void cpasync16(uint32_t saddr, const void* gaddr) {
    asm volatile("cp.async.cg.shared.global [%0], [%1], 16;"
                 :: "r"(saddr), "l"(gaddr) : "memory");
}
__device__ __forceinline__ void cpasync_commit() {
    asm volatile("cp.async.commit_group;" ::: "memory");
}
__device__ __forceinline__ void cpasync_wait0() {
    asm volatile("cp.async.wait_group 0;" ::: "memory");
}
__device__ __forceinline__ uint32_t packh2(__half a, __half b) {
    return (uint32_t)__half_as_ushort(a) | ((uint32_t)__half_as_ushort(b) << 16);
}
__device__ __forceinline__ uint32_t packf16_2(float lo, float hi) {
    uint32_t d;
    asm("cvt.rn.f16x2.f32 %0, %1, %2;" : "=r"(d) : "f"(hi), "f"(lo));
    return d;
}

// ============================ elementwise layers ============================
__global__ void k_conv1(const float* __restrict__ x, const float* __restrict__ w,
                        const float* __restrict__ b, float* __restrict__ out) {
    const int HO = 118, WO = 158;
    int i = blockIdx.x * blockDim.x + threadIdx.x;
    if (i >= 96 * HO * WO) return;
    int c = i / (HO * WO), r = i % (HO * WO), oh = r / WO, ow = r % WO;
    float acc = b[c];
    const float* wp = w + c * 3 * 121;
    for (int ci = 0; ci < 3; ci++) {
        const float* xc = x + ci * 480 * 640;
        const float* wc = wp + ci * 121;
        #pragma unroll
        for (int kh = 0; kh < 11; kh++) {
            const float* xp = xc + (oh * 4 + kh) * 640 + ow * 4;
            const float* wq = wc + kh * 11;
            #pragma unroll
            for (int kw = 0; kw < 11; kw++) acc = fmaf(xp[kw], wq[kw], acc);
        }
    }
    out[i] = fmaxf(acc, 0.f);
}

__global__ void k_pooluplrn(const float* __restrict__ c1, float* __restrict__ out) {
    int i = blockIdx.x * blockDim.x + threadIdx.x;
    if (i >= 96 * 59 * 79) return;
    int c = i / (59 * 79), r = i % (59 * 79), oh = r / 79, ow = r % 79;
    int hi = (oh * 58) / 59, wi = (ow * 78) / 79;
    int jlo = c - 2 > 0 ? c - 2 : 0;
    int jhi = c + 2 < 95 ? c + 2 : 95;
    const int HW = 118 * 158;
    float m = -1e30f;
    #pragma unroll
    for (int dh = 0; dh < 3; dh++) {
        #pragma unroll
        for (int dw = 0; dw < 3; dw++) {
            const float* p = c1 + (2 * hi + dh) * 158 + 2 * wi + dw;
            float s = 0.f;
            for (int j = jlo; j <= jhi; j++) { float v = p[j * HW]; s = fmaf(v, v, s); }
            float t = 2.0f + 1e-4f * s;
            float rr = rsqrtf(t);
            m = fmaxf(m, p[c * HW] * rr * sqrtf(rr));
        }
    }
    out[i] = m;
}

// ---- fused conv2 split-K(3) reduce + bias + relu + LRN(k=8) + maxpool ----
__global__ void k_redpool2(const float* __restrict__ p, const float* __restrict__ bias,
                           float* __restrict__ out) {
    int i = blockIdx.x * blockDim.x + threadIdx.x;
    if (i >= 256 * 29 * 39) return;
    int c = i / (29 * 39), r = i % (29 * 39), oh = r / 39, ow = r % 39;
    int jlo = c - 2 > 0 ? c - 2 : 0;
    int jhi = c + 2 < 255 ? c + 2 : 255;
    float m = -1e30f;
    #pragma unroll
    for (int dh = 0; dh < 3; dh++) {
        #pragma unroll
        for (int dw = 0; dw < 3; dw++) {
            int pos = (2 * oh + dh) * 79 + 2 * ow + dw;
            float s = 0.f, center = 0.f;
            for (int j = jlo; j <= jhi; j++) {
                size_t o = (size_t)j * 4661 + pos;
                float v = fmaxf(p[o] + p[o + 1193216] + p[o + 2 * 1193216] + bias[j], 0.f);
                s = fmaf(v, v, s);
                if (j == c) center = v;
            }
            float t = 8.0f + 1e-4f * s;
            float rr = rsqrtf(t);
            m = fmaxf(m, center * rr * sqrtf(rr));
        }
    }
    out[i] = m;
}

__global__ void k_pool(const float* __restrict__ in, float* __restrict__ out,
                       int C, int Hin, int Win, int Ho, int Wo) {
    int i = blockIdx.x * blockDim.x + threadIdx.x;
    if (i >= C * Ho * Wo) return;
    int c = i / (Ho * Wo), r = i % (Ho * Wo), oh = r / Wo, ow = r % Wo;
    const float* p = in + (c * Hin + 2 * oh) * Win + 2 * ow;
    float m = p[0];
    #pragma unroll
    for (int dh = 0; dh < 3; dh++)
        #pragma unroll
        for (int dw = 0; dw < 3; dw++) m = fmaxf(m, p[dh * Win + dw]);
    out[i] = m;
}

// ---- weight pre-split: w -> (wh, wl) with exact x64 fp16 decomposition ----
__global__ void k_splitW(const float* __restrict__ w, __half* __restrict__ wh,
                         __half* __restrict__ wl, int total) {
    int i = (blockIdx.x * 256 + threadIdx.x) * 8;
    if (i >= total) return;
    float4 v0 = *reinterpret_cast<const float4*>(w + i);
    float4 v1 = *reinterpret_cast<const float4*>(w + i + 4);
    float s[8] = {v0.x, v0.y, v0.z, v0.w, v1.x, v1.y, v1.z, v1.w};
    __half h[8];
    float l[8];
    #pragma unroll
    for (int e = 0; e < 8; e++) {
        float as = s[e] * 64.f;
        h[e] = __float2half_rn(as);
        l[e] = as - __half2float(h[e]);
    }
    *reinterpret_cast<uint4*>(wh + i) =
        make_uint4(packh2(h[0], h[1]), packh2(h[2], h[3]),
                   packh2(h[4], h[5]), packh2(h[6], h[7]));
    *reinterpret_cast<uint4*>(wl + i) =
        make_uint4(packf16_2(l[0], l[1]), packf16_2(l[2], l[3]),
                   packf16_2(l[4], l[5]), packf16_2(l[6], l[7]));
}

// ---- im2col + transpose, fp16 single, 8 k per thread ----
template <int KSZ>
__global__ void k_prepF8(const float* __restrict__ src, __half* __restrict__ f,
                         int H, int W, int pad, int Ho, int Wo, int K) {
    int kidx = (blockIdx.x * 256 + threadIdx.x) * 8;
    if (kidx >= K) return;
    int n = blockIdx.y;
    int oh = n / Wo, ow = n % Wo;
    bool vn = n < Ho * Wo;
    int kw = kidx % KSZ;
    int t = kidx / KSZ;
    int kh = t % KSZ, cc = t / KSZ;
    float v[8];
    #pragma unroll
    for (int j = 0; j < 8; j++) {
        float val = 0.f;
        if (vn) {
            int ih = oh - pad + kh, iw = ow - pad + kw;
            if (ih >= 0 && ih < H && iw >= 0 && iw < W)
                val = src[((size_t)cc * H + ih) * W + iw];
        }
        v[j] = val;
        if (++kw == KSZ) { kw = 0; if (++kh == KSZ) { kh = 0; ++cc; } }
    }
    uint4 pv = make_uint4(packf16_2(v[0], v[1]), packf16_2(v[2], v[3]),
                          packf16_2(v[4], v[5]), packf16_2(v[6], v[7]));
    *reinterpret_cast<uint4*>(f + (size_t)n * K + kidx) = pv;
}

// ---- fused reduce(4)+bias+relu -> d_out(x6) AND transposed fp16 single ----
__global__ void k_fuse6(const float* __restrict__ p, const float* __restrict__ bias,
                        float* __restrict__ out, __half* __restrict__ xf) {
    __shared__ float t[32][33];
    int rb = blockIdx.x * 32, nb = blockIdx.y * 32;
    int tx = threadIdx.x, ty = threadIdx.y;
    #pragma unroll
    for (int j = 0; j < 4; j++) {
        int row = rb + ty + j * 8;
        int n = nb + tx;
        float v = 0.f;
        if (n < 300) {
            size_t o = (size_t)row * 300 + n;
            v = fmaxf(p[o] + p[o + 1228800] + p[o + 2 * 1228800] + p[o + 3 * 1228800]
                      + bias[row], 0.f);
            out[o] = v;
        }
        t[ty + j * 8][tx] = v;
    }
    __syncthreads();
    #pragma unroll
    for (int j = 0; j < 4; j++) {
        int n = nb + ty + j * 8;
        int k = rb + tx;
        xf[(size_t)n * 4096 + k] = __float2half_rn(t[tx][ty + j * 8]);
    }
}

struct Bias4 { const float* b[4]; };
__global__ void k_fuse7(const float* __restrict__ P, Bias4 bias,
                        __half* __restrict__ xf) {
    __shared__ float t[32][33];
    int br = blockIdx.z;
    const float* p = P + (size_t)br * 1228800;
    int rb = blockIdx.x * 32, nb = blockIdx.y * 32;
    int tx = threadIdx.x, ty = threadIdx.y;
    #pragma unroll
    for (int j = 0; j < 4; j++) {
        int row = rb + ty + j * 8;
        int n = nb + tx;
        float v = 0.f;
        if (n < 300) {
            size_t o = (size_t)row * 300 + n;
            v = fmaxf(p[o] + p[o + 4 * 1228800] + bias.b[br][row], 0.f);
        }
        t[ty + j * 8][tx] = v;
    }
    __syncthreads();
    #pragma unroll
    for (int j = 0; j < 4; j++) {
        int n = nb + ty + j * 8;
        int k = rb + tx;
        xf[(size_t)br * 1310720 + (size_t)n * 4096 + k] =
            __float2half_rn(t[tx][ty + j * 8]);
    }
}

__global__ void k_fuse8(const float* __restrict__ p, Bias4 bias, float* __restrict__ out) {
    int i = blockIdx.x * blockDim.x + threadIdx.x;
    if (i >= 518400) return;
    int br, start, r;
    long oofs;
    if (i < 76800)       { br = 0; start = 0;      r = 8; oofs = 1228800L; }
    else if (i < 115200) { br = 1; start = 76800;  r = 8; oofs = 1305600L; }
    else if (i < 422400) { br = 2; start = 115200; r = 4; oofs = 1344000L; }
    else                 { br = 3; start = 422400; r = 8; oofs = 1651200L; }
    int li = i - start;
    int OW = 20 * r;
    int OHW = 300 * r * r;
    int oc = li / OHW, rem = li % OHW;
    int oh = rem / OW, ow = rem % OW;
    int ic = oc * r * r + (oh % r) * r + (ow % r);
    int src = start + ic * 300 + (oh / r) * 20 + (ow / r);
    float v = p[src] + p[src + 518400] + p[src + 2 * 518400] + p[src + 3 * 518400];
    out[oofs + li] = v + bias.b[br][ic];
}

__global__ void k_redG(const float* __restrict__ p, const float* __restrict__ bias,
                       float* __restrict__ out, int total, int Ncols, int S,
                       long stride, int relu) {
    int i = blockIdx.x * blockDim.x + threadIdx.x;
    if (i >= total) return;
    float v = 0.f;
    for (int s = 0; s < S; s++) v += p[(size_t)s * stride + i];
    v += bias[i / Ncols];
    out[i] = relu ? fmaxf(v, 0.f) : v;
}

// ============================ fp16 HMMA GEMM cores ============================
#define STG 24576
#define GT_SMEM (2 * STG + 1024)
#define STG2 20480
#define GT2_SMEM (2 * STG2 + 1024)

// ---- core A: in-kernel A split (conv6/7/8) ----
__device__ __forceinline__ void gemm_core_f16(
    char* dsm, const float* __restrict__ A, const __half* __restrict__ Bf,
    float* __restrict__ C, int M, int K, int Ncols, int m0, int n0,
    int c0, int cEnd) {
    const int tid = threadIdx.x;
    const int lane = tid & 31;
    const int wid = tid >> 5;
    const int wm = wid & 3, wn = wid >> 2;

    const uint32_t base = (smem_u32(dsm) + 1023u) & ~1023u;
    const int bR = tid >> 2, bF = tid & 3;
    const uint32_t bOff = swz64((uint32_t)(bR * 64 + bF * 16));
    const __half* bSrc = Bf + (size_t)(n0 + bR) * K + bF * 8;

    uint32_t pA[2], pB[2];
    {
        uint32_t r = (uint32_t)(wm * 32 + (lane & 15));
        uint32_t kc = (uint32_t)((lane >> 4) * 16);
        #pragma unroll
        for (int mt = 0; mt < 2; mt++) {
            uint32_t o = (r + mt * 16) * 64 + kc;
            pA[mt] = o ^ ((o >> 3) & 0x30);
        }
        uint32_t rn = (uint32_t)(wn * 32 + (lane & 7) + ((lane >> 4) << 3));
        uint32_t kcb = (uint32_t)(((lane >> 3) & 1) * 16);
        #pragma unroll
        for (int nt = 0; nt < 2; nt++) {
            uint32_t o = (rn + nt * 16) * 64 + kcb;
            pB[nt] = o ^ ((o >> 3) & 0x30);
        }
    }

    float acc[2][4][4] = {};
    float4 aP[2][2];
    {
        const int k0 = c0 << 5;
        #pragma unroll
        for (int it = 0; it < 2; it++) {
            int idx = tid + it * 256;
            int row = idx >> 2, f8 = idx & 3;
            int gr = m0 + row, k = k0 + f8 * 8;
            if (gr < M) {
                aP[it][0] = *reinterpret_cast<const float4*>(A + (size_t)gr * K + k);
                aP[it][1] = *reinterpret_cast<const float4*>(A + (size_t)gr * K + k + 4);
            } else {
                aP[it][0] = aP[it][1] = make_float4(0.f, 0.f, 0.f, 0.f);
            }
        }
        const uint32_t stg0 = base + (uint32_t)(c0 & 1) * STG;
        cpasync16(stg0 + 16384u + bOff, bSrc + k0);
        cpasync_commit();
    }

    for (int c = c0; c < cEnd; c++) {
        const uint32_t stg = base + (uint32_t)(c & 1) * STG;
        #pragma unroll
        for (int it = 0; it < 2; it++) {
            int idx = tid + it * 256;
            int row = idx >> 2, f8 = idx & 3;
            float s[8] = {aP[it][0].x, aP[it][0].y, aP[it][0].z, aP[it][0].w,
                          aP[it][1].x, aP[it][1].y, aP[it][1].z, aP[it][1].w};
            __half h[8];
            float l[8];
            #pragma unroll
            for (int e = 0; e < 8; e++) {
                float as = s[e] * 64.f;
                h[e] = __float2half_rn(as);
                l[e] = as - __half2float(h[e]);
            }
            uint4 hv = make_uint4(packh2(h[0], h[1]), packh2(h[2], h[3]),
                                  packh2(h[4], h[5]), packh2(h[6], h[7]));
            uint4 lv = make_uint4(packf16_2(l[0], l[1]), packf16_2(l[2], l[3]),
                                  packf16_2(l[4], l[5]), packf16_2(l[6], l[7]));
            uint32_t off = swz64((uint32_t)(row * 64 + f8 * 16));
            sts128(stg + off, hv);
            sts128(stg + 8192u + off, lv);
        }
        cpasync_wait0();
        __syncthreads();
        if (c + 1 < cEnd) {
            const int k0 = (c + 1) << 5;
            #pragma unroll
            for (int it = 0; it < 2; it++) {
                int idx = tid + it * 256;
                int row = idx >> 2, f8 = idx & 3;
                int gr = m0 + row, k = k0 + f8 * 8;
                if (gr < M) {
                    aP[it][0] = *reinterpret_cast<const float4*>(A + (size_t)gr * K + k);
                    aP[it][1] = *reinterpret_cast<const float4*>(A + (size_t)gr * K + k + 4);
                } else {
                    aP[it][0] = aP[it][1] = make_float4(0.f, 0.f, 0.f, 0.f);
                }
            }
            const uint32_t stgN = base + (uint32_t)((c + 1) & 1) * STG;
            cpasync16(stgN + 16384u + bOff, bSrc + k0);
            cpasync_commit();
        }
        #pragma unroll
        for (int ks = 0; ks < 2; ks++) {
            const uint32_t kb = (uint32_t)(ks << 5);
            uint32_t ah[2][4], al[2][4], bf_[2][4];
            ldm4(ah[0], stg + (pA[0] ^ kb));
            ldm4(ah[1], stg + (pA[1] ^ kb));
            ldm4(al[0], stg + 8192u + (pA[0] ^ kb));
            ldm4(al[1], stg + 8192u + (pA[1] ^ kb));
            ldm4(bf_[0], stg + 16384u + (pB[0] ^ kb));
            ldm4(bf_[1], stg + 16384u + (pB[1] ^ kb));
            #pragma unroll
            for (int mt = 0; mt < 2; mt++)
                #pragma unroll
                for (int nt = 0; nt < 4; nt++) {
                    const uint32_t* b2 = &bf_[nt >> 1][(nt & 1) * 2];
                    mma_f16(acc[mt][nt], ah[mt], b2);
                    mma_f16(acc[mt][nt], al[mt], b2);
                }
        }
    }

    const float INV = 1.f / 64.f;
    #pragma unroll
    for (int mt = 0; mt < 2; mt++) {
        int r0 = m0 + wm * 32 + mt * 16 + (lane >> 2);
        #pragma unroll
        for (int half = 0; half < 2; half++) {
            int row = r0 + half * 8;
            if (row >= M) continue;
            #pragma unroll
            for (int nt = 0; nt < 4; nt++) {
                int col = n0 + wn * 32 + nt * 8 + (lane & 3) * 2;
                if (col < Ncols)
                    C[(size_t)row * Ncols + col] = acc[mt][nt][half * 2] * INV;
                if (col + 1 < Ncols)
                    C[(size_t)row * Ncols + col + 1] = acc[mt][nt][half * 2 + 1] * INV;
            }
        }
    }
}

// ---- core B: pre-split A, all-cp.async (conv2..5); M must be mult of 128 ----
__device__ __forceinline__ void gemm_core_pre(
    char* dsm, const __half* __restrict__ Ah, const __half* __restrict__ Al,
    const __half* __restrict__ Bf, float* __restrict__ C,
    int M, int K, int Ncols, int m0, int n0, int c0, int cEnd) {
    const int tid = threadIdx.x;
    const int lane = tid & 31;
    const int wid = tid >> 5;
    const int wm = wid & 3, wn = wid >> 2;

    const uint32_t base = (smem_u32(dsm) + 1023u) & ~1023u;
    const int r0 = tid >> 2, f8 = tid & 3;
    const uint32_t o0 = swz64((uint32_t)(r0 * 64 + f8 * 16));
    const uint32_t o1 = swz64((uint32_t)((r0 + 64) * 64 + f8 * 16));
    const __half* ahS = Ah + (size_t)(m0 + r0) * K + f8 * 8;
    const __half* alS = Al + (size_t)(m0 + r0) * K + f8 * 8;
    const __half* bS  = Bf + (size_t)(n0 + r0) * K + f8 * 8;
    const size_t rowK64 = (size_t)64 * K;

    uint32_t pA[2], pB[2];
    {
        uint32_t r = (uint32_t)(wm * 32 + (lane & 15));
        uint32_t kc = (uint32_t)((lane >> 4) * 16);
        #pragma unroll
        for (int mt = 0; mt < 2; mt++) {
            uint32_t o = (r + mt * 16) * 64 + kc;
            pA[mt] = o ^ ((o >> 3) & 0x30);
        }
        uint32_t rn = (uint32_t)(wn * 32 + (lane & 7) + ((lane >> 4) << 3));
        uint32_t kcb = (uint32_t)(((lane >> 3) & 1) * 16);
        #pragma unroll
        for (int nt = 0; nt < 2; nt++) {
            uint32_t o = (rn + nt * 16) * 64 + kcb;
            pB[nt] = o ^ ((o >> 3) & 0x30);
        }
    }

    float acc[2][4][4] = {};
    {
        const int k0 = c0 << 5;
        const uint32_t stg = base + (uint32_t)(c0 & 1) * STG2;
        cpasync16(stg + o0, ahS + k0);
        cpasync16(stg + o1, ahS + rowK64 + k0);
        cpasync16(stg + 8192u + o0, alS + k0);
        cpasync16(stg + 8192u + o1, alS + rowK64 + k0);
        cpasync16(stg + 16384u + o0, bS + k0);
        cpasync_commit();
    }

    for (int c = c0; c < cEnd; c++) {
        const uint32_t stg = base + (uint32_t)(c & 1) * STG2;
        cpasync_wait0();
        __syncthreads();
        if (c + 1 < cEnd) {
            const int k0 = (c + 1) << 5;
            const uint32_t stgN = base + (uint32_t)((c + 1) & 1) * STG2;
            cpasync16(stgN + o0, ahS + k0);
            cpasync16(stgN + o1, ahS + rowK64 + k0);
            cpasync16(stgN + 8192u + o0, alS + k0);
            cpasync16(stgN + 8192u + o1, alS + rowK64 + k0);
            cpasync16(stgN + 16384u + o0, bS + k0);
            cpasync_commit();
        }
        #pragma unroll
        for (int ks = 0; ks < 2; ks++) {
            const uint32_t kb = (uint32_t)(ks << 5);
            uint32_t ah[2][4], al[2][4], bf_[2][4];
            ldm4(ah[0], stg + (pA[0] ^ kb));
            ldm4(ah[1], stg + (pA[1] ^ kb));
            ldm4(al[0], stg + 8192u + (pA[0] ^ kb));
            ldm4(al[1], stg + 8192u + (pA[1] ^ kb));
            ldm4(bf_[0], stg + 16384u + (pB[0] ^ kb));
            ldm4(bf_[1], stg + 16384u + (pB[1] ^ kb));
            #pragma unroll
            for (int mt = 0; mt < 2; mt++)
                #pragma unroll
                for (int nt = 0; nt < 4; nt++) {
                    const uint32_t* b2 = &bf_[nt >> 1][(nt & 1) * 2];
                    mma_f16(acc[mt][nt], ah[mt], b2);
                    mma_f16(acc[mt][nt], al[mt], b2);
                }
        }
    }

    const float INV = 1.f / 64.f;
    #pragma unroll
    for (int mt = 0; mt < 2; mt++) {
        int r2 = m0 + wm * 32 + mt * 16 + (lane >> 2);
        #pragma unroll
        for (int half = 0; half < 2; half++) {
            int row = r2 + half * 8;
            #pragma unroll
            for (int nt = 0; nt < 4; nt++) {
                int col = n0 + wn * 32 + nt * 8 + (lane & 3) * 2;
                if (col < Ncols)
                    C[(size_t)row * Ncols + col] = acc[mt][nt][half * 2] * INV;
                if (col + 1 < Ncols)
                    C[(size_t)row * Ncols + col + 1] = acc[mt][nt][half * 2 + 1] * INV;
            }
        }
    }
}

// pre-split-A fp16 split-K GEMM (conv2..5), 3 CTAs/SM
__global__ __launch_bounds__(256, 3) void k_gemm_skP(
    const __half* __restrict__ Ah, const __half* __restrict__ Al,
    const __half* __restrict__ Bf, float* __restrict__ P,
    int M, int K, int Ncols, int S, long stride) {
    extern __shared__ char dsm[];
    const int z = blockIdx.z;
    const int nc = K >> 5;
    const int per = nc / S, rem = nc % S;
    const int c0 = z * per + (z < rem ? z : rem);
    const int cEnd = c0 + per + (z < rem ? 1 : 0);
    gemm_core_pre(dsm, Ah, Al, Bf, P + (size_t)z * stride, M, K, Ncols,
                  blockIdx.y * 128, blockIdx.x * 64, c0, cEnd);
}

// conv6 fp16 split-K=4
__global__ __launch_bounds__(256, 2) void k_gemm_sk6f(
    const float* __restrict__ A, const __half* __restrict__ Bf,
    float* __restrict__ P) {
    extern __shared__ char dsm[];
    const int z = blockIdx.z;
    const int per = (13824 >> 5) >> 2;
    gemm_core_f16(dsm, A, Bf, P + (size_t)z * 1228800, 4096, 13824, 300,
                  blockIdx.y * 128, blockIdx.x * 64, z * per, (z + 1) * per);
}

struct Ptr4 { const float* p[4]; };
__global__ __launch_bounds__(256, 2) void k_gemm7f(
    Ptr4 W, const __half* __restrict__ Bf, float* __restrict__ P) {
    extern __shared__ char dsm[];
    const int br = blockIdx.z >> 1, sl = blockIdx.z & 1;
    const int per = 128 >> 1;
    float* out = P + (size_t)sl * 4 * 1228800 + (size_t)br * 1228800;
    gemm_core_f16(dsm, W.p[br], Bf, out, 4096, 4096, 300,
                  blockIdx.y * 128, blockIdx.x * 64, sl * per, (sl + 1) * per);
}

__global__ __launch_bounds__(256, 2) void k_gemm8f(
    Ptr4 W, const __half* __restrict__ Bf, float* __restrict__ P) {
    extern __shared__ char dsm[];
    const int br = blockIdx.z >> 2, sl = blockIdx.z & 3;
    const int C8s[4] = {256, 128, 1024, 320};
    const int roff[4] = {0, 256, 384, 1408};
    const int M = C8s[br];
    const int m0 = blockIdx.y * 128;
    if (m0 >= M) return;
    const int per = 128 >> 2;
    float* out = P + (size_t)sl * 518400 + (size_t)roff[br] * 300;
    gemm_core_f16(dsm, W.p[br], Bf + (size_t)br * 1310720, out, M, 4096, 300,
                  m0, blockIdx.x * 64, sl * per, (sl + 1) * per);
}

static inline dim3 blk1(long n) { return dim3((unsigned)((n + 255) / 256)); }

extern "C" void kernel_launch(void* const* d_in, const int* in_sizes, int n_in,
                              void* d_out, int out_size) {
    const float* x  = (const float*)d_in[0];
    const float* w1 = (const float*)d_in[1];  const float* b1 = (const float*)d_in[2];
    const float* w2 = (const float*)d_in[3];  const float* b2 = (const float*)d_in[4];
    const float* w3 = (const float*)d_in[5];  const float* b3 = (const float*)d_in[6];
    const float* w4 = (const float*)d_in[7];  const float* b4 = (const float*)d_in[8];
    const float* w5 = (const float*)d_in[9];  const float* b5 = (const float*)d_in[10];
    const float* w6 = (const float*)d_in[11]; const float* b6 = (const float*)d_in[12];
    const float* w7[4] = {(const float*)d_in[13], (const float*)d_in[17],
                          (const float*)d_in[21], (const float*)d_in[25]};
    const float* b7[4] = {(const float*)d_in[14], (const float*)d_in[18],
                          (const float*)d_in[22], (const float*)d_in[26]};
    const float* w8[4] = {(const float*)d_in[15], (const float*)d_in[19],
                          (const float*)d_in[23], (const float*)d_in[27]};
    const float* b8[4] = {(const float*)d_in[16], (const float*)d_in[20],
                          (const float*)d_in[24], (const float*)d_in[28]};
    float* out = (float*)d_out;

    cudaFuncSetAttribute(k_gemm_skP,  cudaFuncAttributeMaxDynamicSharedMemorySize, GT2_SMEM);
    cudaFuncSetAttribute(k_gemm_sk6f, cudaFuncAttributeMaxDynamicSharedMemorySize, GT_SMEM);
    cudaFuncSetAttribute(k_gemm7f,    cudaFuncAttributeMaxDynamicSharedMemorySize, GT_SMEM);
    cudaFuncSetAttribute(k_gemm8f,    cudaFuncAttributeMaxDynamicSharedMemorySize, GT_SMEM);

    float *c1, *u1, *p2, *c3, *c4, *c5, *p5, *p6, *p7, *p8;
    __half *bf, *x6f, *x7f, *wh, *wl;
    cudaGetSymbolAddress((void**)&c1, g_c1);
    cudaGetSymbolAddress((void**)&u1, g_u1);
    cudaGetSymbolAddress((void**)&p2, g_p2);
    cudaGetSymbolAddress((void**)&c3, g_c3);
    cudaGetSymbolAddress((void**)&c4, g_c4);
    cudaGetSymbolAddress((void**)&c5, g_c5);
    cudaGetSymbolAddress((void**)&p5, g_p5);
    cudaGetSymbolAddress((void**)&p6, g_p6);
    cudaGetSymbolAddress((void**)&p7, g_p7);
    cudaGetSymbolAddress((void**)&p8, g_p8);
    cudaGetSymbolAddress((void**)&bf, g_Bf);
    cudaGetSymbolAddress((void**)&x6f, g_x6f);
    cudaGetSymbolAddress((void**)&x7f, g_x7f);
    cudaGetSymbolAddress((void**)&wh, gWh);
    cudaGetSymbolAddress((void**)&wl, gWl);

    // stage 1: direct conv1 -> fused LRN+pool+upsample
    k_conv1<<<blk1(96L * 118 * 158), 256>>>(x, w1, b1, c1);
    k_pooluplrn<<<blk1(96L * 59 * 79), 256>>>(c1, u1);

    // conv2: M=256 K=2400 N=4661 (Npad 4672), split-K=3; fused red+LRN+pool
    k_splitW<<<blk1(256L * 2400 / 8), 256>>>(w2, wh, wl, 256 * 2400);
    k_prepF8<5><<<dim3(2, 4672), 256>>>(u1, bf, 59, 79, 2, 59, 79, 2400);
    k_gemm_skP<<<dim3(73, 2, 3), 256, GT2_SMEM>>>(wh, wl, bf, p6,
                                                  256, 2400, 4661, 3, 1193216L);
    k_redpool2<<<blk1(256L * 29 * 39), 256>>>(p6, b2, p2);

    // conv3: M=384 K=2304 N=1131 (Npad 1152), split-K=6
    k_splitW<<<blk1(384L * 2304 / 8), 256>>>(w3, wh, wl, 384 * 2304);
    k_prepF8<3><<<dim3(2, 1152), 256>>>(p2, bf, 29, 39, 1, 29, 39, 2304);
    k_gemm_skP<<<dim3(18, 3, 6), 256, GT2_SMEM>>>(wh, wl, bf, p6,
                                                  384, 2304, 1131, 6, 434304L);
    k_redG<<<blk1(434304L), 256>>>(p6, b3, c3, 434304, 1131, 6, 434304L, 1);
    // conv4: K=3456, split-K=6
    k_splitW<<<blk1(384L * 3456 / 8), 256>>>(w4, wh, wl, 384 * 3456);
    k_prepF8<3><<<dim3(2, 1152), 256>>>(c3, bf, 29, 39, 1, 29, 39, 3456);
    k_gemm_skP<<<dim3(18, 3, 6), 256, GT2_SMEM>>>(wh, wl, bf, p6,
                                                  384, 3456, 1131, 6, 434304L);
    k_redG<<<blk1(434304L), 256>>>(p6, b4, c4, 434304, 1131, 6, 434304L, 1);
    // conv5
    k_splitW<<<blk1(384L * 3456 / 8), 256>>>(w5, wh, wl, 384 * 3456);
    k_prepF8<3><<<dim3(2, 1152), 256>>>(c4, bf, 29, 39, 1, 29, 39, 3456);
    k_gemm_skP<<<dim3(18, 3, 6), 256, GT2_SMEM>>>(wh, wl, bf, p6,
                                                  384, 3456, 1131, 6, 434304L);
    k_redG<<<blk1(434304L), 256>>>(p6, b5, c5, 434304, 1131, 6, 434304L, 1);
    k_pool<<<blk1(384L * 14 * 19), 256>>>(c5, p5, 384, 29, 39, 14, 19);

    // conv6 (fp16 2-MMA): split-K=4 -> fused reduce+relu -> d_out + x6 fp16
    k_prepF8<6><<<dim3(7, 320), 256>>>(p5, bf, 14, 19, 3, 15, 20, 13824);
    k_gemm_sk6f<<<dim3(5, 32, 4), 256, GT_SMEM>>>(w6, bf, p6);
    k_fuse6<<<dim3(128, 10), dim3(32, 8)>>>(p6, b6, out, x6f);

    // gemm7 (fp16 2-MMA, 4 branches, split-K=2) -> fused -> x7 fp16
    Ptr4 W7 = {{w7[0], w7[1], w7[2], w7[3]}};
    k_gemm7f<<<dim3(5, 32, 8), 256, GT_SMEM>>>(W7, x6f, p7);
    Bias4 B7 = {{b7[0], b7[1], b7[2], b7[3]}};
    k_fuse7<<<dim3(128, 10, 4), dim3(32, 8)>>>(p7, B7, x7f);

    // gemm8 (fp16 2-MMA, 4 branches packed, split-K=4) -> reduce+bias+tile
    Ptr4 W8 = {{w8[0], w8[1], w8[2], w8[3]}};
    k_gemm8f<<<dim3(5, 8, 16), 256, GT_SMEM>>>(W8, x7f, p8);
    Bias4 B8 = {{b8[0], b8[1], b8[2], b8[3]}};
    k_fuse8<<<blk1(518400L), 256>>>(p8, B8, out);
}